// round 2
// baseline (speedup 1.0000x reference)
#include <cuda_runtime.h>
#include <cuda_bf16.h>
#include <math.h>

// Problem constants
#define D_MODEL   1024
#define NUM_HEADS 16
#define HEAD_DIM  64
#define BATCH     2
#define SEQ       2048
#define M_TOT     (BATCH * SEQ)          // 4096 rows for the projection GEMMs
#define ATT_SCALE 0.125f                 // HEAD_DIM^-0.5

// ---------------------------------------------------------------------------
// Scratch (device globals: allocation-free per harness rules)
// ---------------------------------------------------------------------------
__device__ float g_q[BATCH * NUM_HEADS * SEQ * HEAD_DIM];   // [B,H,N,Dh]
__device__ float g_k[BATCH * NUM_HEADS * SEQ * HEAD_DIM];
__device__ float g_v[BATCH * NUM_HEADS * SEQ * HEAD_DIM];
__device__ float g_ctx[BATCH * SEQ * D_MODEL];              // [B,N,H*Dh]

// ---------------------------------------------------------------------------
// SGEMM: C = A @ W^T, A [M,K] row-major, W [N,K] row-major.
// 128x128x8 tile, 256 threads, 8x8 register micro-tile, reg-prefetch pipeline.
// ---------------------------------------------------------------------------
#define BM 128
#define BN 128
#define BK 8

// Projection kernel: blockIdx.z selects (query,Wq)->g_q / (key,Wk)->g_k / (value,Wv)->g_v
// Output scattered into [B,H,N,Dh] layout.
__global__ __launch_bounds__(256)
void proj_kernel(const float* __restrict__ query,
                 const float* __restrict__ key,
                 const float* __restrict__ value,
                 const float* __restrict__ Wq,
                 const float* __restrict__ Wk,
                 const float* __restrict__ Wv)
{
    const int z = blockIdx.z;
    const float* A = (z == 0) ? query : ((z == 1) ? key : value);
    const float* W = (z == 0) ? Wq    : ((z == 1) ? Wk  : Wv);
    float*       O = (z == 0) ? g_q   : ((z == 1) ? g_k : g_v);

    const int t  = threadIdx.x;
    const int m0 = blockIdx.y * BM;
    const int n0 = blockIdx.x * BN;
    const int K  = D_MODEL;

    const int lr = t >> 1;            // 0..127 : row within tile (A and W symmetric)
    const int lc = (t & 1) * 4;       // 0 or 4 : col within BK

    const float* Ag = A + (m0 + lr) * K + lc;
    const float* Wg = W + (n0 + lr) * K + lc;

    __shared__ float As[BK][BM];
    __shared__ float Bs[BK][BN];

    float acc[8][8];
#pragma unroll
    for (int i = 0; i < 8; i++)
#pragma unroll
        for (int j = 0; j < 8; j++) acc[i][j] = 0.f;

    float4 aR = *(const float4*)(Ag);
    float4 bR = *(const float4*)(Wg);

    const int ty = t >> 4;            // 0..15
    const int tx = t & 15;            // 0..15

    for (int k0 = 0; k0 < K; k0 += BK) {
        As[lc + 0][lr] = aR.x; As[lc + 1][lr] = aR.y;
        As[lc + 2][lr] = aR.z; As[lc + 3][lr] = aR.w;
        Bs[lc + 0][lr] = bR.x; Bs[lc + 1][lr] = bR.y;
        Bs[lc + 2][lr] = bR.z; Bs[lc + 3][lr] = bR.w;
        __syncthreads();

        if (k0 + BK < K) {
            aR = *(const float4*)(Ag + k0 + BK);
            bR = *(const float4*)(Wg + k0 + BK);
        }

#pragma unroll
        for (int kk = 0; kk < BK; kk++) {
            float a[8], b[8];
            *(float4*)(a)     = *(const float4*)(&As[kk][ty * 8]);
            *(float4*)(a + 4) = *(const float4*)(&As[kk][ty * 8 + 4]);
            *(float4*)(b)     = *(const float4*)(&Bs[kk][tx * 8]);
            *(float4*)(b + 4) = *(const float4*)(&Bs[kk][tx * 8 + 4]);
#pragma unroll
            for (int i = 0; i < 8; i++)
#pragma unroll
                for (int j = 0; j < 8; j++)
                    acc[i][j] += a[i] * b[j];
        }
        __syncthreads();
    }

    // Epilogue: scatter to [B,H,N,Dh].  n = h*64 + d; tx*8+j is 4-aligned and
    // stays inside one 64-wide head block, so float4 stores are valid.
#pragma unroll
    for (int i = 0; i < 8; i++) {
        const int m  = m0 + ty * 8 + i;
        const int b  = m >> 11;        // / SEQ
        const int nq = m & (SEQ - 1);
#pragma unroll
        for (int j = 0; j < 8; j += 4) {
            const int n = n0 + tx * 8 + j;
            const int h = n >> 6;
            const int d = n & 63;
            float4 o = make_float4(acc[i][j], acc[i][j + 1], acc[i][j + 2], acc[i][j + 3]);
            *(float4*)&O[((b * NUM_HEADS + h) * SEQ + nq) * HEAD_DIM + d] = o;
        }
    }
}

// Output projection: out = g_ctx @ Wo^T + bo, plain row-major [M_TOT, D_MODEL].
__global__ __launch_bounds__(256)
void out_kernel(const float* __restrict__ Wo,
                const float* __restrict__ bo,
                float* __restrict__ Cout)
{
    const int t  = threadIdx.x;
    const int m0 = blockIdx.y * BM;
    const int n0 = blockIdx.x * BN;
    const int K  = D_MODEL;

    const int lr = t >> 1;
    const int lc = (t & 1) * 4;

    const float* Ag = g_ctx + (m0 + lr) * K + lc;
    const float* Wg = Wo    + (n0 + lr) * K + lc;

    __shared__ float As[BK][BM];
    __shared__ float Bs[BK][BN];

    float acc[8][8];
#pragma unroll
    for (int i = 0; i < 8; i++)
#pragma unroll
        for (int j = 0; j < 8; j++) acc[i][j] = 0.f;

    float4 aR = *(const float4*)(Ag);
    float4 bR = *(const float4*)(Wg);

    const int ty = t >> 4;
    const int tx = t & 15;

    for (int k0 = 0; k0 < K; k0 += BK) {
        As[lc + 0][lr] = aR.x; As[lc + 1][lr] = aR.y;
        As[lc + 2][lr] = aR.z; As[lc + 3][lr] = aR.w;
        Bs[lc + 0][lr] = bR.x; Bs[lc + 1][lr] = bR.y;
        Bs[lc + 2][lr] = bR.z; Bs[lc + 3][lr] = bR.w;
        __syncthreads();

        if (k0 + BK < K) {
            aR = *(const float4*)(Ag + k0 + BK);
            bR = *(const float4*)(Wg + k0 + BK);
        }

#pragma unroll
        for (int kk = 0; kk < BK; kk++) {
            float a[8], b[8];
            *(float4*)(a)     = *(const float4*)(&As[kk][ty * 8]);
            *(float4*)(a + 4) = *(const float4*)(&As[kk][ty * 8 + 4]);
            *(float4*)(b)     = *(const float4*)(&Bs[kk][tx * 8]);
            *(float4*)(b + 4) = *(const float4*)(&Bs[kk][tx * 8 + 4]);
#pragma unroll
            for (int i = 0; i < 8; i++)
#pragma unroll
                for (int j = 0; j < 8; j++)
                    acc[i][j] += a[i] * b[j];
        }
        __syncthreads();
    }

#pragma unroll
    for (int i = 0; i < 8; i++) {
        const int m = m0 + ty * 8 + i;
#pragma unroll
        for (int j = 0; j < 8; j += 4) {
            const int n = n0 + tx * 8 + j;
            float4 o = make_float4(acc[i][j]     + bo[n],
                                   acc[i][j + 1] + bo[n + 1],
                                   acc[i][j + 2] + bo[n + 2],
                                   acc[i][j + 3] + bo[n + 3]);
            *(float4*)&Cout[(size_t)m * D_MODEL + n] = o;
        }
    }
}

// ---------------------------------------------------------------------------
// Flash attention (fp32): one block = one (b,h) x 64 q-rows.
// SMEM: Qst[d][r] (d-major, scaled), KPst = K[d][j] then aliased as P[j][r],
// Vs[j][dv]. 256 threads, 4x4 micro-tile per thread for both S and O GEMMs.
// Online softmax with per-row (m,l) replicated across the 16 lanes of a row group.
// ---------------------------------------------------------------------------
#define QTILE 64
#define KTILE 64
#define SPITCH 68                       // 64 + 4 pad: conflict-free, float4-aligned
#define ATTN_SMEM (3 * 64 * SPITCH * 4) // 52224 bytes

__global__ __launch_bounds__(256)
void attn_kernel()
{
    extern __shared__ float sm[];
    float* Qst  = sm;                   // [64][SPITCH]  Qst[d*SPITCH + r]
    float* KPst = sm + 64 * SPITCH;     // K: [d][j]  -> later P: [j][r]
    float* Vs   = sm + 2 * 64 * SPITCH; // [j][dv]

    const int t   = threadIdx.x;
    const int q0  = blockIdx.x * QTILE;
    const int bh  = blockIdx.y;

    const float* qb = g_q + (size_t)bh * SEQ * HEAD_DIM;
    const float* kb = g_k + (size_t)bh * SEQ * HEAD_DIM;
    const float* vb = g_v + (size_t)bh * SEQ * HEAD_DIM;

    // loader mapping: 4 lanes cover 64 contiguous bytes of one row
    const int lr    = t >> 2;           // 0..63 row
    const int dbase = (t & 3) * 4;      // 0,4,8,12

    // load Q tile (scaled) transposed into Qst[d][r]
#pragma unroll
    for (int u = 0; u < 4; u++) {
        const int d = dbase + u * 16;
        float4 qv = *(const float4*)(qb + (size_t)(q0 + lr) * HEAD_DIM + d);
        Qst[(d + 0) * SPITCH + lr] = qv.x * ATT_SCALE;
        Qst[(d + 1) * SPITCH + lr] = qv.y * ATT_SCALE;
        Qst[(d + 2) * SPITCH + lr] = qv.z * ATT_SCALE;
        Qst[(d + 3) * SPITCH + lr] = qv.w * ATT_SCALE;
    }
    __syncthreads();

    const int ty = t >> 4;              // 0..15 : rows ty*4..+3
    const int tx = t & 15;              // 0..15 : cols tx*4..+3

    float m_i[4], l_i[4], acc[4][4];
#pragma unroll
    for (int i = 0; i < 4; i++) {
        m_i[i] = -1e30f;
        l_i[i] = 0.f;
#pragma unroll
        for (int c = 0; c < 4; c++) acc[i][c] = 0.f;
    }

    for (int kt = 0; kt < SEQ / KTILE; kt++) {
        const int j0 = kt * KTILE;

        // load K transposed into KPst[d][j], V direct into Vs[j][dv]
#pragma unroll
        for (int u = 0; u < 4; u++) {
            const int d = dbase + u * 16;
            float4 kv = *(const float4*)(kb + (size_t)(j0 + lr) * HEAD_DIM + d);
            KPst[(d + 0) * SPITCH + lr] = kv.x;
            KPst[(d + 1) * SPITCH + lr] = kv.y;
            KPst[(d + 2) * SPITCH + lr] = kv.z;
            KPst[(d + 3) * SPITCH + lr] = kv.w;
            float4 vv = *(const float4*)(vb + (size_t)(j0 + lr) * HEAD_DIM + d);
            *(float4*)&Vs[lr * SPITCH + d] = vv;
        }
        __syncthreads();

        // S[4][4] = (Q*scale) @ K^T for this thread's (row, jcol) micro-tile
        float s[4][4];
#pragma unroll
        for (int i = 0; i < 4; i++)
#pragma unroll
            for (int jj = 0; jj < 4; jj++) s[i][jj] = 0.f;

#pragma unroll 16
        for (int d = 0; d < HEAD_DIM; d++) {
            float4 a = *(const float4*)&Qst[d * SPITCH + ty * 4];
            float4 b = *(const float4*)&KPst[d * SPITCH + tx * 4];
            s[0][0] += a.x * b.x; s[0][1] += a.x * b.y; s[0][2] += a.x * b.z; s[0][3] += a.x * b.w;
            s[1][0] += a.y * b.x; s[1][1] += a.y * b.y; s[1][2] += a.y * b.z; s[1][3] += a.y * b.w;
            s[2][0] += a.z * b.x; s[2][1] += a.z * b.y; s[2][2] += a.z * b.z; s[2][3] += a.z * b.w;
            s[3][0] += a.w * b.x; s[3][1] += a.w * b.y; s[3][2] += a.w * b.z; s[3][3] += a.w * b.w;
        }
        __syncthreads();   // done reading KPst as K; about to overwrite with P

        // online softmax per row; write P transposed into KPst[j][r]
#pragma unroll
        for (int i = 0; i < 4; i++) {
            float rm = fmaxf(fmaxf(s[i][0], s[i][1]), fmaxf(s[i][2], s[i][3]));
            rm = fmaxf(rm, __shfl_xor_sync(0xffffffffu, rm, 1));
            rm = fmaxf(rm, __shfl_xor_sync(0xffffffffu, rm, 2));
            rm = fmaxf(rm, __shfl_xor_sync(0xffffffffu, rm, 4));
            rm = fmaxf(rm, __shfl_xor_sync(0xffffffffu, rm, 8));

            const float mnew = fmaxf(m_i[i], rm);
            const float corr = __expf(m_i[i] - mnew);
            float rs = 0.f;
#pragma unroll
            for (int jj = 0; jj < 4; jj++) {
                float p = __expf(s[i][jj] - mnew);
                s[i][jj] = p;
                rs += p;
            }
            rs += __shfl_xor_sync(0xffffffffu, rs, 1);
            rs += __shfl_xor_sync(0xffffffffu, rs, 2);
            rs += __shfl_xor_sync(0xffffffffu, rs, 4);
            rs += __shfl_xor_sync(0xffffffffu, rs, 8);

            l_i[i] = l_i[i] * corr + rs;
            m_i[i] = mnew;
#pragma unroll
            for (int c = 0; c < 4; c++) acc[i][c] *= corr;
#pragma unroll
            for (int jj = 0; jj < 4; jj++)
                KPst[(tx * 4 + jj) * SPITCH + ty * 4 + i] = s[i][jj];
        }
        __syncthreads();   // P visible to all

        // O += P @ V
#pragma unroll 16
        for (int j = 0; j < KTILE; j++) {
            float4 a = *(const float4*)&KPst[j * SPITCH + ty * 4];
            float4 b = *(const float4*)&Vs[j * SPITCH + tx * 4];
            acc[0][0] += a.x * b.x; acc[0][1] += a.x * b.y; acc[0][2] += a.x * b.z; acc[0][3] += a.x * b.w;
            acc[1][0] += a.y * b.x; acc[1][1] += a.y * b.y; acc[1][2] += a.y * b.z; acc[1][3] += a.y * b.w;
            acc[2][0] += a.z * b.x; acc[2][1] += a.z * b.y; acc[2][2] += a.z * b.z; acc[2][3] += a.z * b.w;
            acc[3][0] += a.w * b.x; acc[3][1] += a.w * b.y; acc[3][2] += a.w * b.z; acc[3][3] += a.w * b.w;
        }
        __syncthreads();   // before next tile overwrites KPst / Vs
    }

    // epilogue: O /= l ; write ctx[b, q0+r, h*64 + dv]
    const int b = bh >> 4;
    const int h = bh & 15;
#pragma unroll
    for (int i = 0; i < 4; i++) {
        const float inv = 1.f / l_i[i];
        float4 o = make_float4(acc[i][0] * inv, acc[i][1] * inv,
                               acc[i][2] * inv, acc[i][3] * inv);
        const int r = q0 + ty * 4 + i;
        *(float4*)&g_ctx[((size_t)b * SEQ + r) * D_MODEL + h * HEAD_DIM + tx * 4] = o;
    }
}

// ---------------------------------------------------------------------------
// kernel_launch
// ---------------------------------------------------------------------------
extern "C" void kernel_launch(void* const* d_in, const int* in_sizes, int n_in,
                              void* d_out, int out_size)
{
    const float* query = (const float*)d_in[0];
    const float* key   = (const float*)d_in[1];
    const float* value = (const float*)d_in[2];
    const float* Wq    = (const float*)d_in[3];
    const float* Wk    = (const float*)d_in[4];
    const float* Wv    = (const float*)d_in[5];
    const float* Wo    = (const float*)d_in[6];
    const float* bo    = (const float*)d_in[7];
    float* out = (float*)d_out;

    // 1) Q/K/V projections (z = 0/1/2)
    proj_kernel<<<dim3(D_MODEL / BN, M_TOT / BM, 3), 256>>>(query, key, value, Wq, Wk, Wv);

    // 2) flash attention
    cudaFuncSetAttribute(attn_kernel, cudaFuncAttributeMaxDynamicSharedMemorySize, ATTN_SMEM);
    attn_kernel<<<dim3(SEQ / QTILE, BATCH * NUM_HEADS), 256, ATTN_SMEM>>>();

    // 3) output projection + bias
    out_kernel<<<dim3(D_MODEL / BN, M_TOT / BM), 256>>>(Wo, bo, out);
}

// round 4
// speedup vs baseline: 2.7375x; 2.7375x over previous
#include <cuda_runtime.h>
#include <cuda_bf16.h>
#include <math.h>

// Problem constants
#define D_MODEL   1024
#define NUM_HEADS 16
#define HEAD_DIM  64
#define BATCH     2
#define SEQ       2048
#define M_TOT     (BATCH * SEQ)
#define ATT_SCALE 0.125f

// ---------------------------------------------------------------------------
// Scratch (device globals: allocation-free per harness rules)
// ---------------------------------------------------------------------------
__device__ float g_q[BATCH * NUM_HEADS * SEQ * HEAD_DIM];   // [B,H,N,Dh]
__device__ float g_k[BATCH * NUM_HEADS * SEQ * HEAD_DIM];
__device__ float g_v[BATCH * NUM_HEADS * SEQ * HEAD_DIM];
__device__ float g_ctx[BATCH * SEQ * D_MODEL];              // [B,N,H*Dh]

// ---------------------------------------------------------------------------
// tf32 helpers
// ---------------------------------------------------------------------------
__device__ __forceinline__ float to_tf32(float x) {
    unsigned u;
    asm("cvt.rna.tf32.f32 %0, %1;" : "=r"(u) : "f"(x));
    return __uint_as_float(u);
}

__device__ __forceinline__ void mma_tf32(float* c,
                                         unsigned a0, unsigned a1, unsigned a2, unsigned a3,
                                         unsigned b0, unsigned b1)
{
    asm volatile(
        "mma.sync.aligned.m16n8k8.row.col.f32.tf32.tf32.f32 "
        "{%0,%1,%2,%3}, {%4,%5,%6,%7}, {%8,%9}, {%0,%1,%2,%3};\n"
        : "+f"(c[0]), "+f"(c[1]), "+f"(c[2]), "+f"(c[3])
        : "r"(a0), "r"(a1), "r"(a2), "r"(a3), "r"(b0), "r"(b1));
}

// ---------------------------------------------------------------------------
// tf32 MMA GEMM: C = A @ W^T.  A [M,K] rm, W [N,K] rm.
// 128x128x16 CTA tile, 256 threads = 8 warps (2 m x 4 n), warp tile 64x32.
// mma m16n8k8: per warp 4 mtiles x 4 ntiles.
// ---------------------------------------------------------------------------
#define GBM 128
#define GBN 128
#define GBK 16
#define GPITCH 20   // 16 + 4 pad -> conflict-free frag loads

struct GemmSmem {
    float As[GBM * GPITCH];
    float Bs[GBN * GPITCH];
};

// Core compute shared by both GEMM kernels.
// Epilogue mode 0: scatter to [B,H,N,Dh] (O = g_q/g_k/g_v)
// Epilogue mode 1: plain row-major + bias (O = out, bias = bo)
__device__ __forceinline__ void gemm_tf32_body(const float* __restrict__ A,
                                               const float* __restrict__ W,
                                               float* __restrict__ O,
                                               const float* __restrict__ bo,
                                               int m0, int n0, int epilogue_mode)
{
    __shared__ GemmSmem sm;
    const int t    = threadIdx.x;
    const int lane = t & 31;
    const int wid  = t >> 5;
    const int wm   = wid & 1;       // 0..1
    const int wn   = wid >> 1;      // 0..3
    const int K    = D_MODEL;

    float acc[4][4][4];
#pragma unroll
    for (int i = 0; i < 4; i++)
#pragma unroll
        for (int j = 0; j < 4; j++)
#pragma unroll
            for (int r = 0; r < 4; r++) acc[i][j][r] = 0.f;

    // global load mapping: f4 index i = t + 256*u (u<2); row=i/4, c4=i%4
    const int gr0 = t >> 2;             // rows for u=0: 0..63
    const int gc4 = (t & 3) * 4;

    float4 aV[2], bV[2];
    aV[0] = *(const float4*)(A + (size_t)(m0 + gr0)      * K + gc4);
    aV[1] = *(const float4*)(A + (size_t)(m0 + gr0 + 64) * K + gc4);
    bV[0] = *(const float4*)(W + (size_t)(n0 + gr0)      * K + gc4);
    bV[1] = *(const float4*)(W + (size_t)(n0 + gr0 + 64) * K + gc4);

    for (int k0 = 0; k0 < K; k0 += GBK) {
#pragma unroll
        for (int u = 0; u < 2; u++) {
            const int row = gr0 + u * 64;
            float* as = &sm.As[row * GPITCH + gc4];
            as[0] = to_tf32(aV[u].x); as[1] = to_tf32(aV[u].y);
            as[2] = to_tf32(aV[u].z); as[3] = to_tf32(aV[u].w);
            float* bs = &sm.Bs[row * GPITCH + gc4];
            bs[0] = to_tf32(bV[u].x); bs[1] = to_tf32(bV[u].y);
            bs[2] = to_tf32(bV[u].z); bs[3] = to_tf32(bV[u].w);
        }
        __syncthreads();

        if (k0 + GBK < K) {
            aV[0] = *(const float4*)(A + (size_t)(m0 + gr0)      * K + k0 + GBK + gc4);
            aV[1] = *(const float4*)(A + (size_t)(m0 + gr0 + 64) * K + k0 + GBK + gc4);
            bV[0] = *(const float4*)(W + (size_t)(n0 + gr0)      * K + k0 + GBK + gc4);
            bV[1] = *(const float4*)(W + (size_t)(n0 + gr0 + 64) * K + k0 + GBK + gc4);
        }

        const int fr = lane >> 2;       // 0..7
        const int fc = lane & 3;        // 0..3
#pragma unroll
        for (int ks = 0; ks < 2; ks++) {
            const int kc = ks * 8 + fc;
            unsigned af[4][4];
#pragma unroll
            for (int mt = 0; mt < 4; mt++) {
                const int rb = wm * 64 + mt * 16 + fr;
                af[mt][0] = __float_as_uint(sm.As[rb * GPITCH + kc]);
                af[mt][1] = __float_as_uint(sm.As[(rb + 8) * GPITCH + kc]);
                af[mt][2] = __float_as_uint(sm.As[rb * GPITCH + kc + 4]);
                af[mt][3] = __float_as_uint(sm.As[(rb + 8) * GPITCH + kc + 4]);
            }
#pragma unroll
            for (int nt = 0; nt < 4; nt++) {
                const int nb = wn * 32 + nt * 8 + fr;
                unsigned b0 = __float_as_uint(sm.Bs[nb * GPITCH + kc]);
                unsigned b1 = __float_as_uint(sm.Bs[nb * GPITCH + kc + 4]);
#pragma unroll
                for (int mt = 0; mt < 4; mt++)
                    mma_tf32(acc[mt][nt], af[mt][0], af[mt][1], af[mt][2], af[mt][3], b0, b1);
            }
        }
        __syncthreads();
    }

    // epilogue: c0,c1 -> (row fr, col 2fc / 2fc+1); c2,c3 -> row fr+8
    const int fr = lane >> 2;
    const int fc = lane & 3;
#pragma unroll
    for (int mt = 0; mt < 4; mt++) {
        const int r0 = m0 + wm * 64 + mt * 16 + fr;
#pragma unroll
        for (int nt = 0; nt < 4; nt++) {
            const int col = n0 + wn * 32 + nt * 8 + fc * 2;
            if (epilogue_mode == 0) {
                // scatter to [B,H,N,Dh]
                const int h = col >> 6, d = col & 63;
#pragma unroll
                for (int half = 0; half < 2; half++) {
                    const int m  = r0 + half * 8;
                    const int b  = m >> 11;
                    const int nq = m & (SEQ - 1);
                    float2 o = make_float2(acc[mt][nt][half * 2], acc[mt][nt][half * 2 + 1]);
                    *(float2*)&O[(((size_t)b * NUM_HEADS + h) * SEQ + nq) * HEAD_DIM + d] = o;
                }
            } else {
                const float b0 = bo[col], b1 = bo[col + 1];
#pragma unroll
                for (int half = 0; half < 2; half++) {
                    const int m = r0 + half * 8;
                    float2 o = make_float2(acc[mt][nt][half * 2] + b0,
                                           acc[mt][nt][half * 2 + 1] + b1);
                    *(float2*)&O[(size_t)m * D_MODEL + col] = o;
                }
            }
        }
    }
}

__global__ __launch_bounds__(256)
void proj_kernel(const float* __restrict__ query,
                 const float* __restrict__ key,
                 const float* __restrict__ value,
                 const float* __restrict__ Wq,
                 const float* __restrict__ Wk,
                 const float* __restrict__ Wv)
{
    const int z = blockIdx.z;
    const float* A = (z == 0) ? query : ((z == 1) ? key : value);
    const float* W = (z == 0) ? Wq    : ((z == 1) ? Wk  : Wv);
    float*       O = (z == 0) ? g_q   : ((z == 1) ? g_k : g_v);
    gemm_tf32_body(A, W, O, nullptr, blockIdx.y * GBM, blockIdx.x * GBN, 0);
}

__global__ __launch_bounds__(256)
void out_kernel(const float* __restrict__ Wo,
                const float* __restrict__ bo,
                float* __restrict__ Cout)
{
    gemm_tf32_body(g_ctx, Wo, Cout, bo, blockIdx.y * GBM, blockIdx.x * GBN, 1);
}

// ---------------------------------------------------------------------------
// Flash attention with tf32 MMA.
// Block = 128 q-rows of one (b,h). 256 threads = 8 warps; warp w owns q rows
// [w*16, w*16+16). Q frags live in registers for the whole K loop.
// SMEM: Ps [128][68] (Q staging, then P per k-tile), Ks [64][68] (K as [j][d]),
// Vt [64][68] (V transposed as [dv][j]).
// ---------------------------------------------------------------------------
#define QT 128
#define KT 64
#define APITCH 68
#define ATTN_SMEM ((QT * APITCH + 2 * KT * APITCH) * 4)   // 69632 B

__global__ __launch_bounds__(256)
void attn_kernel()
{
    extern __shared__ float sm[];
    float* Ps = sm;                      // [128][APITCH]
    float* Ks = sm + QT * APITCH;        // [64][APITCH]   K[j][d]
    float* Vt = Ks + KT * APITCH;        // [64][APITCH]   V^T[dv][j]

    const int t    = threadIdx.x;
    const int lane = t & 31;
    const int w    = t >> 5;
    const int fr   = lane >> 2;          // 0..7
    const int fc   = lane & 3;           // 0..3

    const int q0 = blockIdx.x * QT;
    const int bh = blockIdx.y;
    const float* qb = g_q + (size_t)bh * SEQ * HEAD_DIM;
    const float* kb = g_k + (size_t)bh * SEQ * HEAD_DIM;
    const float* vb = g_v + (size_t)bh * SEQ * HEAD_DIM;

    // ---- stage Q (scaled, tf32) into Ps, then load frags into registers ----
    // Q tile = 128 rows x 64 cols = 2048 float4 -> 256 threads x 8 iters.
    {
#pragma unroll
        for (int u = 0; u < 8; u++) {
            const int i = t + 256 * u;
            const int row = i >> 4;            // 0..127
            const int c = (i & 15) * 4;        // 0..60
            float4 qv = *(const float4*)(qb + (size_t)(q0 + row) * HEAD_DIM + c);
            float* p = &Ps[row * APITCH + c];
            p[0] = to_tf32(qv.x * ATT_SCALE); p[1] = to_tf32(qv.y * ATT_SCALE);
            p[2] = to_tf32(qv.z * ATT_SCALE); p[3] = to_tf32(qv.w * ATT_SCALE);
        }
    }
    __syncthreads();

    unsigned qa[8][4];
#pragma unroll
    for (int ks = 0; ks < 8; ks++) {
        const int kc = ks * 8 + fc;
        const int rb = w * 16 + fr;
        qa[ks][0] = __float_as_uint(Ps[rb * APITCH + kc]);
        qa[ks][1] = __float_as_uint(Ps[(rb + 8) * APITCH + kc]);
        qa[ks][2] = __float_as_uint(Ps[rb * APITCH + kc + 4]);
        qa[ks][3] = __float_as_uint(Ps[(rb + 8) * APITCH + kc + 4]);
    }
    __syncthreads();   // everyone has Q frags; Ps free for P

    float o[8][4];
    float m0 = -1e30f, m1 = -1e30f, l0 = 0.f, l1 = 0.f;
#pragma unroll
    for (int nt = 0; nt < 8; nt++)
#pragma unroll
        for (int r = 0; r < 4; r++) o[nt][r] = 0.f;

    for (int kt = 0; kt < SEQ / KT; kt++) {
        const int j0 = kt * KT;

        // ---- stage K [j][d] (coalesced): 64x64 = 1024 float4 ----
#pragma unroll
        for (int u = 0; u < 4; u++) {
            const int i = t + 256 * u;
            const int row = i >> 4;
            const int c = (i & 15) * 4;
            float4 kv = *(const float4*)(kb + (size_t)(j0 + row) * HEAD_DIM + c);
            float* p = &Ks[row * APITCH + c];
            p[0] = to_tf32(kv.x); p[1] = to_tf32(kv.y);
            p[2] = to_tf32(kv.z); p[3] = to_tf32(kv.w);
        }
        // ---- stage V transposed: Vt[d][j]  (conflict-free stores) ----
        {
            const int j = t & 63;
            const int db = (t >> 6) * 16;
#pragma unroll
            for (int u = 0; u < 4; u++) {
                float4 vv = *(const float4*)(vb + (size_t)(j0 + j) * HEAD_DIM + db + 4 * u);
                Vt[(db + 4 * u + 0) * APITCH + j] = to_tf32(vv.x);
                Vt[(db + 4 * u + 1) * APITCH + j] = to_tf32(vv.y);
                Vt[(db + 4 * u + 2) * APITCH + j] = to_tf32(vv.z);
                Vt[(db + 4 * u + 3) * APITCH + j] = to_tf32(vv.w);
            }
        }
        __syncthreads();

        // ---- S = Q @ K^T (warp tile 16 x 64) ----
        float s[8][4];
#pragma unroll
        for (int nt = 0; nt < 8; nt++)
#pragma unroll
            for (int r = 0; r < 4; r++) s[nt][r] = 0.f;

#pragma unroll
        for (int ks = 0; ks < 8; ks++) {
            const int kc = ks * 8 + fc;
#pragma unroll
            for (int nt = 0; nt < 8; nt++) {
                const int nb = nt * 8 + fr;
                unsigned b0 = __float_as_uint(Ks[nb * APITCH + kc]);
                unsigned b1 = __float_as_uint(Ks[nb * APITCH + kc + 4]);
                mma_tf32(s[nt], qa[ks][0], qa[ks][1], qa[ks][2], qa[ks][3], b0, b1);
            }
        }

        // ---- online softmax (rows fr and fr+8 of this warp's tile) ----
        float rm0 = -1e30f, rm1 = -1e30f;
#pragma unroll
        for (int nt = 0; nt < 8; nt++) {
            rm0 = fmaxf(rm0, fmaxf(s[nt][0], s[nt][1]));
            rm1 = fmaxf(rm1, fmaxf(s[nt][2], s[nt][3]));
        }
        rm0 = fmaxf(rm0, __shfl_xor_sync(0xffffffffu, rm0, 1));
        rm0 = fmaxf(rm0, __shfl_xor_sync(0xffffffffu, rm0, 2));
        rm1 = fmaxf(rm1, __shfl_xor_sync(0xffffffffu, rm1, 1));
        rm1 = fmaxf(rm1, __shfl_xor_sync(0xffffffffu, rm1, 2));

        const float mn0 = fmaxf(m0, rm0);
        const float mn1 = fmaxf(m1, rm1);
        const float cr0 = __expf(m0 - mn0);
        const float cr1 = __expf(m1 - mn1);
        m0 = mn0; m1 = mn1;

        float rs0 = 0.f, rs1 = 0.f;
        const int wr = w * 16 + fr;
#pragma unroll
        for (int nt = 0; nt < 8; nt++) {
            float p00 = __expf(s[nt][0] - mn0);
            float p01 = __expf(s[nt][1] - mn0);
            float p10 = __expf(s[nt][2] - mn1);
            float p11 = __expf(s[nt][3] - mn1);
            rs0 += p00 + p01;
            rs1 += p10 + p11;
            const int col = nt * 8 + fc * 2;
            *(float2*)&Ps[wr * APITCH + col]       = make_float2(to_tf32(p00), to_tf32(p01));
            *(float2*)&Ps[(wr + 8) * APITCH + col] = make_float2(to_tf32(p10), to_tf32(p11));
        }
        rs0 += __shfl_xor_sync(0xffffffffu, rs0, 1);
        rs0 += __shfl_xor_sync(0xffffffffu, rs0, 2);
        rs1 += __shfl_xor_sync(0xffffffffu, rs1, 1);
        rs1 += __shfl_xor_sync(0xffffffffu, rs1, 2);
        l0 = l0 * cr0 + rs0;
        l1 = l1 * cr1 + rs1;

#pragma unroll
        for (int nt = 0; nt < 8; nt++) {
            o[nt][0] *= cr0; o[nt][1] *= cr0;
            o[nt][2] *= cr1; o[nt][3] *= cr1;
        }
        __syncwarp();      // P rows of this warp visible to this warp

        // ---- O += P @ V  (A = P from Ps, B = Vt) ----
#pragma unroll
        for (int ks = 0; ks < 8; ks++) {
            const int kc = ks * 8 + fc;
            const int rb = w * 16 + fr;
            unsigned a0 = __float_as_uint(Ps[rb * APITCH + kc]);
            unsigned a1 = __float_as_uint(Ps[(rb + 8) * APITCH + kc]);
            unsigned a2 = __float_as_uint(Ps[rb * APITCH + kc + 4]);
            unsigned a3 = __float_as_uint(Ps[(rb + 8) * APITCH + kc + 4]);
#pragma unroll
            for (int nt = 0; nt < 8; nt++) {
                const int nb = nt * 8 + fr;
                unsigned b0 = __float_as_uint(Vt[nb * APITCH + kc]);
                unsigned b1 = __float_as_uint(Vt[nb * APITCH + kc + 4]);
                mma_tf32(o[nt], a0, a1, a2, a3, b0, b1);
            }
        }
        __syncthreads();   // before next tile overwrites Ks/Vt
    }

    // ---- epilogue: O /= l, write to g_ctx [B, N, H*Dh] ----
    const int b = bh >> 4;
    const int h = bh & 15;
    const float inv0 = 1.f / l0;
    const float inv1 = 1.f / l1;
    const int r0 = q0 + w * 16 + fr;
#pragma unroll
    for (int nt = 0; nt < 8; nt++) {
        const int dv = nt * 8 + fc * 2;
        float* base0 = &g_ctx[((size_t)b * SEQ + r0) * D_MODEL + h * HEAD_DIM + dv];
        float* base1 = &g_ctx[((size_t)b * SEQ + r0 + 8) * D_MODEL + h * HEAD_DIM + dv];
        *(float2*)base0 = make_float2(o[nt][0] * inv0, o[nt][1] * inv0);
        *(float2*)base1 = make_float2(o[nt][2] * inv1, o[nt][3] * inv1);
    }
}

// ---------------------------------------------------------------------------
// kernel_launch
// ---------------------------------------------------------------------------
extern "C" void kernel_launch(void* const* d_in, const int* in_sizes, int n_in,
                              void* d_out, int out_size)
{
    const float* query = (const float*)d_in[0];
    const float* key   = (const float*)d_in[1];
    const float* value = (const float*)d_in[2];
    const float* Wq    = (const float*)d_in[3];
    const float* Wk    = (const float*)d_in[4];
    const float* Wv    = (const float*)d_in[5];
    const float* Wo    = (const float*)d_in[6];
    const float* bo    = (const float*)d_in[7];
    float* out = (float*)d_out;

    proj_kernel<<<dim3(D_MODEL / GBN, M_TOT / GBM, 3), 256>>>(query, key, value, Wq, Wk, Wv);

    cudaFuncSetAttribute(attn_kernel, cudaFuncAttributeMaxDynamicSharedMemorySize, ATTN_SMEM);
    attn_kernel<<<dim3(SEQ / QT, BATCH * NUM_HEADS), 256, ATTN_SMEM>>>();

    out_kernel<<<dim3(D_MODEL / GBN, M_TOT / GBM), 256>>>(Wo, bo, out);
}

// round 5
// speedup vs baseline: 2.8007x; 1.0231x over previous
#include <cuda_runtime.h>
#include <cuda_bf16.h>
#include <math.h>

// Problem constants
#define D_MODEL   1024
#define NUM_HEADS 16
#define HEAD_DIM  64
#define BATCH     2
#define SEQ       2048
#define M_TOT     (BATCH * SEQ)
#define ATT_SCALE 0.125f

// ---------------------------------------------------------------------------
// Scratch (device globals: allocation-free per harness rules)
// ---------------------------------------------------------------------------
__device__ float g_q[BATCH * NUM_HEADS * SEQ * HEAD_DIM];   // [B,H,N,Dh]
__device__ float g_k[BATCH * NUM_HEADS * SEQ * HEAD_DIM];
__device__ float g_v[BATCH * NUM_HEADS * SEQ * HEAD_DIM];
__device__ float g_ctx[BATCH * SEQ * D_MODEL];              // [B,N,H*Dh]

// ---------------------------------------------------------------------------
// tf32 helpers
// ---------------------------------------------------------------------------
__device__ __forceinline__ float to_tf32(float x) {
    unsigned u;
    asm("cvt.rna.tf32.f32 %0, %1;" : "=r"(u) : "f"(x));
    return __uint_as_float(u);
}

__device__ __forceinline__ void mma_tf32(float* c,
                                         unsigned a0, unsigned a1, unsigned a2, unsigned a3,
                                         unsigned b0, unsigned b1)
{
    asm volatile(
        "mma.sync.aligned.m16n8k8.row.col.f32.tf32.tf32.f32 "
        "{%0,%1,%2,%3}, {%4,%5,%6,%7}, {%8,%9}, {%0,%1,%2,%3};\n"
        : "+f"(c[0]), "+f"(c[1]), "+f"(c[2]), "+f"(c[3])
        : "r"(a0), "r"(a1), "r"(a2), "r"(a3), "r"(b0), "r"(b1));
}

// ---------------------------------------------------------------------------
// tf32 MMA GEMM: C = A @ W^T.  A [M,K] rm, W [N,K] rm.
// CTA tile 128x128x16, 128 threads = 4 warps (2m x 2n), warp tile 64x64.
// Double-buffered SMEM, one __syncthreads per k-iter, register prefetch.
// ---------------------------------------------------------------------------
#define GBM 128
#define GBN 128
#define GBK 16
#define GPITCH 20            // 16 + 4 pad -> conflict-free frag reads
#define GSTAGE (GBM * GPITCH)
#define NKB (D_MODEL / GBK)  // 64

__device__ __forceinline__ void gemm_tf32_body(const float* __restrict__ A,
                                               const float* __restrict__ W,
                                               float* __restrict__ O,
                                               const float* __restrict__ bo,
                                               int m0, int n0, int epilogue_mode)
{
    __shared__ float As[2][GSTAGE];
    __shared__ float Bs[2][GSTAGE];

    const int t    = threadIdx.x;       // 0..127
    const int lane = t & 31;
    const int wid  = t >> 5;            // 0..3
    const int wm   = wid & 1;           // 0..1
    const int wn   = wid >> 1;          // 0..1
    const int fr   = lane >> 2;         // 0..7
    const int fc   = lane & 3;          // 0..3
    const int K    = D_MODEL;

    float acc[4][8][4];
#pragma unroll
    for (int i = 0; i < 4; i++)
#pragma unroll
        for (int j = 0; j < 8; j++)
#pragma unroll
            for (int r = 0; r < 4; r++) acc[i][j][r] = 0.f;

    // staging mapping: f4 index i = t + 128u (u<4); row = i>>2, c4 = (i&3)*4
    const int srow = t >> 2;            // 0..31 (+32u)
    const int sc4  = (t & 3) * 4;

    float4 aV[4], bV[4];
#pragma unroll
    for (int u = 0; u < 4; u++) {
        aV[u] = *(const float4*)(A + (size_t)(m0 + srow + 32 * u) * K + sc4);
        bV[u] = *(const float4*)(W + (size_t)(n0 + srow + 32 * u) * K + sc4);
    }
    // prologue: stage tile 0
#pragma unroll
    for (int u = 0; u < 4; u++) {
        float* as = &As[0][(srow + 32 * u) * GPITCH + sc4];
        as[0] = to_tf32(aV[u].x); as[1] = to_tf32(aV[u].y);
        as[2] = to_tf32(aV[u].z); as[3] = to_tf32(aV[u].w);
        float* bs = &Bs[0][(srow + 32 * u) * GPITCH + sc4];
        bs[0] = to_tf32(bV[u].x); bs[1] = to_tf32(bV[u].y);
        bs[2] = to_tf32(bV[u].z); bs[3] = to_tf32(bV[u].w);
    }
    __syncthreads();

    for (int kb = 0; kb < NKB; kb++) {
        const int cur = kb & 1;
        const bool more = (kb + 1 < NKB);

        if (more) {
            const int k0 = (kb + 1) * GBK;
#pragma unroll
            for (int u = 0; u < 4; u++) {
                aV[u] = *(const float4*)(A + (size_t)(m0 + srow + 32 * u) * K + k0 + sc4);
                bV[u] = *(const float4*)(W + (size_t)(n0 + srow + 32 * u) * K + k0 + sc4);
            }
        }

#pragma unroll
        for (int ks = 0; ks < 2; ks++) {
            const int kc = ks * 8 + fc;
            unsigned af[4][4];
#pragma unroll
            for (int mt = 0; mt < 4; mt++) {
                const int rb = wm * 64 + mt * 16 + fr;
                af[mt][0] = __float_as_uint(As[cur][rb * GPITCH + kc]);
                af[mt][1] = __float_as_uint(As[cur][(rb + 8) * GPITCH + kc]);
                af[mt][2] = __float_as_uint(As[cur][rb * GPITCH + kc + 4]);
                af[mt][3] = __float_as_uint(As[cur][(rb + 8) * GPITCH + kc + 4]);
            }
#pragma unroll
            for (int nt = 0; nt < 8; nt++) {
                const int nb = wn * 64 + nt * 8 + fr;
                unsigned b0 = __float_as_uint(Bs[cur][nb * GPITCH + kc]);
                unsigned b1 = __float_as_uint(Bs[cur][nb * GPITCH + kc + 4]);
#pragma unroll
                for (int mt = 0; mt < 4; mt++)
                    mma_tf32(acc[mt][nt], af[mt][0], af[mt][1], af[mt][2], af[mt][3], b0, b1);
            }
        }

        if (more) {
            const int nxt = cur ^ 1;
#pragma unroll
            for (int u = 0; u < 4; u++) {
                float* as = &As[nxt][(srow + 32 * u) * GPITCH + sc4];
                as[0] = to_tf32(aV[u].x); as[1] = to_tf32(aV[u].y);
                as[2] = to_tf32(aV[u].z); as[3] = to_tf32(aV[u].w);
                float* bs = &Bs[nxt][(srow + 32 * u) * GPITCH + sc4];
                bs[0] = to_tf32(bV[u].x); bs[1] = to_tf32(bV[u].y);
                bs[2] = to_tf32(bV[u].z); bs[3] = to_tf32(bV[u].w);
            }
        }
        __syncthreads();
    }

    // epilogue: c0,c1 -> (row fr, col 2fc/2fc+1); c2,c3 -> row fr+8
#pragma unroll
    for (int mt = 0; mt < 4; mt++) {
        const int r0 = m0 + wm * 64 + mt * 16 + fr;
#pragma unroll
        for (int nt = 0; nt < 8; nt++) {
            const int col = n0 + wn * 64 + nt * 8 + fc * 2;
            if (epilogue_mode == 0) {
                const int h = col >> 6, d = col & 63;
#pragma unroll
                for (int half = 0; half < 2; half++) {
                    const int m  = r0 + half * 8;
                    const int b  = m >> 11;
                    const int nq = m & (SEQ - 1);
                    float2 o = make_float2(acc[mt][nt][half * 2], acc[mt][nt][half * 2 + 1]);
                    *(float2*)&O[(((size_t)b * NUM_HEADS + h) * SEQ + nq) * HEAD_DIM + d] = o;
                }
            } else {
                const float b0 = bo[col], b1 = bo[col + 1];
#pragma unroll
                for (int half = 0; half < 2; half++) {
                    const int m = r0 + half * 8;
                    float2 o = make_float2(acc[mt][nt][half * 2] + b0,
                                           acc[mt][nt][half * 2 + 1] + b1);
                    *(float2*)&O[(size_t)m * D_MODEL + col] = o;
                }
            }
        }
    }
}

__global__ __launch_bounds__(128)
void proj_kernel(const float* __restrict__ query,
                 const float* __restrict__ key,
                 const float* __restrict__ value,
                 const float* __restrict__ Wq,
                 const float* __restrict__ Wk,
                 const float* __restrict__ Wv)
{
    const int z = blockIdx.z;
    const float* A = (z == 0) ? query : ((z == 1) ? key : value);
    const float* W = (z == 0) ? Wq    : ((z == 1) ? Wk  : Wv);
    float*       O = (z == 0) ? g_q   : ((z == 1) ? g_k : g_v);
    gemm_tf32_body(A, W, O, nullptr, blockIdx.y * GBM, blockIdx.x * GBN, 0);
}

__global__ __launch_bounds__(128)
void out_kernel(const float* __restrict__ Wo,
                const float* __restrict__ bo,
                float* __restrict__ Cout)
{
    gemm_tf32_body(g_ctx, Wo, Cout, bo, blockIdx.y * GBM, blockIdx.x * GBN, 1);
}

// ---------------------------------------------------------------------------
// Flash attention with tf32 MMA, double-buffered K/V staging.
// Block = 128 q-rows of one (b,h). 256 threads = 8 warps; warp w owns q rows
// [w*16, w*16+16). Q frags in registers for the whole loop.
// SMEM (dynamic): Ps [128][68] (Q staging then P), Ks[2][64][68], Vt[2][64][68].
// ---------------------------------------------------------------------------
#define QT 128
#define KT 64
#define NT (SEQ / KT)                   // 32
#define APITCH 68
#define ABUF (KT * APITCH)              // 4352 floats
#define ATTN_SMEM ((QT * APITCH + 4 * ABUF) * 4)   // 104448 B

__global__ __launch_bounds__(256)
void attn_kernel()
{
    extern __shared__ float sm[];
    float* Ps  = sm;                    // [128][APITCH]
    float* KsB = sm + QT * APITCH;      // 2 x [64][APITCH]  K[j][d]
    float* VtB = KsB + 2 * ABUF;        // 2 x [64][APITCH]  V^T[dv][j]

    const int t    = threadIdx.x;
    const int lane = t & 31;
    const int w    = t >> 5;
    const int fr   = lane >> 2;
    const int fc   = lane & 3;

    const int q0 = blockIdx.x * QT;
    const int bh = blockIdx.y;
    const float* qb = g_q + (size_t)bh * SEQ * HEAD_DIM;
    const float* kb = g_k + (size_t)bh * SEQ * HEAD_DIM;
    const float* vb = g_v + (size_t)bh * SEQ * HEAD_DIM;

    // staging maps
    const int krow = t >> 4;            // 0..15 (+16u)  for Q/K staging
    const int kcc  = (t & 15) * 4;
    const int vj   = t & 63;            // V transpose map
    const int vdb  = (t >> 6) * 16;

    // ---- issue LDGs: Q tile (8 f4) and K/V tile 0 (4+4 f4) ----
    float4 qV[8], kV[4], vV[4];
#pragma unroll
    for (int u = 0; u < 8; u++) {
        const int row = (t >> 4) + 16 * u;      // 0..127
        qV[u] = *(const float4*)(qb + (size_t)(q0 + row) * HEAD_DIM + kcc);
    }
#pragma unroll
    for (int u = 0; u < 4; u++)
        kV[u] = *(const float4*)(kb + (size_t)(krow + 16 * u) * HEAD_DIM + kcc);
#pragma unroll
    for (int u = 0; u < 4; u++)
        vV[u] = *(const float4*)(vb + (size_t)vj * HEAD_DIM + vdb + 4 * u);

    // ---- stage Q (scaled, tf32) ----
#pragma unroll
    for (int u = 0; u < 8; u++) {
        const int row = (t >> 4) + 16 * u;
        float* p = &Ps[row * APITCH + kcc];
        p[0] = to_tf32(qV[u].x * ATT_SCALE); p[1] = to_tf32(qV[u].y * ATT_SCALE);
        p[2] = to_tf32(qV[u].z * ATT_SCALE); p[3] = to_tf32(qV[u].w * ATT_SCALE);
    }
    __syncthreads();

    unsigned qa[8][4];
#pragma unroll
    for (int ks = 0; ks < 8; ks++) {
        const int kc = ks * 8 + fc;
        const int rb = w * 16 + fr;
        qa[ks][0] = __float_as_uint(Ps[rb * APITCH + kc]);
        qa[ks][1] = __float_as_uint(Ps[(rb + 8) * APITCH + kc]);
        qa[ks][2] = __float_as_uint(Ps[rb * APITCH + kc + 4]);
        qa[ks][3] = __float_as_uint(Ps[(rb + 8) * APITCH + kc + 4]);
    }

    // ---- stage K/V tile 0 into buffer 0 ----
    {
        float* Ks = KsB;
        float* Vt = VtB;
#pragma unroll
        for (int u = 0; u < 4; u++) {
            float* p = &Ks[(krow + 16 * u) * APITCH + kcc];
            p[0] = to_tf32(kV[u].x); p[1] = to_tf32(kV[u].y);
            p[2] = to_tf32(kV[u].z); p[3] = to_tf32(kV[u].w);
        }
#pragma unroll
        for (int u = 0; u < 4; u++) {
            Vt[(vdb + 4 * u + 0) * APITCH + vj] = to_tf32(vV[u].x);
            Vt[(vdb + 4 * u + 1) * APITCH + vj] = to_tf32(vV[u].y);
            Vt[(vdb + 4 * u + 2) * APITCH + vj] = to_tf32(vV[u].z);
            Vt[(vdb + 4 * u + 3) * APITCH + vj] = to_tf32(vV[u].w);
        }
    }
    __syncthreads();   // buf0 ready; also guards Ps reuse (qa frags read by all)

    float o[8][4];
    float m0 = -1e30f, m1 = -1e30f, l0 = 0.f, l1 = 0.f;
#pragma unroll
    for (int nt = 0; nt < 8; nt++)
#pragma unroll
        for (int r = 0; r < 4; r++) o[nt][r] = 0.f;

    for (int kt = 0; kt < NT; kt++) {
        const int cur = kt & 1;
        const bool more = (kt + 1 < NT);
        float* Ks = KsB + cur * ABUF;
        float* Vt = VtB + cur * ABUF;

        if (more) {
            const int j0 = (kt + 1) * KT;
#pragma unroll
            for (int u = 0; u < 4; u++)
                kV[u] = *(const float4*)(kb + (size_t)(j0 + krow + 16 * u) * HEAD_DIM + kcc);
#pragma unroll
            for (int u = 0; u < 4; u++)
                vV[u] = *(const float4*)(vb + (size_t)(j0 + vj) * HEAD_DIM + vdb + 4 * u);
        }

        // ---- S = Q @ K^T (warp tile 16 x 64) ----
        float s[8][4];
#pragma unroll
        for (int nt = 0; nt < 8; nt++)
#pragma unroll
            for (int r = 0; r < 4; r++) s[nt][r] = 0.f;

#pragma unroll
        for (int ks = 0; ks < 8; ks++) {
            const int kc = ks * 8 + fc;
#pragma unroll
            for (int nt = 0; nt < 8; nt++) {
                const int nb = nt * 8 + fr;
                unsigned b0 = __float_as_uint(Ks[nb * APITCH + kc]);
                unsigned b1 = __float_as_uint(Ks[nb * APITCH + kc + 4]);
                mma_tf32(s[nt], qa[ks][0], qa[ks][1], qa[ks][2], qa[ks][3], b0, b1);
            }
        }

        // ---- online softmax ----
        float rm0 = -1e30f, rm1 = -1e30f;
#pragma unroll
        for (int nt = 0; nt < 8; nt++) {
            rm0 = fmaxf(rm0, fmaxf(s[nt][0], s[nt][1]));
            rm1 = fmaxf(rm1, fmaxf(s[nt][2], s[nt][3]));
        }
        rm0 = fmaxf(rm0, __shfl_xor_sync(0xffffffffu, rm0, 1));
        rm0 = fmaxf(rm0, __shfl_xor_sync(0xffffffffu, rm0, 2));
        rm1 = fmaxf(rm1, __shfl_xor_sync(0xffffffffu, rm1, 1));
        rm1 = fmaxf(rm1, __shfl_xor_sync(0xffffffffu, rm1, 2));

        const float mn0 = fmaxf(m0, rm0);
        const float mn1 = fmaxf(m1, rm1);
        const float cr0 = __expf(m0 - mn0);
        const float cr1 = __expf(m1 - mn1);
        m0 = mn0; m1 = mn1;

        float rs0 = 0.f, rs1 = 0.f;
        const int wr = w * 16 + fr;
#pragma unroll
        for (int nt = 0; nt < 8; nt++) {
            float p00 = __expf(s[nt][0] - mn0);
            float p01 = __expf(s[nt][1] - mn0);
            float p10 = __expf(s[nt][2] - mn1);
            float p11 = __expf(s[nt][3] - mn1);
            rs0 += p00 + p01;
            rs1 += p10 + p11;
            const int col = nt * 8 + fc * 2;
            *(float2*)&Ps[wr * APITCH + col]       = make_float2(to_tf32(p00), to_tf32(p01));
            *(float2*)&Ps[(wr + 8) * APITCH + col] = make_float2(to_tf32(p10), to_tf32(p11));
        }
        rs0 += __shfl_xor_sync(0xffffffffu, rs0, 1);
        rs0 += __shfl_xor_sync(0xffffffffu, rs0, 2);
        rs1 += __shfl_xor_sync(0xffffffffu, rs1, 1);
        rs1 += __shfl_xor_sync(0xffffffffu, rs1, 2);
        l0 = l0 * cr0 + rs0;
        l1 = l1 * cr1 + rs1;

#pragma unroll
        for (int nt = 0; nt < 8; nt++) {
            o[nt][0] *= cr0; o[nt][1] *= cr0;
            o[nt][2] *= cr1; o[nt][3] *= cr1;
        }
        __syncwarp();      // this warp's P rows visible to itself

        // ---- O += P @ V ----
#pragma unroll
        for (int ks = 0; ks < 8; ks++) {
            const int kc = ks * 8 + fc;
            const int rb = w * 16 + fr;
            unsigned a0 = __float_as_uint(Ps[rb * APITCH + kc]);
            unsigned a1 = __float_as_uint(Ps[(rb + 8) * APITCH + kc]);
            unsigned a2 = __float_as_uint(Ps[rb * APITCH + kc + 4]);
            unsigned a3 = __float_as_uint(Ps[(rb + 8) * APITCH + kc + 4]);
#pragma unroll
            for (int nt = 0; nt < 8; nt++) {
                const int nb = nt * 8 + fr;
                unsigned b0 = __float_as_uint(Vt[nb * APITCH + kc]);
                unsigned b1 = __float_as_uint(Vt[nb * APITCH + kc + 4]);
                mma_tf32(o[nt], a0, a1, a2, a3, b0, b1);
            }
        }

        // ---- stage next tile into alternate buffer ----
        if (more) {
            float* Ksn = KsB + (cur ^ 1) * ABUF;
            float* Vtn = VtB + (cur ^ 1) * ABUF;
#pragma unroll
            for (int u = 0; u < 4; u++) {
                float* p = &Ksn[(krow + 16 * u) * APITCH + kcc];
                p[0] = to_tf32(kV[u].x); p[1] = to_tf32(kV[u].y);
                p[2] = to_tf32(kV[u].z); p[3] = to_tf32(kV[u].w);
            }
#pragma unroll
            for (int u = 0; u < 4; u++) {
                Vtn[(vdb + 4 * u + 0) * APITCH + vj] = to_tf32(vV[u].x);
                Vtn[(vdb + 4 * u + 1) * APITCH + vj] = to_tf32(vV[u].y);
                Vtn[(vdb + 4 * u + 2) * APITCH + vj] = to_tf32(vV[u].z);
                Vtn[(vdb + 4 * u + 3) * APITCH + vj] = to_tf32(vV[u].w);
            }
        }
        __syncthreads();
    }

    // ---- epilogue: O /= l, write g_ctx [B, N, H*Dh] ----
    const int b = bh >> 4;
    const int h = bh & 15;
    const float inv0 = 1.f / l0;
    const float inv1 = 1.f / l1;
    const int r0 = q0 + w * 16 + fr;
#pragma unroll
    for (int nt = 0; nt < 8; nt++) {
        const int dv = nt * 8 + fc * 2;
        float* base0 = &g_ctx[((size_t)b * SEQ + r0) * D_MODEL + h * HEAD_DIM + dv];
        float* base1 = &g_ctx[((size_t)b * SEQ + r0 + 8) * D_MODEL + h * HEAD_DIM + dv];
        *(float2*)base0 = make_float2(o[nt][0] * inv0, o[nt][1] * inv0);
        *(float2*)base1 = make_float2(o[nt][2] * inv1, o[nt][3] * inv1);
    }
}

// ---------------------------------------------------------------------------
// kernel_launch
// ---------------------------------------------------------------------------
extern "C" void kernel_launch(void* const* d_in, const int* in_sizes, int n_in,
                              void* d_out, int out_size)
{
    const float* query = (const float*)d_in[0];
    const float* key   = (const float*)d_in[1];
    const float* value = (const float*)d_in[2];
    const float* Wq    = (const float*)d_in[3];
    const float* Wk    = (const float*)d_in[4];
    const float* Wv    = (const float*)d_in[5];
    const float* Wo    = (const float*)d_in[6];
    const float* bo    = (const float*)d_in[7];
    float* out = (float*)d_out;

    proj_kernel<<<dim3(D_MODEL / GBN, M_TOT / GBM, 3), 128>>>(query, key, value, Wq, Wk, Wv);

    cudaFuncSetAttribute(attn_kernel, cudaFuncAttributeMaxDynamicSharedMemorySize, ATTN_SMEM);
    attn_kernel<<<dim3(SEQ / QT, BATCH * NUM_HEADS), 256, ATTN_SMEM>>>();

    out_kernel<<<dim3(D_MODEL / GBN, M_TOT / GBM), 128>>>(Wo, bo, out);
}

// round 7
// speedup vs baseline: 2.8413x; 1.0145x over previous
#include <cuda_runtime.h>
#include <cuda_bf16.h>
#include <cstdint>
#include <math.h>

// Problem constants
#define D_MODEL   1024
#define NUM_HEADS 16
#define HEAD_DIM  64
#define BATCH     2
#define SEQ       2048
#define M_TOT     (BATCH * SEQ)
#define ATT_SCALE 0.125f

// ---------------------------------------------------------------------------
// Scratch (device globals: allocation-free per harness rules)
// ---------------------------------------------------------------------------
__device__ float g_q[BATCH * NUM_HEADS * SEQ * HEAD_DIM];   // [B,H,N,Dh]
__device__ float g_k[BATCH * NUM_HEADS * SEQ * HEAD_DIM];
__device__ float g_v[BATCH * NUM_HEADS * SEQ * HEAD_DIM];
__device__ float g_ctx[BATCH * SEQ * D_MODEL];              // [B,N,H*Dh]

// ---------------------------------------------------------------------------
// helpers
// ---------------------------------------------------------------------------
__device__ __forceinline__ uint32_t smem_to_u32(const void* p) {
    uint32_t a;
    asm("{ .reg .u64 t; cvta.to.shared.u64 t, %1; cvt.u32.u64 %0, t; }" : "=r"(a) : "l"(p));
    return a;
}

__device__ __forceinline__ float to_tf32(float x) {
    unsigned u;
    asm("cvt.rna.tf32.f32 %0, %1;" : "=r"(u) : "f"(x));
    return __uint_as_float(u);
}

__device__ __forceinline__ void mma_tf32(float* c,
                                         unsigned a0, unsigned a1, unsigned a2, unsigned a3,
                                         unsigned b0, unsigned b1)
{
    asm volatile(
        "mma.sync.aligned.m16n8k8.row.col.f32.tf32.tf32.f32 "
        "{%0,%1,%2,%3}, {%4,%5,%6,%7}, {%8,%9}, {%0,%1,%2,%3};\n"
        : "+f"(c[0]), "+f"(c[1]), "+f"(c[2]), "+f"(c[3])
        : "r"(a0), "r"(a1), "r"(a2), "r"(a3), "r"(b0), "r"(b1));
}

// ldmatrix x4: four 8x8 b16 (= 8x4 f32) matrices; per-lane addr selects rows.
__device__ __forceinline__ void ldsm_x4(uint32_t& d0, uint32_t& d1,
                                        uint32_t& d2, uint32_t& d3, uint32_t addr)
{
    asm volatile("ldmatrix.sync.aligned.m8n8.x4.shared.b16 {%0,%1,%2,%3}, [%4];"
                 : "=r"(d0), "=r"(d1), "=r"(d2), "=r"(d3) : "r"(addr));
}

// ---------------------------------------------------------------------------
// tf32 MMA GEMM: C = A @ W^T.  A [M,K] rm, W [N,K] rm.
// CTA tile 128x128x16, 128 threads = 4 warps (2m x 2n), warp tile 64x64.
// Double-buffered SMEM, ldmatrix fragment loads, register prefetch.
// ---------------------------------------------------------------------------
#define GBM 128
#define GBN 128
#define GBK 16
#define GPITCH 20            // 16 + 4 pad -> conflict-free (LDSM phases verified)
#define GSTAGE (GBM * GPITCH)
#define NKB (D_MODEL / GBK)  // 64

__device__ __forceinline__ void gemm_tf32_body(const float* __restrict__ A,
                                               const float* __restrict__ W,
                                               float* __restrict__ O,
                                               const float* __restrict__ bo,
                                               int m0, int n0, int epilogue_mode)
{
    __shared__ __align__(16) float As[2][GSTAGE];
    __shared__ __align__(16) float Bs[2][GSTAGE];

    const int t    = threadIdx.x;       // 0..127
    const int lane = t & 31;
    const int wid  = t >> 5;            // 0..3
    const int wm   = wid & 1;
    const int wn   = wid >> 1;
    const int fr   = lane >> 2;
    const int fc   = lane & 3;
    const int g    = lane >> 3;         // ldmatrix address group 0..3
    const int li   = lane & 7;          // row within group
    const int K    = D_MODEL;

    const uint32_t asb[2] = { smem_to_u32(&As[0][0]), smem_to_u32(&As[1][0]) };
    const uint32_t bsb[2] = { smem_to_u32(&Bs[0][0]), smem_to_u32(&Bs[1][0]) };

    float acc[4][8][4];
#pragma unroll
    for (int i = 0; i < 4; i++)
#pragma unroll
        for (int j = 0; j < 8; j++)
#pragma unroll
            for (int r = 0; r < 4; r++) acc[i][j][r] = 0.f;

    // staging mapping: f4 index i = t + 128u (u<4); row = i>>2, c4 = (i&3)*4
    const int srow = t >> 2;            // 0..31 (+32u)
    const int sc4  = (t & 3) * 4;

    float4 aV[4], bV[4];
#pragma unroll
    for (int u = 0; u < 4; u++) {
        aV[u] = *(const float4*)(A + (size_t)(m0 + srow + 32 * u) * K + sc4);
        bV[u] = *(const float4*)(W + (size_t)(n0 + srow + 32 * u) * K + sc4);
    }
#pragma unroll
    for (int u = 0; u < 4; u++) {
        float* as = &As[0][(srow + 32 * u) * GPITCH + sc4];
        as[0] = to_tf32(aV[u].x); as[1] = to_tf32(aV[u].y);
        as[2] = to_tf32(aV[u].z); as[3] = to_tf32(aV[u].w);
        float* bs = &Bs[0][(srow + 32 * u) * GPITCH + sc4];
        bs[0] = to_tf32(bV[u].x); bs[1] = to_tf32(bV[u].y);
        bs[2] = to_tf32(bV[u].z); bs[3] = to_tf32(bV[u].w);
    }
    __syncthreads();

    for (int kb = 0; kb < NKB; kb++) {
        const int cur = kb & 1;
        const bool more = (kb + 1 < NKB);

        if (more) {
            const int k0 = (kb + 1) * GBK;
#pragma unroll
            for (int u = 0; u < 4; u++) {
                aV[u] = *(const float4*)(A + (size_t)(m0 + srow + 32 * u) * K + k0 + sc4);
                bV[u] = *(const float4*)(W + (size_t)(n0 + srow + 32 * u) * K + k0 + sc4);
            }
        }

#pragma unroll
        for (int ks = 0; ks < 2; ks++) {
            const int kc0 = ks * 8;
            uint32_t af[4][4];
#pragma unroll
            for (int mt = 0; mt < 4; mt++) {
                const int row = wm * 64 + mt * 16 + (g & 1) * 8 + li;
                const uint32_t addr = asb[cur] +
                    (uint32_t)((row * GPITCH + kc0 + (g >> 1) * 4) * 4);
                ldsm_x4(af[mt][0], af[mt][1], af[mt][2], af[mt][3], addr);
            }
            uint32_t bf[8][2];
#pragma unroll
            for (int np = 0; np < 4; np++) {
                const int row = wn * 64 + np * 16 + (g >> 1) * 8 + li;
                const uint32_t addr = bsb[cur] +
                    (uint32_t)((row * GPITCH + kc0 + (g & 1) * 4) * 4);
                ldsm_x4(bf[2 * np][0], bf[2 * np][1],
                        bf[2 * np + 1][0], bf[2 * np + 1][1], addr);
            }
#pragma unroll
            for (int nt = 0; nt < 8; nt++)
#pragma unroll
                for (int mt = 0; mt < 4; mt++)
                    mma_tf32(acc[mt][nt], af[mt][0], af[mt][1], af[mt][2], af[mt][3],
                             bf[nt][0], bf[nt][1]);
        }

        if (more) {
            const int nxt = cur ^ 1;
#pragma unroll
            for (int u = 0; u < 4; u++) {
                float* as = &As[nxt][(srow + 32 * u) * GPITCH + sc4];
                as[0] = to_tf32(aV[u].x); as[1] = to_tf32(aV[u].y);
                as[2] = to_tf32(aV[u].z); as[3] = to_tf32(aV[u].w);
                float* bs = &Bs[nxt][(srow + 32 * u) * GPITCH + sc4];
                bs[0] = to_tf32(bV[u].x); bs[1] = to_tf32(bV[u].y);
                bs[2] = to_tf32(bV[u].z); bs[3] = to_tf32(bV[u].w);
            }
        }
        __syncthreads();
    }

    // epilogue
#pragma unroll
    for (int mt = 0; mt < 4; mt++) {
        const int r0 = m0 + wm * 64 + mt * 16 + fr;
#pragma unroll
        for (int nt = 0; nt < 8; nt++) {
            const int col = n0 + wn * 64 + nt * 8 + fc * 2;
            if (epilogue_mode == 0) {
                const int h = col >> 6, d = col & 63;
#pragma unroll
                for (int half = 0; half < 2; half++) {
                    const int m  = r0 + half * 8;
                    const int b  = m >> 11;
                    const int nq = m & (SEQ - 1);
                    float2 o = make_float2(acc[mt][nt][half * 2], acc[mt][nt][half * 2 + 1]);
                    *(float2*)&O[(((size_t)b * NUM_HEADS + h) * SEQ + nq) * HEAD_DIM + d] = o;
                }
            } else {
                const float b0 = bo[col], b1 = bo[col + 1];
#pragma unroll
                for (int half = 0; half < 2; half++) {
                    const int m = r0 + half * 8;
                    float2 o = make_float2(acc[mt][nt][half * 2] + b0,
                                           acc[mt][nt][half * 2 + 1] + b1);
                    *(float2*)&O[(size_t)m * D_MODEL + col] = o;
                }
            }
        }
    }
}

__global__ __launch_bounds__(128)
void proj_kernel(const float* __restrict__ query,
                 const float* __restrict__ key,
                 const float* __restrict__ value,
                 const float* __restrict__ Wq,
                 const float* __restrict__ Wk,
                 const float* __restrict__ Wv)
{
    const int z = blockIdx.z;
    const float* A = (z == 0) ? query : ((z == 1) ? key : value);
    const float* W = (z == 0) ? Wq    : ((z == 1) ? Wk  : Wv);
    float*       O = (z == 0) ? g_q   : ((z == 1) ? g_k : g_v);
    gemm_tf32_body(A, W, O, nullptr, blockIdx.y * GBM, blockIdx.x * GBN, 0);
}

__global__ __launch_bounds__(128)
void out_kernel(const float* __restrict__ Wo,
                const float* __restrict__ bo,
                float* __restrict__ Cout)
{
    gemm_tf32_body(g_ctx, Wo, Cout, bo, blockIdx.y * GBM, blockIdx.x * GBN, 1);
}

// ---------------------------------------------------------------------------
// Flash attention with tf32 MMA, double-buffered K/V staging, ldmatrix frags.
// Block = 128 q-rows of one (b,h). 256 threads = 8 warps; warp w owns q rows
// [w*16, w*16+16). Q frags in registers for the whole loop.
// SMEM (dynamic): Ps [128][68] (Q staging then P), Ks[2][64][68], Vt[2][64][68].
// ---------------------------------------------------------------------------
#define QT 128
#define KT 64
#define NT (SEQ / KT)                   // 32
#define APITCH 68
#define ABUF (KT * APITCH)              // 4352 floats
#define ATTN_SMEM ((QT * APITCH + 4 * ABUF) * 4)   // 104448 B

__global__ __launch_bounds__(256)
void attn_kernel()
{
    extern __shared__ __align__(16) float sm[];
    float* Ps  = sm;                    // [128][APITCH]
    float* KsB = sm + QT * APITCH;      // 2 x [64][APITCH]  K[j][d]
    float* VtB = KsB + 2 * ABUF;        // 2 x [64][APITCH]  V^T[dv][j]

    const int t    = threadIdx.x;
    const int lane = t & 31;
    const int w    = t >> 5;
    const int fr   = lane >> 2;
    const int fc   = lane & 3;
    const int g    = lane >> 3;
    const int li   = lane & 7;

    const uint32_t ps_u  = smem_to_u32(sm);
    const uint32_t ksb_u = ps_u + QT * APITCH * 4;
    const uint32_t vtb_u = ksb_u + 2 * ABUF * 4;

    const int q0 = blockIdx.x * QT;
    const int bh = blockIdx.y;
    const float* qb = g_q + (size_t)bh * SEQ * HEAD_DIM;
    const float* kb = g_k + (size_t)bh * SEQ * HEAD_DIM;
    const float* vb = g_v + (size_t)bh * SEQ * HEAD_DIM;

    // staging maps
    const int krow = t >> 4;            // 0..15 (+16u)
    const int kcc  = (t & 15) * 4;
    const int vj   = t & 63;
    const int vdb  = (t >> 6) * 16;

    // ---- issue LDGs: Q tile and K/V tile 0 ----
    float4 qV[8], kV[4], vV[4];
#pragma unroll
    for (int u = 0; u < 8; u++) {
        const int row = (t >> 4) + 16 * u;
        qV[u] = *(const float4*)(qb + (size_t)(q0 + row) * HEAD_DIM + kcc);
    }
#pragma unroll
    for (int u = 0; u < 4; u++)
        kV[u] = *(const float4*)(kb + (size_t)(krow + 16 * u) * HEAD_DIM + kcc);
#pragma unroll
    for (int u = 0; u < 4; u++)
        vV[u] = *(const float4*)(vb + (size_t)vj * HEAD_DIM + vdb + 4 * u);

    // ---- stage Q (scaled, tf32) ----
#pragma unroll
    for (int u = 0; u < 8; u++) {
        const int row = (t >> 4) + 16 * u;
        float* p = &Ps[row * APITCH + kcc];
        p[0] = to_tf32(qV[u].x * ATT_SCALE); p[1] = to_tf32(qV[u].y * ATT_SCALE);
        p[2] = to_tf32(qV[u].z * ATT_SCALE); p[3] = to_tf32(qV[u].w * ATT_SCALE);
    }
    __syncthreads();

    unsigned qa[8][4];
#pragma unroll
    for (int ks = 0; ks < 8; ks++) {
        // ldmatrix A-pattern from Ps: rows w*16 .. +16, cols ks*8 .. +8
        const int row = w * 16 + (g & 1) * 8 + li;
        const uint32_t addr = ps_u + (uint32_t)((row * APITCH + ks * 8 + (g >> 1) * 4) * 4);
        ldsm_x4(qa[ks][0], qa[ks][1], qa[ks][2], qa[ks][3], addr);
    }

    // ---- stage K/V tile 0 into buffer 0 ----
    {
        float* Ks = KsB;
        float* Vt = VtB;
#pragma unroll
        for (int u = 0; u < 4; u++) {
            float* p = &Ks[(krow + 16 * u) * APITCH + kcc];
            p[0] = to_tf32(kV[u].x); p[1] = to_tf32(kV[u].y);
            p[2] = to_tf32(kV[u].z); p[3] = to_tf32(kV[u].w);
        }
#pragma unroll
        for (int u = 0; u < 4; u++) {
            Vt[(vdb + 4 * u + 0) * APITCH + vj] = to_tf32(vV[u].x);
            Vt[(vdb + 4 * u + 1) * APITCH + vj] = to_tf32(vV[u].y);
            Vt[(vdb + 4 * u + 2) * APITCH + vj] = to_tf32(vV[u].z);
            Vt[(vdb + 4 * u + 3) * APITCH + vj] = to_tf32(vV[u].w);
        }
    }
    __syncthreads();

    float o[8][4];
    float m0 = -1e30f, m1 = -1e30f, l0 = 0.f, l1 = 0.f;
#pragma unroll
    for (int nt = 0; nt < 8; nt++)
#pragma unroll
        for (int r = 0; r < 4; r++) o[nt][r] = 0.f;

    for (int kt = 0; kt < NT; kt++) {
        const int cur = kt & 1;
        const bool more = (kt + 1 < NT);
        const uint32_t ks_u = ksb_u + (uint32_t)(cur * ABUF * 4);
        const uint32_t vt_u = vtb_u + (uint32_t)(cur * ABUF * 4);

        if (more) {
            const int j0 = (kt + 1) * KT;
#pragma unroll
            for (int u = 0; u < 4; u++)
                kV[u] = *(const float4*)(kb + (size_t)(j0 + krow + 16 * u) * HEAD_DIM + kcc);
#pragma unroll
            for (int u = 0; u < 4; u++)
                vV[u] = *(const float4*)(vb + (size_t)(j0 + vj) * HEAD_DIM + vdb + 4 * u);
        }

        // ---- S = Q @ K^T ----
        float s[8][4];
#pragma unroll
        for (int nt = 0; nt < 8; nt++)
#pragma unroll
            for (int r = 0; r < 4; r++) s[nt][r] = 0.f;

#pragma unroll
        for (int ks = 0; ks < 8; ks++) {
            const int kc0 = ks * 8;
            uint32_t bf[8][2];
#pragma unroll
            for (int np = 0; np < 4; np++) {
                const int row = np * 16 + (g >> 1) * 8 + li;
                const uint32_t addr = ks_u + (uint32_t)((row * APITCH + kc0 + (g & 1) * 4) * 4);
                ldsm_x4(bf[2 * np][0], bf[2 * np][1],
                        bf[2 * np + 1][0], bf[2 * np + 1][1], addr);
            }
#pragma unroll
            for (int nt = 0; nt < 8; nt++)
                mma_tf32(s[nt], qa[ks][0], qa[ks][1], qa[ks][2], qa[ks][3],
                         bf[nt][0], bf[nt][1]);
        }

        // ---- online softmax ----
        float rm0 = -1e30f, rm1 = -1e30f;
#pragma unroll
        for (int nt = 0; nt < 8; nt++) {
            rm0 = fmaxf(rm0, fmaxf(s[nt][0], s[nt][1]));
            rm1 = fmaxf(rm1, fmaxf(s[nt][2], s[nt][3]));
        }
        rm0 = fmaxf(rm0, __shfl_xor_sync(0xffffffffu, rm0, 1));
        rm0 = fmaxf(rm0, __shfl_xor_sync(0xffffffffu, rm0, 2));
        rm1 = fmaxf(rm1, __shfl_xor_sync(0xffffffffu, rm1, 1));
        rm1 = fmaxf(rm1, __shfl_xor_sync(0xffffffffu, rm1, 2));

        const float mn0 = fmaxf(m0, rm0);
        const float mn1 = fmaxf(m1, rm1);
        const float cr0 = __expf(m0 - mn0);
        const float cr1 = __expf(m1 - mn1);
        m0 = mn0; m1 = mn1;

        float rs0 = 0.f, rs1 = 0.f;
        const int wr = w * 16 + fr;
#pragma unroll
        for (int nt = 0; nt < 8; nt++) {
            float p00 = __expf(s[nt][0] - mn0);
            float p01 = __expf(s[nt][1] - mn0);
            float p10 = __expf(s[nt][2] - mn1);
            float p11 = __expf(s[nt][3] - mn1);
            rs0 += p00 + p01;
            rs1 += p10 + p11;
            const int col = nt * 8 + fc * 2;
            *(float2*)&Ps[wr * APITCH + col]       = make_float2(to_tf32(p00), to_tf32(p01));
            *(float2*)&Ps[(wr + 8) * APITCH + col] = make_float2(to_tf32(p10), to_tf32(p11));
        }
        rs0 += __shfl_xor_sync(0xffffffffu, rs0, 1);
        rs0 += __shfl_xor_sync(0xffffffffu, rs0, 2);
        rs1 += __shfl_xor_sync(0xffffffffu, rs1, 1);
        rs1 += __shfl_xor_sync(0xffffffffu, rs1, 2);
        l0 = l0 * cr0 + rs0;
        l1 = l1 * cr1 + rs1;

#pragma unroll
        for (int nt = 0; nt < 8; nt++) {
            o[nt][0] *= cr0; o[nt][1] *= cr0;
            o[nt][2] *= cr1; o[nt][3] *= cr1;
        }
        __syncwarp();      // this warp's P rows visible to itself

        // ---- O += P @ V ----
#pragma unroll
        for (int ks = 0; ks < 8; ks++) {
            const int kc0 = ks * 8;
            // A-frag from Ps (this warp's 16 rows)
            uint32_t a0, a1, a2, a3;
            {
                const int row = w * 16 + (g & 1) * 8 + li;
                const uint32_t addr = ps_u + (uint32_t)((row * APITCH + kc0 + (g >> 1) * 4) * 4);
                ldsm_x4(a0, a1, a2, a3, addr);
            }
            uint32_t bf[8][2];
#pragma unroll
            for (int np = 0; np < 4; np++) {
                const int row = np * 16 + (g >> 1) * 8 + li;
                const uint32_t addr = vt_u + (uint32_t)((row * APITCH + kc0 + (g & 1) * 4) * 4);
                ldsm_x4(bf[2 * np][0], bf[2 * np][1],
                        bf[2 * np + 1][0], bf[2 * np + 1][1], addr);
            }
#pragma unroll
            for (int nt = 0; nt < 8; nt++)
                mma_tf32(o[nt], a0, a1, a2, a3, bf[nt][0], bf[nt][1]);
        }

        // ---- stage next tile into alternate buffer ----
        if (more) {
            float* Ksn = KsB + (cur ^ 1) * ABUF;
            float* Vtn = VtB + (cur ^ 1) * ABUF;
#pragma unroll
            for (int u = 0; u < 4; u++) {
                float* p = &Ksn[(krow + 16 * u) * APITCH + kcc];
                p[0] = to_tf32(kV[u].x); p[1] = to_tf32(kV[u].y);
                p[2] = to_tf32(kV[u].z); p[3] = to_tf32(kV[u].w);
            }
#pragma unroll
            for (int u = 0; u < 4; u++) {
                Vtn[(vdb + 4 * u + 0) * APITCH + vj] = to_tf32(vV[u].x);
                Vtn[(vdb + 4 * u + 1) * APITCH + vj] = to_tf32(vV[u].y);
                Vtn[(vdb + 4 * u + 2) * APITCH + vj] = to_tf32(vV[u].z);
                Vtn[(vdb + 4 * u + 3) * APITCH + vj] = to_tf32(vV[u].w);
            }
        }
        __syncthreads();
    }

    // ---- epilogue: O /= l, write g_ctx [B, N, H*Dh] ----
    const int b = bh >> 4;
    const int h = bh & 15;
    const float inv0 = 1.f / l0;
    const float inv1 = 1.f / l1;
    const int r0 = q0 + w * 16 + fr;
#pragma unroll
    for (int nt = 0; nt < 8; nt++) {
        const int dv = nt * 8 + fc * 2;
        float* base0 = &g_ctx[((size_t)b * SEQ + r0) * D_MODEL + h * HEAD_DIM + dv];
        float* base1 = &g_ctx[((size_t)b * SEQ + r0 + 8) * D_MODEL + h * HEAD_DIM + dv];
        *(float2*)base0 = make_float2(o[nt][0] * inv0, o[nt][1] * inv0);
        *(float2*)base1 = make_float2(o[nt][2] * inv1, o[nt][3] * inv1);
    }
}

// ---------------------------------------------------------------------------
// kernel_launch
// ---------------------------------------------------------------------------
extern "C" void kernel_launch(void* const* d_in, const int* in_sizes, int n_in,
                              void* d_out, int out_size)
{
    const float* query = (const float*)d_in[0];
    const float* key   = (const float*)d_in[1];
    const float* value = (const float*)d_in[2];
    const float* Wq    = (const float*)d_in[3];
    const float* Wk    = (const float*)d_in[4];
    const float* Wv    = (const float*)d_in[5];
    const float* Wo    = (const float*)d_in[6];
    const float* bo    = (const float*)d_in[7];
    float* out = (float*)d_out;

    proj_kernel<<<dim3(D_MODEL / GBN, M_TOT / GBM, 3), 128>>>(query, key, value, Wq, Wk, Wv);

    cudaFuncSetAttribute(attn_kernel, cudaFuncAttributeMaxDynamicSharedMemorySize, ATTN_SMEM);
    attn_kernel<<<dim3(SEQ / QT, BATCH * NUM_HEADS), 256, ATTN_SMEM>>>();

    out_kernel<<<dim3(D_MODEL / GBN, M_TOT / GBM), 128>>>(Wo, bo, out);
}

// round 8
// speedup vs baseline: 2.8886x; 1.0167x over previous
#include <cuda_runtime.h>
#include <cuda_bf16.h>
#include <cstdint>
#include <math.h>

// Problem constants
#define D_MODEL   1024
#define NUM_HEADS 16
#define HEAD_DIM  64
#define BATCH     2
#define SEQ       2048
#define M_TOT     (BATCH * SEQ)
#define ATT_SCALE 0.125f

// ---------------------------------------------------------------------------
// Scratch (device globals: allocation-free per harness rules)
// ---------------------------------------------------------------------------
__device__ float g_q[BATCH * NUM_HEADS * SEQ * HEAD_DIM];   // [B,H,N,Dh] tf32-rounded, pre-scaled
__device__ float g_k[BATCH * NUM_HEADS * SEQ * HEAD_DIM];   // tf32-rounded
__device__ float g_v[BATCH * NUM_HEADS * SEQ * HEAD_DIM];   // tf32-rounded
__device__ float g_ctx[BATCH * SEQ * D_MODEL];              // tf32-rounded

__device__ float r_q[M_TOT * D_MODEL];     // rounded query
__device__ float r_k[M_TOT * D_MODEL];     // rounded key
__device__ float r_v[M_TOT * D_MODEL];     // rounded value
__device__ float r_wq[D_MODEL * D_MODEL];  // rounded 0.125*Wq
__device__ float r_wk[D_MODEL * D_MODEL];
__device__ float r_wv[D_MODEL * D_MODEL];
__device__ float r_wo[D_MODEL * D_MODEL];

// ---------------------------------------------------------------------------
// helpers
// ---------------------------------------------------------------------------
__device__ __forceinline__ uint32_t smem_to_u32(const void* p) {
    uint32_t a;
    asm("{ .reg .u64 t; cvta.to.shared.u64 t, %1; cvt.u32.u64 %0, t; }" : "=r"(a) : "l"(p));
    return a;
}

__device__ __forceinline__ float to_tf32(float x) {
    unsigned u;
    asm("cvt.rna.tf32.f32 %0, %1;" : "=r"(u) : "f"(x));
    return __uint_as_float(u);
}

__device__ __forceinline__ void mma_tf32(float* c,
                                         unsigned a0, unsigned a1, unsigned a2, unsigned a3,
                                         unsigned b0, unsigned b1)
{
    asm volatile(
        "mma.sync.aligned.m16n8k8.row.col.f32.tf32.tf32.f32 "
        "{%0,%1,%2,%3}, {%4,%5,%6,%7}, {%8,%9}, {%0,%1,%2,%3};\n"
        : "+f"(c[0]), "+f"(c[1]), "+f"(c[2]), "+f"(c[3])
        : "r"(a0), "r"(a1), "r"(a2), "r"(a3), "r"(b0), "r"(b1));
}

__device__ __forceinline__ void ldsm_x4(uint32_t& d0, uint32_t& d1,
                                        uint32_t& d2, uint32_t& d3, uint32_t addr)
{
    asm volatile("ldmatrix.sync.aligned.m8n8.x4.shared.b16 {%0,%1,%2,%3}, [%4];"
                 : "=r"(d0), "=r"(d1), "=r"(d2), "=r"(d3) : "r"(addr));
}

__device__ __forceinline__ void cp16(uint32_t dst, const float* src) {
    asm volatile("cp.async.cg.shared.global [%0], [%1], 16;" :: "r"(dst), "l"(src));
}
#define CP_COMMIT() asm volatile("cp.async.commit_group;" ::: "memory")
#define CP_WAIT(n)  asm volatile("cp.async.wait_group %0;" :: "n"(n) : "memory")

// ---------------------------------------------------------------------------
// prep: d[i] = to_tf32(s[i] * scale), vectorized
// ---------------------------------------------------------------------------
__global__ __launch_bounds__(256)
void prep_kernel(const float* __restrict__ s, float* __restrict__ d, int n4, float scale)
{
    int i = blockIdx.x * blockDim.x + threadIdx.x;
    const int stride = gridDim.x * blockDim.x;
    for (; i < n4; i += stride) {
        float4 v = ((const float4*)s)[i];
        float4 w;
        w.x = to_tf32(v.x * scale); w.y = to_tf32(v.y * scale);
        w.z = to_tf32(v.z * scale); w.w = to_tf32(v.w * scale);
        ((float4*)d)[i] = w;
    }
}

// ---------------------------------------------------------------------------
// tf32 MMA GEMM: C = A @ W^T. A,W pre-rounded tf32. CTA 128x128x16, 256 thr =
// 8 warps (2m x 4n), warp tile 64x32. 3-stage cp.async pipeline, LDSM frags.
// ---------------------------------------------------------------------------
#define GBM 128
#define GBN 128
#define GBK 16
#define GPITCH 20
#define GSTG (GBM * GPITCH)          // 2560 floats
#define NKB (D_MODEL / GBK)          // 64
#define GEMM_SMEM (3 * GSTG * 2 * 4) // 61440 B

__device__ __forceinline__ void gemm_tf32_body(const float* __restrict__ A,
                                               const float* __restrict__ W,
                                               float* __restrict__ O,
                                               const float* __restrict__ bo,
                                               int m0, int n0, int epilogue_mode)
{
    extern __shared__ __align__(16) float gsm[];
    float* As = gsm;                 // [3][GSTG]
    float* Bs = gsm + 3 * GSTG;      // [3][GSTG]

    const int t    = threadIdx.x;    // 0..255
    const int lane = t & 31;
    const int wid  = t >> 5;         // 0..7
    const int wm   = wid & 1;        // 0..1
    const int wn   = wid >> 1;       // 0..3
    const int fr   = lane >> 2;
    const int fc   = lane & 3;
    const int g    = lane >> 3;
    const int li   = lane & 7;
    const int K    = D_MODEL;

    uint32_t as_u[3], bs_u[3];
#pragma unroll
    for (int s = 0; s < 3; s++) {
        as_u[s] = smem_to_u32(As + s * GSTG);
        bs_u[s] = smem_to_u32(Bs + s * GSTG);
    }

    float acc[4][4][4];
#pragma unroll
    for (int i = 0; i < 4; i++)
#pragma unroll
        for (int j = 0; j < 4; j++)
#pragma unroll
            for (int r = 0; r < 4; r++) acc[i][j][r] = 0.f;

    // staging: 512 16B chunks per matrix per tile -> 2 per thread each
    const int srow = t >> 2;         // 0..63  (i>>2 for i=t, + 64 for i=t+256)
    const int sc4  = (t & 3) * 4;

#define GEMM_STAGE(s, kb) do {                                                  \
        const int _k0 = (kb) * GBK;                                             \
        _Pragma("unroll")                                                       \
        for (int _u = 0; _u < 2; _u++) {                                        \
            const int _row = srow + 64 * _u;                                    \
            const uint32_t _so = (uint32_t)((_row * GPITCH + sc4) * 4);         \
            cp16(as_u[s] + _so, A + (size_t)(m0 + _row) * K + _k0 + sc4);       \
            cp16(bs_u[s] + _so, W + (size_t)(n0 + _row) * K + _k0 + sc4);       \
        }                                                                       \
    } while (0)

    GEMM_STAGE(0, 0); CP_COMMIT();
    GEMM_STAGE(1, 1); CP_COMMIT();

    for (int kb = 0; kb < NKB; kb++) {
        const int cur = kb % 3;
        if (kb + 1 < NKB) { CP_WAIT(1); } else { CP_WAIT(0); }
        __syncthreads();

#pragma unroll
        for (int ks = 0; ks < 2; ks++) {
            const int kc0 = ks * 8;
            uint32_t af[4][4];
#pragma unroll
            for (int mt = 0; mt < 4; mt++) {
                const int row = wm * 64 + mt * 16 + (g & 1) * 8 + li;
                const uint32_t addr = as_u[cur] +
                    (uint32_t)((row * GPITCH + kc0 + (g >> 1) * 4) * 4);
                ldsm_x4(af[mt][0], af[mt][1], af[mt][2], af[mt][3], addr);
            }
            uint32_t bf[4][2];
#pragma unroll
            for (int np = 0; np < 2; np++) {
                const int row = wn * 32 + np * 16 + (g >> 1) * 8 + li;
                const uint32_t addr = bs_u[cur] +
                    (uint32_t)((row * GPITCH + kc0 + (g & 1) * 4) * 4);
                ldsm_x4(bf[2 * np][0], bf[2 * np][1],
                        bf[2 * np + 1][0], bf[2 * np + 1][1], addr);
            }
#pragma unroll
            for (int nt = 0; nt < 4; nt++)
#pragma unroll
                for (int mt = 0; mt < 4; mt++)
                    mma_tf32(acc[mt][nt], af[mt][0], af[mt][1], af[mt][2], af[mt][3],
                             bf[nt][0], bf[nt][1]);
        }

        if (kb + 2 < NKB) { GEMM_STAGE((kb + 2) % 3, kb + 2); CP_COMMIT(); }
    }

    // epilogue
#pragma unroll
    for (int mt = 0; mt < 4; mt++) {
        const int r0 = m0 + wm * 64 + mt * 16 + fr;
#pragma unroll
        for (int nt = 0; nt < 4; nt++) {
            const int col = n0 + wn * 32 + nt * 8 + fc * 2;
            if (epilogue_mode == 0) {
                // scatter to [B,H,N,Dh], tf32-rounded (matches old attn staging)
                const int h = col >> 6, d = col & 63;
#pragma unroll
                for (int half = 0; half < 2; half++) {
                    const int m  = r0 + half * 8;
                    const int b  = m >> 11;
                    const int nq = m & (SEQ - 1);
                    float2 o = make_float2(to_tf32(acc[mt][nt][half * 2]),
                                           to_tf32(acc[mt][nt][half * 2 + 1]));
                    *(float2*)&O[(((size_t)b * NUM_HEADS + h) * SEQ + nq) * HEAD_DIM + d] = o;
                }
            } else {
                const float b0 = bo[col], b1 = bo[col + 1];
#pragma unroll
                for (int half = 0; half < 2; half++) {
                    const int m = r0 + half * 8;
                    float2 o = make_float2(acc[mt][nt][half * 2] + b0,
                                           acc[mt][nt][half * 2 + 1] + b1);
                    *(float2*)&O[(size_t)m * D_MODEL + col] = o;
                }
            }
        }
    }
#undef GEMM_STAGE
}

__global__ __launch_bounds__(256)
void proj_kernel()
{
    const int z = blockIdx.z;
    const float* A = (z == 0) ? r_q  : ((z == 1) ? r_k  : r_v);
    const float* W = (z == 0) ? r_wq : ((z == 1) ? r_wk : r_wv);
    float*       O = (z == 0) ? g_q  : ((z == 1) ? g_k  : g_v);
    gemm_tf32_body(A, W, O, nullptr, blockIdx.y * GBM, blockIdx.x * GBN, 0);
}

__global__ __launch_bounds__(256)
void out_kernel(const float* __restrict__ bo, float* __restrict__ Cout)
{
    gemm_tf32_body(g_ctx, r_wo, Cout, bo, blockIdx.y * GBM, blockIdx.x * GBN, 1);
}

// ---------------------------------------------------------------------------
// Flash attention, tf32 mma.sync. Inputs pre-rounded + Q pre-scaled.
// Q/K staged via cp.async (pure copies); V transposed via LDG->STS (no cvt).
// Block = 128 q-rows of one (b,h), 256 threads = 8 warps.
// ---------------------------------------------------------------------------
#define QT 128
#define KT 64
#define NT (SEQ / KT)                   // 32
#define APITCH 68
#define ABUF (KT * APITCH)              // 4352 floats
#define ATTN_SMEM ((QT * APITCH + 4 * ABUF) * 4)   // 104448 B

__global__ __launch_bounds__(256)
void attn_kernel()
{
    extern __shared__ __align__(16) float sm[];
    float* Ps  = sm;                    // [128][APITCH]  Q staging then P
    float* VtB = sm + QT * APITCH + 2 * ABUF;  // 2 x [64][APITCH]  V^T[dv][j]

    const int t    = threadIdx.x;
    const int lane = t & 31;
    const int w    = t >> 5;
    const int fr   = lane >> 2;
    const int fc   = lane & 3;
    const int g    = lane >> 3;
    const int li   = lane & 7;

    const uint32_t ps_u  = smem_to_u32(sm);
    const uint32_t ksb_u = ps_u + QT * APITCH * 4;
    const uint32_t vtb_u = ksb_u + 2 * ABUF * 4;

    const int q0 = blockIdx.x * QT;
    const int bh = blockIdx.y;
    const float* qb = g_q + (size_t)bh * SEQ * HEAD_DIM;
    const float* kb = g_k + (size_t)bh * SEQ * HEAD_DIM;
    const float* vb = g_v + (size_t)bh * SEQ * HEAD_DIM;

    // cp.async staging map: i = t + 256u; row = i>>4, col = (i&15)*4 floats
    const int crow = t >> 4;
    const int ccol = (t & 15) * 4;
    // V transpose map
    const int vj  = t & 63;
    const int vdb = (t >> 6) * 16;

    // ---- prologue: Q (8 chunks) + K0 (4 chunks) via cp.async; V0 via LDG ----
#pragma unroll
    for (int u = 0; u < 8; u++) {
        const int row = crow + 16 * u;
        cp16(ps_u + (uint32_t)((row * APITCH + ccol) * 4),
             qb + (size_t)(q0 + row) * HEAD_DIM + ccol);
    }
#pragma unroll
    for (int u = 0; u < 4; u++) {
        const int row = crow + 16 * u;
        cp16(ksb_u + (uint32_t)((row * APITCH + ccol) * 4),
             kb + (size_t)row * HEAD_DIM + ccol);
    }
    CP_COMMIT();

    float4 vV[4];
#pragma unroll
    for (int u = 0; u < 4; u++)
        vV[u] = *(const float4*)(vb + (size_t)vj * HEAD_DIM + vdb + 4 * u);

    CP_WAIT(0);
    __syncthreads();

    // Q frags to registers
    unsigned qa[8][4];
#pragma unroll
    for (int ks = 0; ks < 8; ks++) {
        const int row = w * 16 + (g & 1) * 8 + li;
        const uint32_t addr = ps_u + (uint32_t)((row * APITCH + ks * 8 + (g >> 1) * 4) * 4);
        ldsm_x4(qa[ks][0], qa[ks][1], qa[ks][2], qa[ks][3], addr);
    }

    // V0 -> Vt buf0 (transposed, no cvt)
    {
        float* Vt = VtB;
#pragma unroll
        for (int u = 0; u < 4; u++) {
            Vt[(vdb + 4 * u + 0) * APITCH + vj] = vV[u].x;
            Vt[(vdb + 4 * u + 1) * APITCH + vj] = vV[u].y;
            Vt[(vdb + 4 * u + 2) * APITCH + vj] = vV[u].z;
            Vt[(vdb + 4 * u + 3) * APITCH + vj] = vV[u].w;
        }
    }
    __syncthreads();

    float o[8][4];
    float m0 = -1e30f, m1 = -1e30f, l0 = 0.f, l1 = 0.f;
#pragma unroll
    for (int nt = 0; nt < 8; nt++)
#pragma unroll
        for (int r = 0; r < 4; r++) o[nt][r] = 0.f;

    for (int kt = 0; kt < NT; kt++) {
        const int cur = kt & 1;
        const bool more = (kt + 1 < NT);
        const uint32_t ks_u = ksb_u + (uint32_t)(cur * ABUF * 4);
        const uint32_t vt_u = vtb_u + (uint32_t)(cur * ABUF * 4);

        if (more) {
            const int j0 = (kt + 1) * KT;
            const uint32_t kdst = ksb_u + (uint32_t)((cur ^ 1) * ABUF * 4);
#pragma unroll
            for (int u = 0; u < 4; u++) {
                const int row = crow + 16 * u;
                cp16(kdst + (uint32_t)((row * APITCH + ccol) * 4),
                     kb + (size_t)(j0 + row) * HEAD_DIM + ccol);
            }
            CP_COMMIT();
#pragma unroll
            for (int u = 0; u < 4; u++)
                vV[u] = *(const float4*)(vb + (size_t)(j0 + vj) * HEAD_DIM + vdb + 4 * u);
        }

        // ---- S = Q @ K^T ----
        float s[8][4];
#pragma unroll
        for (int nt = 0; nt < 8; nt++)
#pragma unroll
            for (int r = 0; r < 4; r++) s[nt][r] = 0.f;

#pragma unroll
        for (int ks = 0; ks < 8; ks++) {
            const int kc0 = ks * 8;
            uint32_t bf[8][2];
#pragma unroll
            for (int np = 0; np < 4; np++) {
                const int row = np * 16 + (g >> 1) * 8 + li;
                const uint32_t addr = ks_u + (uint32_t)((row * APITCH + kc0 + (g & 1) * 4) * 4);
                ldsm_x4(bf[2 * np][0], bf[2 * np][1],
                        bf[2 * np + 1][0], bf[2 * np + 1][1], addr);
            }
#pragma unroll
            for (int nt = 0; nt < 8; nt++)
                mma_tf32(s[nt], qa[ks][0], qa[ks][1], qa[ks][2], qa[ks][3],
                         bf[nt][0], bf[nt][1]);
        }

        // ---- online softmax ----
        float rm0 = -1e30f, rm1 = -1e30f;
#pragma unroll
        for (int nt = 0; nt < 8; nt++) {
            rm0 = fmaxf(rm0, fmaxf(s[nt][0], s[nt][1]));
            rm1 = fmaxf(rm1, fmaxf(s[nt][2], s[nt][3]));
        }
        rm0 = fmaxf(rm0, __shfl_xor_sync(0xffffffffu, rm0, 1));
        rm0 = fmaxf(rm0, __shfl_xor_sync(0xffffffffu, rm0, 2));
        rm1 = fmaxf(rm1, __shfl_xor_sync(0xffffffffu, rm1, 1));
        rm1 = fmaxf(rm1, __shfl_xor_sync(0xffffffffu, rm1, 2));

        const float mn0 = fmaxf(m0, rm0);
        const float mn1 = fmaxf(m1, rm1);
        const float cr0 = __expf(m0 - mn0);
        const float cr1 = __expf(m1 - mn1);
        m0 = mn0; m1 = mn1;

        float rs0 = 0.f, rs1 = 0.f;
        const int wr = w * 16 + fr;
#pragma unroll
        for (int nt = 0; nt < 8; nt++) {
            float p00 = __expf(s[nt][0] - mn0);
            float p01 = __expf(s[nt][1] - mn0);
            float p10 = __expf(s[nt][2] - mn1);
            float p11 = __expf(s[nt][3] - mn1);
            rs0 += p00 + p01;
            rs1 += p10 + p11;
            const int col = nt * 8 + fc * 2;
            *(float2*)&Ps[wr * APITCH + col]       = make_float2(to_tf32(p00), to_tf32(p01));
            *(float2*)&Ps[(wr + 8) * APITCH + col] = make_float2(to_tf32(p10), to_tf32(p11));
        }
        rs0 += __shfl_xor_sync(0xffffffffu, rs0, 1);
        rs0 += __shfl_xor_sync(0xffffffffu, rs0, 2);
        rs1 += __shfl_xor_sync(0xffffffffu, rs1, 1);
        rs1 += __shfl_xor_sync(0xffffffffu, rs1, 2);
        l0 = l0 * cr0 + rs0;
        l1 = l1 * cr1 + rs1;

#pragma unroll
        for (int nt = 0; nt < 8; nt++) {
            o[nt][0] *= cr0; o[nt][1] *= cr0;
            o[nt][2] *= cr1; o[nt][3] *= cr1;
        }
        __syncwarp();

        // ---- O += P @ V ----
#pragma unroll
        for (int ks = 0; ks < 8; ks++) {
            const int kc0 = ks * 8;
            uint32_t a0, a1, a2, a3;
            {
                const int row = w * 16 + (g & 1) * 8 + li;
                const uint32_t addr = ps_u + (uint32_t)((row * APITCH + kc0 + (g >> 1) * 4) * 4);
                ldsm_x4(a0, a1, a2, a3, addr);
            }
            uint32_t bf[8][2];
#pragma unroll
            for (int np = 0; np < 4; np++) {
                const int row = np * 16 + (g >> 1) * 8 + li;
                const uint32_t addr = vt_u + (uint32_t)((row * APITCH + kc0 + (g & 1) * 4) * 4);
                ldsm_x4(bf[2 * np][0], bf[2 * np][1],
                        bf[2 * np + 1][0], bf[2 * np + 1][1], addr);
            }
#pragma unroll
            for (int nt = 0; nt < 8; nt++)
                mma_tf32(o[nt], a0, a1, a2, a3, bf[nt][0], bf[nt][1]);
        }

        // ---- stage next V (transposed), wait next K ----
        if (more) {
            float* Vtn = VtB + (cur ^ 1) * ABUF;
#pragma unroll
            for (int u = 0; u < 4; u++) {
                Vtn[(vdb + 4 * u + 0) * APITCH + vj] = vV[u].x;
                Vtn[(vdb + 4 * u + 1) * APITCH + vj] = vV[u].y;
                Vtn[(vdb + 4 * u + 2) * APITCH + vj] = vV[u].z;
                Vtn[(vdb + 4 * u + 3) * APITCH + vj] = vV[u].w;
            }
            CP_WAIT(0);
        }
        __syncthreads();
    }

    // ---- epilogue: O /= l, tf32-round (matches old out_kernel staging) ----
    const int b = bh >> 4;
    const int h = bh & 15;
    const float inv0 = 1.f / l0;
    const float inv1 = 1.f / l1;
    const int r0 = q0 + w * 16 + fr;
#pragma unroll
    for (int nt = 0; nt < 8; nt++) {
        const int dv = nt * 8 + fc * 2;
        float* base0 = &g_ctx[((size_t)b * SEQ + r0) * D_MODEL + h * HEAD_DIM + dv];
        float* base1 = &g_ctx[((size_t)b * SEQ + r0 + 8) * D_MODEL + h * HEAD_DIM + dv];
        *(float2*)base0 = make_float2(to_tf32(o[nt][0] * inv0), to_tf32(o[nt][1] * inv0));
        *(float2*)base1 = make_float2(to_tf32(o[nt][2] * inv1), to_tf32(o[nt][3] * inv1));
    }
}

// ---------------------------------------------------------------------------
// kernel_launch
// ---------------------------------------------------------------------------
extern "C" void kernel_launch(void* const* d_in, const int* in_sizes, int n_in,
                              void* d_out, int out_size)
{
    const float* query = (const float*)d_in[0];
    const float* key   = (const float*)d_in[1];
    const float* value = (const float*)d_in[2];
    const float* Wq    = (const float*)d_in[3];
    const float* Wk    = (const float*)d_in[4];
    const float* Wv    = (const float*)d_in[5];
    const float* Wo    = (const float*)d_in[6];
    const float* bo    = (const float*)d_in[7];
    float* out = (float*)d_out;

    float *p_rq, *p_rk, *p_rv, *p_wq, *p_wk, *p_wv, *p_wo;
    cudaGetSymbolAddress((void**)&p_rq, r_q);
    cudaGetSymbolAddress((void**)&p_rk, r_k);
    cudaGetSymbolAddress((void**)&p_rv, r_v);
    cudaGetSymbolAddress((void**)&p_wq, r_wq);
    cudaGetSymbolAddress((void**)&p_wk, r_wk);
    cudaGetSymbolAddress((void**)&p_wv, r_wv);
    cudaGetSymbolAddress((void**)&p_wo, r_wo);

    const int n4_in = M_TOT * D_MODEL / 4;     // 1048576
    const int n4_w  = D_MODEL * D_MODEL / 4;   // 262144

    // prep: round inputs and weights to tf32 (scale folded into Wq; exact)
    prep_kernel<<<1024, 256>>>(query, p_rq, n4_in, 1.f);
    prep_kernel<<<1024, 256>>>(key,   p_rk, n4_in, 1.f);
    prep_kernel<<<1024, 256>>>(value, p_rv, n4_in, 1.f);
    prep_kernel<<<512,  256>>>(Wq, p_wq, n4_w, ATT_SCALE);
    prep_kernel<<<512,  256>>>(Wk, p_wk, n4_w, 1.f);
    prep_kernel<<<512,  256>>>(Wv, p_wv, n4_w, 1.f);
    prep_kernel<<<512,  256>>>(Wo, p_wo, n4_w, 1.f);

    cudaFuncSetAttribute(proj_kernel, cudaFuncAttributeMaxDynamicSharedMemorySize, GEMM_SMEM);
    cudaFuncSetAttribute(out_kernel,  cudaFuncAttributeMaxDynamicSharedMemorySize, GEMM_SMEM);
    cudaFuncSetAttribute(attn_kernel, cudaFuncAttributeMaxDynamicSharedMemorySize, ATTN_SMEM);

    proj_kernel<<<dim3(D_MODEL / GBN, M_TOT / GBM, 3), 256, GEMM_SMEM>>>();

    attn_kernel<<<dim3(SEQ / QT, BATCH * NUM_HEADS), 256, ATTN_SMEM>>>();

    out_kernel<<<dim3(D_MODEL / GBN, M_TOT / GBM), 256, GEMM_SMEM>>>(bo, out);
}

// round 9
// speedup vs baseline: 5.0937x; 1.7634x over previous
#include <cuda_runtime.h>
#include <cuda_fp16.h>
#include <cstdint>
#include <math.h>

// Problem constants
#define D_MODEL   1024
#define NUM_HEADS 16
#define HEAD_DIM  64
#define BATCH     2
#define SEQ       2048
#define M_TOT     (BATCH * SEQ)
#define ATT_SCALE 0.125f

// ---------------------------------------------------------------------------
// Scratch (device globals: allocation-free per harness rules)
// ---------------------------------------------------------------------------
__device__ __half g_q[BATCH * NUM_HEADS * SEQ * HEAD_DIM];  // [B,H,N,Dh] fp16 (scale folded)
__device__ __half g_k[BATCH * NUM_HEADS * SEQ * HEAD_DIM];
__device__ __half g_v[BATCH * NUM_HEADS * SEQ * HEAD_DIM];
__device__ __half g_ctx[BATCH * SEQ * D_MODEL];             // [B,N,H*Dh] fp16

__device__ __half r_q[M_TOT * D_MODEL];                     // fp16 inputs
__device__ __half r_k[M_TOT * D_MODEL];
__device__ __half r_v[M_TOT * D_MODEL];
__device__ __half r_wq[D_MODEL * D_MODEL];                  // fp16 0.125*Wq
__device__ __half r_wk[D_MODEL * D_MODEL];
__device__ __half r_wv[D_MODEL * D_MODEL];
__device__ __half r_wo[D_MODEL * D_MODEL];

// ---------------------------------------------------------------------------
// helpers
// ---------------------------------------------------------------------------
__device__ __forceinline__ uint32_t smem_to_u32(const void* p) {
    uint32_t a;
    asm("{ .reg .u64 t; cvta.to.shared.u64 t, %1; cvt.u32.u64 %0, t; }" : "=r"(a) : "l"(p));
    return a;
}

// fp16 mma m16n8k16, fp32 accumulate
__device__ __forceinline__ void mma_f16(float* c,
                                        uint32_t a0, uint32_t a1, uint32_t a2, uint32_t a3,
                                        uint32_t b0, uint32_t b1)
{
    asm volatile(
        "mma.sync.aligned.m16n8k16.row.col.f32.f16.f16.f32 "
        "{%0,%1,%2,%3}, {%4,%5,%6,%7}, {%8,%9}, {%0,%1,%2,%3};\n"
        : "+f"(c[0]), "+f"(c[1]), "+f"(c[2]), "+f"(c[3])
        : "r"(a0), "r"(a1), "r"(a2), "r"(a3), "r"(b0), "r"(b1));
}

__device__ __forceinline__ void ldsm_x4(uint32_t& d0, uint32_t& d1,
                                        uint32_t& d2, uint32_t& d3, uint32_t addr)
{
    asm volatile("ldmatrix.sync.aligned.m8n8.x4.shared.b16 {%0,%1,%2,%3}, [%4];"
                 : "=r"(d0), "=r"(d1), "=r"(d2), "=r"(d3) : "r"(addr));
}

__device__ __forceinline__ void cp16(uint32_t dst, const void* src) {
    asm volatile("cp.async.cg.shared.global [%0], [%1], 16;" :: "r"(dst), "l"(src));
}
#define CP_COMMIT() asm volatile("cp.async.commit_group;" ::: "memory")
#define CP_WAIT(n)  asm volatile("cp.async.wait_group %0;" :: "n"(n) : "memory")

// ---------------------------------------------------------------------------
// prep: d[i] = half(s[i] * scale), vectorized (float4 -> 4 halves)
// ---------------------------------------------------------------------------
__global__ __launch_bounds__(256)
void prep_kernel(const float* __restrict__ s, __half* __restrict__ d, int n4, float scale)
{
    int i = blockIdx.x * blockDim.x + threadIdx.x;
    const int stride = gridDim.x * blockDim.x;
    for (; i < n4; i += stride) {
        float4 v = ((const float4*)s)[i];
        __half2 h01 = __floats2half2_rn(v.x * scale, v.y * scale);
        __half2 h23 = __floats2half2_rn(v.z * scale, v.w * scale);
        uint2 o;
        o.x = *(uint32_t*)&h01;
        o.y = *(uint32_t*)&h23;
        ((uint2*)d)[i] = o;
    }
}

// ---------------------------------------------------------------------------
// fp16 MMA GEMM: C = A @ W^T. A,W fp16 [.,1024]. CTA 128x128x32(halves),
// 256 thr = 8 warps (2m x 4n), warp tile 64x32. 3-stage cp.async, LDSM frags.
// ---------------------------------------------------------------------------
#define GBM 128
#define GBN 128
#define GBK 32                        // halves per k-chunk
#define GPITCH 40                     // halves: 32 + 8 pad (80B rows, conflict-free)
#define GSTG (GBM * GPITCH)           // halves per stage per matrix
#define NKB (D_MODEL / GBK)           // 32
#define GEMM_SMEM (3 * GSTG * 2 * 2)  // bytes = 61440

__device__ __forceinline__ void gemm_f16_body(const __half* __restrict__ A,
                                              const __half* __restrict__ W,
                                              void* __restrict__ Optr,
                                              const float* __restrict__ bo,
                                              int m0, int n0, int mode)
{
    extern __shared__ __align__(16) __half gsm[];
    __half* As = gsm;                 // [3][GSTG]
    __half* Bs = gsm + 3 * GSTG;

    const int t    = threadIdx.x;
    const int lane = t & 31;
    const int wid  = t >> 5;
    const int wm   = wid & 1;
    const int wn   = wid >> 1;        // 0..3
    const int fr   = lane >> 2;
    const int fc   = lane & 3;
    const int g    = lane >> 3;
    const int li   = lane & 7;
    const int K    = D_MODEL;

    uint32_t as_u[3], bs_u[3];
#pragma unroll
    for (int s = 0; s < 3; s++) {
        as_u[s] = smem_to_u32(As + s * GSTG);
        bs_u[s] = smem_to_u32(Bs + s * GSTG);
    }

    float acc[4][4][4];
#pragma unroll
    for (int i = 0; i < 4; i++)
#pragma unroll
        for (int j = 0; j < 4; j++)
#pragma unroll
            for (int r = 0; r < 4; r++) acc[i][j][r] = 0.f;

    // staging: tile = 128 rows x 32 halves = 512 x 16B chunks per matrix.
    // chunk i = t + 256u (u<2): row = i>>2, c8 = (i&3)*8 halves
    const int srow = t >> 2;          // 0..63 (+64)
    const int sc8  = (t & 3) * 8;

#define GEMM_STAGE(s, kb) do {                                                   \
        const int _k0 = (kb) * GBK;                                              \
        _Pragma("unroll")                                                        \
        for (int _u = 0; _u < 2; _u++) {                                         \
            const int _row = srow + 64 * _u;                                     \
            const uint32_t _so = (uint32_t)((_row * GPITCH + sc8) * 2);          \
            cp16(as_u[s] + _so, A + (size_t)(m0 + _row) * K + _k0 + sc8);        \
            cp16(bs_u[s] + _so, W + (size_t)(n0 + _row) * K + _k0 + sc8);        \
        }                                                                        \
    } while (0)

    GEMM_STAGE(0, 0); CP_COMMIT();
    GEMM_STAGE(1, 1); CP_COMMIT();

    for (int kb = 0; kb < NKB; kb++) {
        const int cur = kb % 3;
        if (kb + 1 < NKB) { CP_WAIT(1); } else { CP_WAIT(0); }
        __syncthreads();

#pragma unroll
        for (int ks = 0; ks < 2; ks++) {
            const int kc0 = ks * 16;  // halves
            uint32_t af[4][4];
#pragma unroll
            for (int mt = 0; mt < 4; mt++) {
                const int row = wm * 64 + mt * 16 + (g & 1) * 8 + li;
                const uint32_t addr = as_u[cur] +
                    (uint32_t)((row * GPITCH + kc0 + (g >> 1) * 8) * 2);
                ldsm_x4(af[mt][0], af[mt][1], af[mt][2], af[mt][3], addr);
            }
            uint32_t bf[4][2];
#pragma unroll
            for (int np = 0; np < 2; np++) {
                const int row = wn * 32 + np * 16 + (g >> 1) * 8 + li;
                const uint32_t addr = bs_u[cur] +
                    (uint32_t)((row * GPITCH + kc0 + (g & 1) * 8) * 2);
                ldsm_x4(bf[2 * np][0], bf[2 * np][1],
                        bf[2 * np + 1][0], bf[2 * np + 1][1], addr);
            }
#pragma unroll
            for (int nt = 0; nt < 4; nt++)
#pragma unroll
                for (int mt = 0; mt < 4; mt++)
                    mma_f16(acc[mt][nt], af[mt][0], af[mt][1], af[mt][2], af[mt][3],
                            bf[nt][0], bf[nt][1]);
        }

        if (kb + 2 < NKB) { GEMM_STAGE((kb + 2) % 3, kb + 2); CP_COMMIT(); }
    }

    // epilogue
#pragma unroll
    for (int mt = 0; mt < 4; mt++) {
        const int r0 = m0 + wm * 64 + mt * 16 + fr;
#pragma unroll
        for (int nt = 0; nt < 4; nt++) {
            const int col = n0 + wn * 32 + nt * 8 + fc * 2;
            if (mode == 0) {
                // scatter to [B,H,N,Dh] as fp16
                __half* O = (__half*)Optr;
                const int h = col >> 6, d = col & 63;
#pragma unroll
                for (int half_ = 0; half_ < 2; half_++) {
                    const int m  = r0 + half_ * 8;
                    const int b  = m >> 11;
                    const int nq = m & (SEQ - 1);
                    __half2 o = __floats2half2_rn(acc[mt][nt][half_ * 2],
                                                  acc[mt][nt][half_ * 2 + 1]);
                    *(__half2*)&O[(((size_t)b * NUM_HEADS + h) * SEQ + nq) * HEAD_DIM + d] = o;
                }
            } else {
                float* O = (float*)Optr;
                const float b0 = bo[col], b1 = bo[col + 1];
#pragma unroll
                for (int half_ = 0; half_ < 2; half_++) {
                    const int m = r0 + half_ * 8;
                    float2 o = make_float2(acc[mt][nt][half_ * 2] + b0,
                                           acc[mt][nt][half_ * 2 + 1] + b1);
                    *(float2*)&O[(size_t)m * D_MODEL + col] = o;
                }
            }
        }
    }
#undef GEMM_STAGE
}

__global__ __launch_bounds__(256)
void proj_kernel()
{
    const int z = blockIdx.z;
    const __half* A = (z == 0) ? r_q  : ((z == 1) ? r_k  : r_v);
    const __half* W = (z == 0) ? r_wq : ((z == 1) ? r_wk : r_wv);
    __half*       O = (z == 0) ? g_q  : ((z == 1) ? g_k  : g_v);
    gemm_f16_body(A, W, O, nullptr, blockIdx.y * GBM, blockIdx.x * GBN, 0);
}

__global__ __launch_bounds__(256)
void out_kernel(const float* __restrict__ bo, float* __restrict__ Cout)
{
    gemm_f16_body(g_ctx, r_wo, Cout, bo, blockIdx.y * GBM, blockIdx.x * GBN, 1);
}

// ---------------------------------------------------------------------------
// Flash attention, fp16 mma m16n8k16, fp32 accum/softmax.
// Block = 128 q-rows of one (b,h), 256 threads = 8 warps.
// SMEM: Ps[128][PS] (Q then P), Ks[2][64][PS], Vt[2][64][PS], halves.
// ---------------------------------------------------------------------------
#define QT 128
#define KT 64
#define NT (SEQ / KT)                  // 32
#define PS 72                          // pitch halves: 64 + 8 (144B rows, conflict-free)
#define ABUF (KT * PS)                 // halves
#define ATTN_SMEM ((QT * PS + 4 * ABUF) * 2)   // 55296 B

__global__ __launch_bounds__(256)
void attn_kernel()
{
    extern __shared__ __align__(16) __half asm_[];
    __half* Ps  = asm_;                      // [128][PS]
    __half* VtB = asm_ + QT * PS + 2 * ABUF; // 2 x [64][PS]  V^T[dv][j]

    const int t    = threadIdx.x;
    const int lane = t & 31;
    const int w    = t >> 5;
    const int fr   = lane >> 2;
    const int fc   = lane & 3;
    const int g    = lane >> 3;
    const int li   = lane & 7;

    const uint32_t ps_u  = smem_to_u32(asm_);
    const uint32_t ksb_u = ps_u + QT * PS * 2;
    const uint32_t vtb_u = ksb_u + 2 * ABUF * 2;

    const int q0 = blockIdx.x * QT;
    const int bh = blockIdx.y;
    const __half* qb = g_q + (size_t)bh * SEQ * HEAD_DIM;
    const __half* kb = g_k + (size_t)bh * SEQ * HEAD_DIM;
    const __half* vb = g_v + (size_t)bh * SEQ * HEAD_DIM;

    // cp.async map: chunk i: row = i>>3, c8 = (i&7)*8 halves
    const int crow = t >> 3;          // 0..31 (+32u)
    const int cc8  = (t & 7) * 8;
    // V transpose map
    const int vj  = t & 63;
    const int vdb = (t >> 6) * 16;

    // ---- prologue: Q (4 chunks/thr) + K0 (2 chunks/thr) cp.async; V0 LDG ----
#pragma unroll
    for (int u = 0; u < 4; u++) {
        const int row = crow + 32 * u;
        cp16(ps_u + (uint32_t)((row * PS + cc8) * 2),
             qb + (size_t)(q0 + row) * HEAD_DIM + cc8);
    }
#pragma unroll
    for (int u = 0; u < 2; u++) {
        const int row = crow + 32 * u;
        cp16(ksb_u + (uint32_t)((row * PS + cc8) * 2),
             kb + (size_t)row * HEAD_DIM + cc8);
    }
    CP_COMMIT();

    uint4 vV[2];
    vV[0] = *(const uint4*)(vb + (size_t)vj * HEAD_DIM + vdb);
    vV[1] = *(const uint4*)(vb + (size_t)vj * HEAD_DIM + vdb + 8);

    CP_WAIT(0);
    __syncthreads();

    // Q frags (4 ksteps of 16)
    uint32_t qa[4][4];
#pragma unroll
    for (int ks = 0; ks < 4; ks++) {
        const int row = w * 16 + (g & 1) * 8 + li;
        const uint32_t addr = ps_u + (uint32_t)((row * PS + ks * 16 + (g >> 1) * 8) * 2);
        ldsm_x4(qa[ks][0], qa[ks][1], qa[ks][2], qa[ks][3], addr);
    }

    // V0 -> Vt buf0 (transposed scalar half stores)
    {
        __half* Vt = VtB;
        const __half* vh = (const __half*)vV;
#pragma unroll
        for (int i = 0; i < 16; i++)
            Vt[(vdb + i) * PS + vj] = vh[i];
    }
    __syncthreads();

    float o[8][4];
    float m0 = -1e30f, m1 = -1e30f, l0 = 0.f, l1 = 0.f;
#pragma unroll
    for (int nt = 0; nt < 8; nt++)
#pragma unroll
        for (int r = 0; r < 4; r++) o[nt][r] = 0.f;

    for (int kt = 0; kt < NT; kt++) {
        const int cur = kt & 1;
        const bool more = (kt + 1 < NT);
        const uint32_t ks_u = ksb_u + (uint32_t)(cur * ABUF * 2);
        const uint32_t vt_u = vtb_u + (uint32_t)(cur * ABUF * 2);

        if (more) {
            const int j0 = (kt + 1) * KT;
            const uint32_t kdst = ksb_u + (uint32_t)((cur ^ 1) * ABUF * 2);
#pragma unroll
            for (int u = 0; u < 2; u++) {
                const int row = crow + 32 * u;
                cp16(kdst + (uint32_t)((row * PS + cc8) * 2),
                     kb + (size_t)(j0 + row) * HEAD_DIM + cc8);
            }
            CP_COMMIT();
            vV[0] = *(const uint4*)(vb + (size_t)(j0 + vj) * HEAD_DIM + vdb);
            vV[1] = *(const uint4*)(vb + (size_t)(j0 + vj) * HEAD_DIM + vdb + 8);
        }

        // ---- S = Q @ K^T (warp tile 16 x 64) ----
        float s[8][4];
#pragma unroll
        for (int nt = 0; nt < 8; nt++)
#pragma unroll
            for (int r = 0; r < 4; r++) s[nt][r] = 0.f;

#pragma unroll
        for (int ks = 0; ks < 4; ks++) {
            const int kc0 = ks * 16;
            uint32_t bf[8][2];
#pragma unroll
            for (int np = 0; np < 4; np++) {
                const int row = np * 16 + (g >> 1) * 8 + li;
                const uint32_t addr = ks_u + (uint32_t)((row * PS + kc0 + (g & 1) * 8) * 2);
                ldsm_x4(bf[2 * np][0], bf[2 * np][1],
                        bf[2 * np + 1][0], bf[2 * np + 1][1], addr);
            }
#pragma unroll
            for (int nt = 0; nt < 8; nt++)
                mma_f16(s[nt], qa[ks][0], qa[ks][1], qa[ks][2], qa[ks][3],
                        bf[nt][0], bf[nt][1]);
        }

        // ---- online softmax ----
        float rm0 = -1e30f, rm1 = -1e30f;
#pragma unroll
        for (int nt = 0; nt < 8; nt++) {
            rm0 = fmaxf(rm0, fmaxf(s[nt][0], s[nt][1]));
            rm1 = fmaxf(rm1, fmaxf(s[nt][2], s[nt][3]));
        }
        rm0 = fmaxf(rm0, __shfl_xor_sync(0xffffffffu, rm0, 1));
        rm0 = fmaxf(rm0, __shfl_xor_sync(0xffffffffu, rm0, 2));
        rm1 = fmaxf(rm1, __shfl_xor_sync(0xffffffffu, rm1, 1));
        rm1 = fmaxf(rm1, __shfl_xor_sync(0xffffffffu, rm1, 2));

        const float mn0 = fmaxf(m0, rm0);
        const float mn1 = fmaxf(m1, rm1);
        const float cr0 = __expf(m0 - mn0);
        const float cr1 = __expf(m1 - mn1);
        m0 = mn0; m1 = mn1;

        float rs0 = 0.f, rs1 = 0.f;
        const int wr = w * 16 + fr;
#pragma unroll
        for (int nt = 0; nt < 8; nt++) {
            float p00 = __expf(s[nt][0] - mn0);
            float p01 = __expf(s[nt][1] - mn0);
            float p10 = __expf(s[nt][2] - mn1);
            float p11 = __expf(s[nt][3] - mn1);
            rs0 += p00 + p01;
            rs1 += p10 + p11;
            const int col = nt * 8 + fc * 2;
            *(__half2*)&Ps[wr * PS + col]       = __floats2half2_rn(p00, p01);
            *(__half2*)&Ps[(wr + 8) * PS + col] = __floats2half2_rn(p10, p11);
        }
        rs0 += __shfl_xor_sync(0xffffffffu, rs0, 1);
        rs0 += __shfl_xor_sync(0xffffffffu, rs0, 2);
        rs1 += __shfl_xor_sync(0xffffffffu, rs1, 1);
        rs1 += __shfl_xor_sync(0xffffffffu, rs1, 2);
        l0 = l0 * cr0 + rs0;
        l1 = l1 * cr1 + rs1;

#pragma unroll
        for (int nt = 0; nt < 8; nt++) {
            o[nt][0] *= cr0; o[nt][1] *= cr0;
            o[nt][2] *= cr1; o[nt][3] *= cr1;
        }
        __syncwarp();      // this warp's P rows visible to itself

        // ---- O += P @ V (k = j, 4 ksteps of 16) ----
#pragma unroll
        for (int ks = 0; ks < 4; ks++) {
            const int kc0 = ks * 16;
            uint32_t a0, a1, a2, a3;
            {
                const int row = w * 16 + (g & 1) * 8 + li;
                const uint32_t addr = ps_u + (uint32_t)((row * PS + kc0 + (g >> 1) * 8) * 2);
                ldsm_x4(a0, a1, a2, a3, addr);
            }
            uint32_t bf[8][2];
#pragma unroll
            for (int np = 0; np < 4; np++) {
                const int row = np * 16 + (g >> 1) * 8 + li;
                const uint32_t addr = vt_u + (uint32_t)((row * PS + kc0 + (g & 1) * 8) * 2);
                ldsm_x4(bf[2 * np][0], bf[2 * np][1],
                        bf[2 * np + 1][0], bf[2 * np + 1][1], addr);
            }
#pragma unroll
            for (int nt = 0; nt < 8; nt++)
                mma_f16(o[nt], a0, a1, a2, a3, bf[nt][0], bf[nt][1]);
        }

        // ---- stage next V (transposed); wait next K ----
        if (more) {
            __half* Vtn = VtB + (cur ^ 1) * ABUF;
            const __half* vh = (const __half*)vV;
#pragma unroll
            for (int i = 0; i < 16; i++)
                Vtn[(vdb + i) * PS + vj] = vh[i];
            CP_WAIT(0);
        }
        __syncthreads();
    }

    // ---- epilogue: O /= l, write g_ctx fp16 ----
    const int b = bh >> 4;
    const int h = bh & 15;
    const float inv0 = 1.f / l0;
    const float inv1 = 1.f / l1;
    const int r0 = q0 + w * 16 + fr;
#pragma unroll
    for (int nt = 0; nt < 8; nt++) {
        const int dv = nt * 8 + fc * 2;
        __half* base0 = &g_ctx[((size_t)b * SEQ + r0) * D_MODEL + h * HEAD_DIM + dv];
        __half* base1 = &g_ctx[((size_t)b * SEQ + r0 + 8) * D_MODEL + h * HEAD_DIM + dv];
        *(__half2*)base0 = __floats2half2_rn(o[nt][0] * inv0, o[nt][1] * inv0);
        *(__half2*)base1 = __floats2half2_rn(o[nt][2] * inv1, o[nt][3] * inv1);
    }
}

// ---------------------------------------------------------------------------
// kernel_launch
// ---------------------------------------------------------------------------
extern "C" void kernel_launch(void* const* d_in, const int* in_sizes, int n_in,
                              void* d_out, int out_size)
{
    const float* query = (const float*)d_in[0];
    const float* key   = (const float*)d_in[1];
    const float* value = (const float*)d_in[2];
    const float* Wq    = (const float*)d_in[3];
    const float* Wk    = (const float*)d_in[4];
    const float* Wv    = (const float*)d_in[5];
    const float* Wo    = (const float*)d_in[6];
    const float* bo    = (const float*)d_in[7];
    float* out = (float*)d_out;

    __half *p_rq, *p_rk, *p_rv, *p_wq, *p_wk, *p_wv, *p_wo;
    cudaGetSymbolAddress((void**)&p_rq, r_q);
    cudaGetSymbolAddress((void**)&p_rk, r_k);
    cudaGetSymbolAddress((void**)&p_rv, r_v);
    cudaGetSymbolAddress((void**)&p_wq, r_wq);
    cudaGetSymbolAddress((void**)&p_wk, r_wk);
    cudaGetSymbolAddress((void**)&p_wv, r_wv);
    cudaGetSymbolAddress((void**)&p_wo, r_wo);

    const int n4_in = M_TOT * D_MODEL / 4;
    const int n4_w  = D_MODEL * D_MODEL / 4;

    prep_kernel<<<1024, 256>>>(query, p_rq, n4_in, 1.f);
    prep_kernel<<<1024, 256>>>(key,   p_rk, n4_in, 1.f);
    prep_kernel<<<1024, 256>>>(value, p_rv, n4_in, 1.f);
    prep_kernel<<<512,  256>>>(Wq, p_wq, n4_w, ATT_SCALE);
    prep_kernel<<<512,  256>>>(Wk, p_wk, n4_w, 1.f);
    prep_kernel<<<512,  256>>>(Wv, p_wv, n4_w, 1.f);
    prep_kernel<<<512,  256>>>(Wo, p_wo, n4_w, 1.f);

    cudaFuncSetAttribute(proj_kernel, cudaFuncAttributeMaxDynamicSharedMemorySize, GEMM_SMEM);
    cudaFuncSetAttribute(out_kernel,  cudaFuncAttributeMaxDynamicSharedMemorySize, GEMM_SMEM);
    cudaFuncSetAttribute(attn_kernel, cudaFuncAttributeMaxDynamicSharedMemorySize, ATTN_SMEM);

    proj_kernel<<<dim3(D_MODEL / GBN, M_TOT / GBM, 3), 256, GEMM_SMEM>>>();

    attn_kernel<<<dim3(SEQ / QT, BATCH * NUM_HEADS), 256, ATTN_SMEM>>>();

    out_kernel<<<dim3(D_MODEL / GBN, M_TOT / GBM), 256, GEMM_SMEM>>>(bo, out);
}

// round 10
// speedup vs baseline: 5.8803x; 1.1544x over previous
#include <cuda_runtime.h>
#include <cuda_fp16.h>
#include <cstdint>
#include <math.h>

// Problem constants
#define D_MODEL   1024
#define NUM_HEADS 16
#define HEAD_DIM  64
#define BATCH     2
#define SEQ       2048
#define M_TOT     (BATCH * SEQ)
#define ATT_SCALE 0.125f

// ---------------------------------------------------------------------------
// Scratch (device globals: allocation-free per harness rules)
// ---------------------------------------------------------------------------
__device__ __half g_q[BATCH * NUM_HEADS * SEQ * HEAD_DIM];  // [B,H,N,Dh] fp16 (scale folded)
__device__ __half g_k[BATCH * NUM_HEADS * SEQ * HEAD_DIM];
__device__ __half g_v[BATCH * NUM_HEADS * SEQ * HEAD_DIM];
__device__ __half g_ctx[BATCH * SEQ * D_MODEL];             // [B,N,H*Dh] fp16

__device__ __half r_q[M_TOT * D_MODEL];                     // fp16 inputs
__device__ __half r_k[M_TOT * D_MODEL];
__device__ __half r_v[M_TOT * D_MODEL];
__device__ __half r_wq[D_MODEL * D_MODEL];                  // fp16 0.125*Wq
__device__ __half r_wk[D_MODEL * D_MODEL];
__device__ __half r_wv[D_MODEL * D_MODEL];
__device__ __half r_wo[D_MODEL * D_MODEL];

// ---------------------------------------------------------------------------
// helpers
// ---------------------------------------------------------------------------
__device__ __forceinline__ uint32_t smem_to_u32(const void* p) {
    uint32_t a;
    asm("{ .reg .u64 t; cvta.to.shared.u64 t, %1; cvt.u32.u64 %0, t; }" : "=r"(a) : "l"(p));
    return a;
}

// fp16 mma m16n8k16, fp32 accumulate
__device__ __forceinline__ void mma_f16(float* c,
                                        uint32_t a0, uint32_t a1, uint32_t a2, uint32_t a3,
                                        uint32_t b0, uint32_t b1)
{
    asm volatile(
        "mma.sync.aligned.m16n8k16.row.col.f32.f16.f16.f32 "
        "{%0,%1,%2,%3}, {%4,%5,%6,%7}, {%8,%9}, {%0,%1,%2,%3};\n"
        : "+f"(c[0]), "+f"(c[1]), "+f"(c[2]), "+f"(c[3])
        : "r"(a0), "r"(a1), "r"(a2), "r"(a3), "r"(b0), "r"(b1));
}

__device__ __forceinline__ void ldsm_x4(uint32_t& d0, uint32_t& d1,
                                        uint32_t& d2, uint32_t& d3, uint32_t addr)
{
    asm volatile("ldmatrix.sync.aligned.m8n8.x4.shared.b16 {%0,%1,%2,%3}, [%4];"
                 : "=r"(d0), "=r"(d1), "=r"(d2), "=r"(d3) : "r"(addr));
}

__device__ __forceinline__ void cp16(uint32_t dst, const void* src) {
    asm volatile("cp.async.cg.shared.global [%0], [%1], 16;" :: "r"(dst), "l"(src));
}
#define CP_COMMIT() asm volatile("cp.async.commit_group;" ::: "memory")
#define CP_WAIT(n)  asm volatile("cp.async.wait_group %0;" :: "n"(n) : "memory")

__device__ __forceinline__ uint32_t pack_h2(float a, float b) {
    __half2 h = __floats2half2_rn(a, b);
    return *(uint32_t*)&h;
}

// ---------------------------------------------------------------------------
// prep (single launch): segment y converts src[y] -> dst[y] (fp16, scaled)
// ---------------------------------------------------------------------------
struct PrepArgs {
    const float* src[7];
    __half*      dst[7];
    int          n4[7];
    float        scale[7];
};

__global__ __launch_bounds__(256)
void prep_all_kernel(PrepArgs a)
{
    const int seg = blockIdx.y;
    const float* __restrict__ s = a.src[seg];
    __half* __restrict__ d = a.dst[seg];
    const int n4 = a.n4[seg];
    const float sc = a.scale[seg];

    const int stride = gridDim.x * blockDim.x;
    for (int i = blockIdx.x * blockDim.x + threadIdx.x; i < n4; i += stride) {
        float4 v = ((const float4*)s)[i];
        uint2 o;
        o.x = pack_h2(v.x * sc, v.y * sc);
        o.y = pack_h2(v.z * sc, v.w * sc);
        ((uint2*)d)[i] = o;
    }
}

// ---------------------------------------------------------------------------
// fp16 MMA GEMM: C = A @ W^T. A,W fp16 [.,1024]. CTA 128x128x32(halves),
// 256 thr = 8 warps (2m x 4n), warp tile 64x32. 3-stage cp.async, LDSM frags.
// ---------------------------------------------------------------------------
#define GBM 128
#define GBN 128
#define GBK 32
#define GPITCH 40
#define GSTG (GBM * GPITCH)
#define NKB (D_MODEL / GBK)
#define GEMM_SMEM (3 * GSTG * 2 * 2)

__device__ __forceinline__ void gemm_f16_body(const __half* __restrict__ A,
                                              const __half* __restrict__ W,
                                              void* __restrict__ Optr,
                                              const float* __restrict__ bo,
                                              int m0, int n0, int mode)
{
    extern __shared__ __align__(16) __half gsm[];
    __half* As = gsm;
    __half* Bs = gsm + 3 * GSTG;

    const int t    = threadIdx.x;
    const int lane = t & 31;
    const int wid  = t >> 5;
    const int wm   = wid & 1;
    const int wn   = wid >> 1;
    const int fr   = lane >> 2;
    const int fc   = lane & 3;
    const int g    = lane >> 3;
    const int li   = lane & 7;
    const int K    = D_MODEL;

    uint32_t as_u[3], bs_u[3];
#pragma unroll
    for (int s = 0; s < 3; s++) {
        as_u[s] = smem_to_u32(As + s * GSTG);
        bs_u[s] = smem_to_u32(Bs + s * GSTG);
    }

    float acc[4][4][4];
#pragma unroll
    for (int i = 0; i < 4; i++)
#pragma unroll
        for (int j = 0; j < 4; j++)
#pragma unroll
            for (int r = 0; r < 4; r++) acc[i][j][r] = 0.f;

    const int srow = t >> 2;
    const int sc8  = (t & 3) * 8;

#define GEMM_STAGE(s, kb) do {                                                   \
        const int _k0 = (kb) * GBK;                                              \
        _Pragma("unroll")                                                        \
        for (int _u = 0; _u < 2; _u++) {                                         \
            const int _row = srow + 64 * _u;                                     \
            const uint32_t _so = (uint32_t)((_row * GPITCH + sc8) * 2);          \
            cp16(as_u[s] + _so, A + (size_t)(m0 + _row) * K + _k0 + sc8);        \
            cp16(bs_u[s] + _so, W + (size_t)(n0 + _row) * K + _k0 + sc8);        \
        }                                                                        \
    } while (0)

    GEMM_STAGE(0, 0); CP_COMMIT();
    GEMM_STAGE(1, 1); CP_COMMIT();

    for (int kb = 0; kb < NKB; kb++) {
        const int cur = kb % 3;
        if (kb + 1 < NKB) { CP_WAIT(1); } else { CP_WAIT(0); }
        __syncthreads();

#pragma unroll
        for (int ks = 0; ks < 2; ks++) {
            const int kc0 = ks * 16;
            uint32_t af[4][4];
#pragma unroll
            for (int mt = 0; mt < 4; mt++) {
                const int row = wm * 64 + mt * 16 + (g & 1) * 8 + li;
                const uint32_t addr = as_u[cur] +
                    (uint32_t)((row * GPITCH + kc0 + (g >> 1) * 8) * 2);
                ldsm_x4(af[mt][0], af[mt][1], af[mt][2], af[mt][3], addr);
            }
            uint32_t bf[4][2];
#pragma unroll
            for (int np = 0; np < 2; np++) {
                const int row = wn * 32 + np * 16 + (g >> 1) * 8 + li;
                const uint32_t addr = bs_u[cur] +
                    (uint32_t)((row * GPITCH + kc0 + (g & 1) * 8) * 2);
                ldsm_x4(bf[2 * np][0], bf[2 * np][1],
                        bf[2 * np + 1][0], bf[2 * np + 1][1], addr);
            }
#pragma unroll
            for (int nt = 0; nt < 4; nt++)
#pragma unroll
                for (int mt = 0; mt < 4; mt++)
                    mma_f16(acc[mt][nt], af[mt][0], af[mt][1], af[mt][2], af[mt][3],
                            bf[nt][0], bf[nt][1]);
        }

        if (kb + 2 < NKB) { GEMM_STAGE((kb + 2) % 3, kb + 2); CP_COMMIT(); }
    }

    // epilogue
#pragma unroll
    for (int mt = 0; mt < 4; mt++) {
        const int r0 = m0 + wm * 64 + mt * 16 + fr;
#pragma unroll
        for (int nt = 0; nt < 4; nt++) {
            const int col = n0 + wn * 32 + nt * 8 + fc * 2;
            if (mode == 0) {
                __half* O = (__half*)Optr;
                const int h = col >> 6, d = col & 63;
#pragma unroll
                for (int half_ = 0; half_ < 2; half_++) {
                    const int m  = r0 + half_ * 8;
                    const int b  = m >> 11;
                    const int nq = m & (SEQ - 1);
                    __half2 o = __floats2half2_rn(acc[mt][nt][half_ * 2],
                                                  acc[mt][nt][half_ * 2 + 1]);
                    *(__half2*)&O[(((size_t)b * NUM_HEADS + h) * SEQ + nq) * HEAD_DIM + d] = o;
                }
            } else {
                float* O = (float*)Optr;
                const float b0 = bo[col], b1 = bo[col + 1];
#pragma unroll
                for (int half_ = 0; half_ < 2; half_++) {
                    const int m = r0 + half_ * 8;
                    float2 o = make_float2(acc[mt][nt][half_ * 2] + b0,
                                           acc[mt][nt][half_ * 2 + 1] + b1);
                    *(float2*)&O[(size_t)m * D_MODEL + col] = o;
                }
            }
        }
    }
#undef GEMM_STAGE
}

__global__ __launch_bounds__(256)
void proj_kernel()
{
    const int z = blockIdx.z;
    const __half* A = (z == 0) ? r_q  : ((z == 1) ? r_k  : r_v);
    const __half* W = (z == 0) ? r_wq : ((z == 1) ? r_wk : r_wv);
    __half*       O = (z == 0) ? g_q  : ((z == 1) ? g_k  : g_v);
    gemm_f16_body(A, W, O, nullptr, blockIdx.y * GBM, blockIdx.x * GBN, 0);
}

__global__ __launch_bounds__(256)
void out_kernel(const float* __restrict__ bo, float* __restrict__ Cout)
{
    gemm_f16_body(g_ctx, r_wo, Cout, bo, blockIdx.y * GBM, blockIdx.x * GBN, 1);
}

// ---------------------------------------------------------------------------
// Flash attention, fp16 mma m16n8k16, fp32 accum/softmax.
// P kept in registers (C-frag of QK^T == A-frag of PV, FA2 layout identity).
// Block = 128 q-rows of one (b,h), 256 threads = 8 warps.
// SMEM: Qs[128][PS] (Q staging only), Ks[2][64][PS], Vt[2][64][PS], halves.
// ---------------------------------------------------------------------------
#define QT 128
#define KT 64
#define NT (SEQ / KT)
#define PS 72
#define ABUF (KT * PS)
#define ATTN_SMEM ((QT * PS + 4 * ABUF) * 2)   // 55296 B

__global__ __launch_bounds__(256)
void attn_kernel()
{
    extern __shared__ __align__(16) __half asm_[];
    __half* VtB = asm_ + QT * PS + 2 * ABUF;   // 2 x [64][PS]  V^T[dv][j]

    const int t    = threadIdx.x;
    const int lane = t & 31;
    const int w    = t >> 5;
    const int g    = lane >> 3;
    const int li   = lane & 7;

    const uint32_t qs_u  = smem_to_u32(asm_);
    const uint32_t ksb_u = qs_u + QT * PS * 2;
    const uint32_t vtb_u = ksb_u + 2 * ABUF * 2;

    const int q0 = blockIdx.x * QT;
    const int bh = blockIdx.y;
    const __half* qb = g_q + (size_t)bh * SEQ * HEAD_DIM;
    const __half* kb = g_k + (size_t)bh * SEQ * HEAD_DIM;
    const __half* vb = g_v + (size_t)bh * SEQ * HEAD_DIM;

    const int crow = t >> 3;          // 0..31 (+32u)
    const int cc8  = (t & 7) * 8;
    const int vj  = t & 63;
    const int vdb = (t >> 6) * 16;

    // ---- prologue: Q + K0 via cp.async; V0 LDG ----
#pragma unroll
    for (int u = 0; u < 4; u++) {
        const int row = crow + 32 * u;
        cp16(qs_u + (uint32_t)((row * PS + cc8) * 2),
             qb + (size_t)(q0 + row) * HEAD_DIM + cc8);
    }
#pragma unroll
    for (int u = 0; u < 2; u++) {
        const int row = crow + 32 * u;
        cp16(ksb_u + (uint32_t)((row * PS + cc8) * 2),
             kb + (size_t)row * HEAD_DIM + cc8);
    }
    CP_COMMIT();

    uint4 vV[2];
    vV[0] = *(const uint4*)(vb + (size_t)vj * HEAD_DIM + vdb);
    vV[1] = *(const uint4*)(vb + (size_t)vj * HEAD_DIM + vdb + 8);

    CP_WAIT(0);
    __syncthreads();

    uint32_t qa[4][4];
#pragma unroll
    for (int ks = 0; ks < 4; ks++) {
        const int row = w * 16 + (g & 1) * 8 + li;
        const uint32_t addr = qs_u + (uint32_t)((row * PS + ks * 16 + (g >> 1) * 8) * 2);
        ldsm_x4(qa[ks][0], qa[ks][1], qa[ks][2], qa[ks][3], addr);
    }

    // V0 -> Vt buf0 (transposed)
    {
        __half* Vt = (__half*)asm_ + QT * PS + 2 * ABUF;
        const __half* vh = (const __half*)vV;
#pragma unroll
        for (int i = 0; i < 16; i++)
            Vt[(vdb + i) * PS + vj] = vh[i];
    }
    __syncthreads();

    float o[8][4];
    float m0 = -1e30f, m1 = -1e30f, l0 = 0.f, l1 = 0.f;
#pragma unroll
    for (int nt = 0; nt < 8; nt++)
#pragma unroll
        for (int r = 0; r < 4; r++) o[nt][r] = 0.f;

    for (int kt = 0; kt < NT; kt++) {
        const int cur = kt & 1;
        const bool more = (kt + 1 < NT);
        const uint32_t ks_u = ksb_u + (uint32_t)(cur * ABUF * 2);
        const uint32_t vt_u = vtb_u + (uint32_t)(cur * ABUF * 2);

        if (more) {
            const int j0 = (kt + 1) * KT;
            const uint32_t kdst = ksb_u + (uint32_t)((cur ^ 1) * ABUF * 2);
#pragma unroll
            for (int u = 0; u < 2; u++) {
                const int row = crow + 32 * u;
                cp16(kdst + (uint32_t)((row * PS + cc8) * 2),
                     kb + (size_t)(j0 + row) * HEAD_DIM + cc8);
            }
            CP_COMMIT();
            vV[0] = *(const uint4*)(vb + (size_t)(j0 + vj) * HEAD_DIM + vdb);
            vV[1] = *(const uint4*)(vb + (size_t)(j0 + vj) * HEAD_DIM + vdb + 8);
        }

        // ---- S = Q @ K^T (warp tile 16 x 64) ----
        float s[8][4];
#pragma unroll
        for (int nt = 0; nt < 8; nt++)
#pragma unroll
            for (int r = 0; r < 4; r++) s[nt][r] = 0.f;

#pragma unroll
        for (int ks = 0; ks < 4; ks++) {
            const int kc0 = ks * 16;
            uint32_t bf[8][2];
#pragma unroll
            for (int np = 0; np < 4; np++) {
                const int row = np * 16 + (g >> 1) * 8 + li;
                const uint32_t addr = ks_u + (uint32_t)((row * PS + kc0 + (g & 1) * 8) * 2);
                ldsm_x4(bf[2 * np][0], bf[2 * np][1],
                        bf[2 * np + 1][0], bf[2 * np + 1][1], addr);
            }
#pragma unroll
            for (int nt = 0; nt < 8; nt++)
                mma_f16(s[nt], qa[ks][0], qa[ks][1], qa[ks][2], qa[ks][3],
                        bf[nt][0], bf[nt][1]);
        }

        // ---- online softmax (in registers) ----
        float rm0 = -1e30f, rm1 = -1e30f;
#pragma unroll
        for (int nt = 0; nt < 8; nt++) {
            rm0 = fmaxf(rm0, fmaxf(s[nt][0], s[nt][1]));
            rm1 = fmaxf(rm1, fmaxf(s[nt][2], s[nt][3]));
        }
        rm0 = fmaxf(rm0, __shfl_xor_sync(0xffffffffu, rm0, 1));
        rm0 = fmaxf(rm0, __shfl_xor_sync(0xffffffffu, rm0, 2));
        rm1 = fmaxf(rm1, __shfl_xor_sync(0xffffffffu, rm1, 1));
        rm1 = fmaxf(rm1, __shfl_xor_sync(0xffffffffu, rm1, 2));

        const float mn0 = fmaxf(m0, rm0);
        const float mn1 = fmaxf(m1, rm1);
        const float cr0 = __expf(m0 - mn0);
        const float cr1 = __expf(m1 - mn1);
        m0 = mn0; m1 = mn1;

        float rs0 = 0.f, rs1 = 0.f;
#pragma unroll
        for (int nt = 0; nt < 8; nt++) {
            s[nt][0] = __expf(s[nt][0] - mn0);
            s[nt][1] = __expf(s[nt][1] - mn0);
            s[nt][2] = __expf(s[nt][2] - mn1);
            s[nt][3] = __expf(s[nt][3] - mn1);
            rs0 += s[nt][0] + s[nt][1];
            rs1 += s[nt][2] + s[nt][3];
        }
        rs0 += __shfl_xor_sync(0xffffffffu, rs0, 1);
        rs0 += __shfl_xor_sync(0xffffffffu, rs0, 2);
        rs1 += __shfl_xor_sync(0xffffffffu, rs1, 1);
        rs1 += __shfl_xor_sync(0xffffffffu, rs1, 2);
        l0 = l0 * cr0 + rs0;
        l1 = l1 * cr1 + rs1;

        // pack P into A-fragments (C-layout of S == A-layout of PV)
        uint32_t pa[4][4];
#pragma unroll
        for (int ks = 0; ks < 4; ks++) {
            pa[ks][0] = pack_h2(s[2 * ks][0],     s[2 * ks][1]);      // (fr,   k=2fc)
            pa[ks][1] = pack_h2(s[2 * ks][2],     s[2 * ks][3]);      // (fr+8, k=2fc)
            pa[ks][2] = pack_h2(s[2 * ks + 1][0], s[2 * ks + 1][1]);  // (fr,   k=2fc+8)
            pa[ks][3] = pack_h2(s[2 * ks + 1][2], s[2 * ks + 1][3]);  // (fr+8, k=2fc+8)
        }

#pragma unroll
        for (int nt = 0; nt < 8; nt++) {
            o[nt][0] *= cr0; o[nt][1] *= cr0;
            o[nt][2] *= cr1; o[nt][3] *= cr1;
        }

        // ---- O += P @ V (register A) ----
#pragma unroll
        for (int ks = 0; ks < 4; ks++) {
            const int kc0 = ks * 16;
            uint32_t bf[8][2];
#pragma unroll
            for (int np = 0; np < 4; np++) {
                const int row = np * 16 + (g >> 1) * 8 + li;
                const uint32_t addr = vt_u + (uint32_t)((row * PS + kc0 + (g & 1) * 8) * 2);
                ldsm_x4(bf[2 * np][0], bf[2 * np][1],
                        bf[2 * np + 1][0], bf[2 * np + 1][1], addr);
            }
#pragma unroll
            for (int nt = 0; nt < 8; nt++)
                mma_f16(o[nt], pa[ks][0], pa[ks][1], pa[ks][2], pa[ks][3],
                        bf[nt][0], bf[nt][1]);
        }

        // ---- stage next V (transposed); wait next K ----
        if (more) {
            __half* Vtn = (__half*)asm_ + QT * PS + 2 * ABUF + (cur ^ 1) * ABUF;
            const __half* vh = (const __half*)vV;
#pragma unroll
            for (int i = 0; i < 16; i++)
                Vtn[(vdb + i) * PS + vj] = vh[i];
            CP_WAIT(0);
        }
        __syncthreads();
    }

    // ---- epilogue: O /= l, write g_ctx fp16 ----
    const int fr = lane >> 2;
    const int fc = lane & 3;
    const int b = bh >> 4;
    const int h = bh & 15;
    const float inv0 = 1.f / l0;
    const float inv1 = 1.f / l1;
    const int r0 = q0 + w * 16 + fr;
#pragma unroll
    for (int nt = 0; nt < 8; nt++) {
        const int dv = nt * 8 + fc * 2;
        __half* base0 = &g_ctx[((size_t)b * SEQ + r0) * D_MODEL + h * HEAD_DIM + dv];
        __half* base1 = &g_ctx[((size_t)b * SEQ + r0 + 8) * D_MODEL + h * HEAD_DIM + dv];
        *(__half2*)base0 = __floats2half2_rn(o[nt][0] * inv0, o[nt][1] * inv0);
        *(__half2*)base1 = __floats2half2_rn(o[nt][2] * inv1, o[nt][3] * inv1);
    }
}

// ---------------------------------------------------------------------------
// kernel_launch
// ---------------------------------------------------------------------------
extern "C" void kernel_launch(void* const* d_in, const int* in_sizes, int n_in,
                              void* d_out, int out_size)
{
    const float* query = (const float*)d_in[0];
    const float* key   = (const float*)d_in[1];
    const float* value = (const float*)d_in[2];
    const float* Wq    = (const float*)d_in[3];
    const float* Wk    = (const float*)d_in[4];
    const float* Wv    = (const float*)d_in[5];
    const float* Wo    = (const float*)d_in[6];
    const float* bo    = (const float*)d_in[7];
    float* out = (float*)d_out;

    __half *p_rq, *p_rk, *p_rv, *p_wq, *p_wk, *p_wv, *p_wo;
    cudaGetSymbolAddress((void**)&p_rq, r_q);
    cudaGetSymbolAddress((void**)&p_rk, r_k);
    cudaGetSymbolAddress((void**)&p_rv, r_v);
    cudaGetSymbolAddress((void**)&p_wq, r_wq);
    cudaGetSymbolAddress((void**)&p_wk, r_wk);
    cudaGetSymbolAddress((void**)&p_wv, r_wv);
    cudaGetSymbolAddress((void**)&p_wo, r_wo);

    const int n4_in = M_TOT * D_MODEL / 4;
    const int n4_w  = D_MODEL * D_MODEL / 4;

    PrepArgs pa;
    pa.src[0] = query; pa.dst[0] = p_rq; pa.n4[0] = n4_in; pa.scale[0] = 1.f;
    pa.src[1] = key;   pa.dst[1] = p_rk; pa.n4[1] = n4_in; pa.scale[1] = 1.f;
    pa.src[2] = value; pa.dst[2] = p_rv; pa.n4[2] = n4_in; pa.scale[2] = 1.f;
    pa.src[3] = Wq;    pa.dst[3] = p_wq; pa.n4[3] = n4_w;  pa.scale[3] = ATT_SCALE;
    pa.src[4] = Wk;    pa.dst[4] = p_wk; pa.n4[4] = n4_w;  pa.scale[4] = 1.f;
    pa.src[5] = Wv;    pa.dst[5] = p_wv; pa.n4[5] = n4_w;  pa.scale[5] = 1.f;
    pa.src[6] = Wo;    pa.dst[6] = p_wo; pa.n4[6] = n4_w;  pa.scale[6] = 1.f;

    prep_all_kernel<<<dim3(160, 7), 256>>>(pa);

    cudaFuncSetAttribute(proj_kernel, cudaFuncAttributeMaxDynamicSharedMemorySize, GEMM_SMEM);
    cudaFuncSetAttribute(out_kernel,  cudaFuncAttributeMaxDynamicSharedMemorySize, GEMM_SMEM);
    cudaFuncSetAttribute(attn_kernel, cudaFuncAttributeMaxDynamicSharedMemorySize, ATTN_SMEM);

    proj_kernel<<<dim3(D_MODEL / GBN, M_TOT / GBM, 3), 256, GEMM_SMEM>>>();

    attn_kernel<<<dim3(SEQ / QT, BATCH * NUM_HEADS), 256, ATTN_SMEM>>>();

    out_kernel<<<dim3(D_MODEL / GBN, M_TOT / GBM), 256, GEMM_SMEM>>>(bo, out);
}

// round 11
// speedup vs baseline: 6.4919x; 1.1040x over previous
#include <cuda_runtime.h>
#include <cuda_fp16.h>
#include <cstdint>
#include <math.h>

// Problem constants
#define D_MODEL   1024
#define NUM_HEADS 16
#define HEAD_DIM  64
#define BATCH     2
#define SEQ       2048
#define M_TOT     (BATCH * SEQ)
#define ATT_SCALE 0.125f
#define LOG2E     1.4426950408889634f

// ---------------------------------------------------------------------------
// Scratch (device globals: allocation-free per harness rules)
// ---------------------------------------------------------------------------
__device__ __half g_q[BATCH * NUM_HEADS * SEQ * HEAD_DIM];  // [B,H,N,Dh] fp16 (0.125*log2e folded)
__device__ __half g_k[BATCH * NUM_HEADS * SEQ * HEAD_DIM];
__device__ __half g_v[BATCH * NUM_HEADS * SEQ * HEAD_DIM];
__device__ __half g_ctx[BATCH * SEQ * D_MODEL];             // [B,N,H*Dh] fp16

__device__ __half r_q[M_TOT * D_MODEL];                     // fp16 inputs
__device__ __half r_k[M_TOT * D_MODEL];
__device__ __half r_v[M_TOT * D_MODEL];
__device__ __half r_wq[D_MODEL * D_MODEL];                  // fp16 (0.125*log2e)*Wq
__device__ __half r_wk[D_MODEL * D_MODEL];
__device__ __half r_wv[D_MODEL * D_MODEL];
__device__ __half r_wo[D_MODEL * D_MODEL];

// ---------------------------------------------------------------------------
// helpers
// ---------------------------------------------------------------------------
__device__ __forceinline__ uint32_t smem_to_u32(const void* p) {
    uint32_t a;
    asm("{ .reg .u64 t; cvta.to.shared.u64 t, %1; cvt.u32.u64 %0, t; }" : "=r"(a) : "l"(p));
    return a;
}

// fp16 mma m16n8k16, fp32 accumulate
__device__ __forceinline__ void mma_f16(float* c,
                                        uint32_t a0, uint32_t a1, uint32_t a2, uint32_t a3,
                                        uint32_t b0, uint32_t b1)
{
    asm volatile(
        "mma.sync.aligned.m16n8k16.row.col.f32.f16.f16.f32 "
        "{%0,%1,%2,%3}, {%4,%5,%6,%7}, {%8,%9}, {%0,%1,%2,%3};\n"
        : "+f"(c[0]), "+f"(c[1]), "+f"(c[2]), "+f"(c[3])
        : "r"(a0), "r"(a1), "r"(a2), "r"(a3), "r"(b0), "r"(b1));
}

__device__ __forceinline__ void ldsm_x4(uint32_t& d0, uint32_t& d1,
                                        uint32_t& d2, uint32_t& d3, uint32_t addr)
{
    asm volatile("ldmatrix.sync.aligned.m8n8.x4.shared.b16 {%0,%1,%2,%3}, [%4];"
                 : "=r"(d0), "=r"(d1), "=r"(d2), "=r"(d3) : "r"(addr));
}

// transposed ldmatrix: for B-frags from row-major V[j][dv]
__device__ __forceinline__ void ldsm_x4_t(uint32_t& d0, uint32_t& d1,
                                          uint32_t& d2, uint32_t& d3, uint32_t addr)
{
    asm volatile("ldmatrix.sync.aligned.m8n8.x4.trans.shared.b16 {%0,%1,%2,%3}, [%4];"
                 : "=r"(d0), "=r"(d1), "=r"(d2), "=r"(d3) : "r"(addr));
}

__device__ __forceinline__ void cp16(uint32_t dst, const void* src) {
    asm volatile("cp.async.cg.shared.global [%0], [%1], 16;" :: "r"(dst), "l"(src));
}
#define CP_COMMIT() asm volatile("cp.async.commit_group;" ::: "memory")
#define CP_WAIT(n)  asm volatile("cp.async.wait_group %0;" :: "n"(n) : "memory")

__device__ __forceinline__ uint32_t pack_h2(float a, float b) {
    __half2 h = __floats2half2_rn(a, b);
    return *(uint32_t*)&h;
}

// ---------------------------------------------------------------------------
// prep (single launch): segment y converts src[y] -> dst[y] (fp16, scaled)
// ---------------------------------------------------------------------------
struct PrepArgs {
    const float* src[7];
    __half*      dst[7];
    int          n4[7];
    float        scale[7];
};

__global__ __launch_bounds__(256)
void prep_all_kernel(PrepArgs a)
{
    const int seg = blockIdx.y;
    const float* __restrict__ s = a.src[seg];
    __half* __restrict__ d = a.dst[seg];
    const int n4 = a.n4[seg];
    const float sc = a.scale[seg];

    const int stride = gridDim.x * blockDim.x;
    for (int i = blockIdx.x * blockDim.x + threadIdx.x; i < n4; i += stride) {
        float4 v = ((const float4*)s)[i];
        uint2 o;
        o.x = pack_h2(v.x * sc, v.y * sc);
        o.y = pack_h2(v.z * sc, v.w * sc);
        ((uint2*)d)[i] = o;
    }
}

// ---------------------------------------------------------------------------
// fp16 MMA GEMM: C = A @ W^T. CTA 128x128x32(halves), 256 thr = 8 warps
// (2m x 4n), warp tile 64x32. 3-stage cp.async, LDSM frags. (unchanged R9)
// ---------------------------------------------------------------------------
#define GBM 128
#define GBN 128
#define GBK 32
#define GPITCH 40
#define GSTG (GBM * GPITCH)
#define NKB (D_MODEL / GBK)
#define GEMM_SMEM (3 * GSTG * 2 * 2)

__device__ __forceinline__ void gemm_f16_body(const __half* __restrict__ A,
                                              const __half* __restrict__ W,
                                              void* __restrict__ Optr,
                                              const float* __restrict__ bo,
                                              int m0, int n0, int mode)
{
    extern __shared__ __align__(16) __half gsm[];
    __half* As = gsm;
    __half* Bs = gsm + 3 * GSTG;

    const int t    = threadIdx.x;
    const int lane = t & 31;
    const int wid  = t >> 5;
    const int wm   = wid & 1;
    const int wn   = wid >> 1;
    const int fr   = lane >> 2;
    const int fc   = lane & 3;
    const int g    = lane >> 3;
    const int li   = lane & 7;
    const int K    = D_MODEL;

    uint32_t as_u[3], bs_u[3];
#pragma unroll
    for (int s = 0; s < 3; s++) {
        as_u[s] = smem_to_u32(As + s * GSTG);
        bs_u[s] = smem_to_u32(Bs + s * GSTG);
    }

    float acc[4][4][4];
#pragma unroll
    for (int i = 0; i < 4; i++)
#pragma unroll
        for (int j = 0; j < 4; j++)
#pragma unroll
            for (int r = 0; r < 4; r++) acc[i][j][r] = 0.f;

    const int srow = t >> 2;
    const int sc8  = (t & 3) * 8;

#define GEMM_STAGE(s, kb) do {                                                   \
        const int _k0 = (kb) * GBK;                                              \
        _Pragma("unroll")                                                        \
        for (int _u = 0; _u < 2; _u++) {                                         \
            const int _row = srow + 64 * _u;                                     \
            const uint32_t _so = (uint32_t)((_row * GPITCH + sc8) * 2);          \
            cp16(as_u[s] + _so, A + (size_t)(m0 + _row) * K + _k0 + sc8);        \
            cp16(bs_u[s] + _so, W + (size_t)(n0 + _row) * K + _k0 + sc8);        \
        }                                                                        \
    } while (0)

    GEMM_STAGE(0, 0); CP_COMMIT();
    GEMM_STAGE(1, 1); CP_COMMIT();

    for (int kb = 0; kb < NKB; kb++) {
        const int cur = kb % 3;
        if (kb + 1 < NKB) { CP_WAIT(1); } else { CP_WAIT(0); }
        __syncthreads();

#pragma unroll
        for (int ks = 0; ks < 2; ks++) {
            const int kc0 = ks * 16;
            uint32_t af[4][4];
#pragma unroll
            for (int mt = 0; mt < 4; mt++) {
                const int row = wm * 64 + mt * 16 + (g & 1) * 8 + li;
                const uint32_t addr = as_u[cur] +
                    (uint32_t)((row * GPITCH + kc0 + (g >> 1) * 8) * 2);
                ldsm_x4(af[mt][0], af[mt][1], af[mt][2], af[mt][3], addr);
            }
            uint32_t bf[4][2];
#pragma unroll
            for (int np = 0; np < 2; np++) {
                const int row = wn * 32 + np * 16 + (g >> 1) * 8 + li;
                const uint32_t addr = bs_u[cur] +
                    (uint32_t)((row * GPITCH + kc0 + (g & 1) * 8) * 2);
                ldsm_x4(bf[2 * np][0], bf[2 * np][1],
                        bf[2 * np + 1][0], bf[2 * np + 1][1], addr);
            }
#pragma unroll
            for (int nt = 0; nt < 4; nt++)
#pragma unroll
                for (int mt = 0; mt < 4; mt++)
                    mma_f16(acc[mt][nt], af[mt][0], af[mt][1], af[mt][2], af[mt][3],
                            bf[nt][0], bf[nt][1]);
        }

        if (kb + 2 < NKB) { GEMM_STAGE((kb + 2) % 3, kb + 2); CP_COMMIT(); }
    }

    // epilogue
#pragma unroll
    for (int mt = 0; mt < 4; mt++) {
        const int r0 = m0 + wm * 64 + mt * 16 + fr;
#pragma unroll
        for (int nt = 0; nt < 4; nt++) {
            const int col = n0 + wn * 32 + nt * 8 + fc * 2;
            if (mode == 0) {
                __half* O = (__half*)Optr;
                const int h = col >> 6, d = col & 63;
#pragma unroll
                for (int half_ = 0; half_ < 2; half_++) {
                    const int m  = r0 + half_ * 8;
                    const int b  = m >> 11;
                    const int nq = m & (SEQ - 1);
                    __half2 o = __floats2half2_rn(acc[mt][nt][half_ * 2],
                                                  acc[mt][nt][half_ * 2 + 1]);
                    *(__half2*)&O[(((size_t)b * NUM_HEADS + h) * SEQ + nq) * HEAD_DIM + d] = o;
                }
            } else {
                float* O = (float*)Optr;
                const float b0 = bo[col], b1 = bo[col + 1];
#pragma unroll
                for (int half_ = 0; half_ < 2; half_++) {
                    const int m = r0 + half_ * 8;
                    float2 o = make_float2(acc[mt][nt][half_ * 2] + b0,
                                           acc[mt][nt][half_ * 2 + 1] + b1);
                    *(float2*)&O[(size_t)m * D_MODEL + col] = o;
                }
            }
        }
    }
#undef GEMM_STAGE
}

__global__ __launch_bounds__(256)
void proj_kernel()
{
    const int z = blockIdx.z;
    const __half* A = (z == 0) ? r_q  : ((z == 1) ? r_k  : r_v);
    const __half* W = (z == 0) ? r_wq : ((z == 1) ? r_wk : r_wv);
    __half*       O = (z == 0) ? g_q  : ((z == 1) ? g_k  : g_v);
    gemm_f16_body(A, W, O, nullptr, blockIdx.y * GBM, blockIdx.x * GBN, 0);
}

__global__ __launch_bounds__(256)
void out_kernel(const float* __restrict__ bo, float* __restrict__ Cout)
{
    gemm_f16_body(g_ctx, r_wo, Cout, bo, blockIdx.y * GBM, blockIdx.x * GBN, 1);
}

// ---------------------------------------------------------------------------
// Flash attention, fp16 mma m16n8k16, fp32 accum.
// Scores arrive in log2-domain (log2e folded into Wq): softmax uses h2exp2,
// producing P fragments directly. V staged row-major via cp.async and read
// with ldmatrix.trans (no manual transpose). P stays in registers (FA2).
// ---------------------------------------------------------------------------
#define QT 128
#define KT 64
#define NT (SEQ / KT)
#define PS 72
#define ABUF (KT * PS)
#define ATTN_SMEM ((QT * PS + 4 * ABUF) * 2)   // 55296 B

__global__ __launch_bounds__(256)
void attn_kernel()
{
    extern __shared__ __align__(16) __half asm_[];

    const int t    = threadIdx.x;
    const int lane = t & 31;
    const int w    = t >> 5;
    const int g    = lane >> 3;
    const int li   = lane & 7;

    const uint32_t qs_u  = smem_to_u32(asm_);
    const uint32_t ksb_u = qs_u + QT * PS * 2;
    const uint32_t vsb_u = ksb_u + 2 * ABUF * 2;

    const int q0 = blockIdx.x * QT;
    const int bh = blockIdx.y;
    const __half* qb = g_q + (size_t)bh * SEQ * HEAD_DIM;
    const __half* kb = g_k + (size_t)bh * SEQ * HEAD_DIM;
    const __half* vb = g_v + (size_t)bh * SEQ * HEAD_DIM;

    // cp.async staging map: chunk i: row = i>>3, c8 = (i&7)*8 halves
    const int crow = t >> 3;          // 0..31 (+32u)
    const int cc8  = (t & 7) * 8;

    // ---- prologue: Q + K0 + V0 via cp.async ----
#pragma unroll
    for (int u = 0; u < 4; u++) {
        const int row = crow + 32 * u;
        cp16(qs_u + (uint32_t)((row * PS + cc8) * 2),
             qb + (size_t)(q0 + row) * HEAD_DIM + cc8);
    }
#pragma unroll
    for (int u = 0; u < 2; u++) {
        const int row = crow + 32 * u;
        cp16(ksb_u + (uint32_t)((row * PS + cc8) * 2),
             kb + (size_t)row * HEAD_DIM + cc8);
        cp16(vsb_u + (uint32_t)((row * PS + cc8) * 2),
             vb + (size_t)row * HEAD_DIM + cc8);
    }
    CP_COMMIT();
    CP_WAIT(0);
    __syncthreads();

    // Q frags (4 ksteps of 16)
    uint32_t qa[4][4];
#pragma unroll
    for (int ks = 0; ks < 4; ks++) {
        const int row = w * 16 + (g & 1) * 8 + li;
        const uint32_t addr = qs_u + (uint32_t)((row * PS + ks * 16 + (g >> 1) * 8) * 2);
        ldsm_x4(qa[ks][0], qa[ks][1], qa[ks][2], qa[ks][3], addr);
    }

    float o[8][4];
    float m0 = -1e30f, m1 = -1e30f, l0 = 0.f, l1 = 0.f;
#pragma unroll
    for (int nt = 0; nt < 8; nt++)
#pragma unroll
        for (int r = 0; r < 4; r++) o[nt][r] = 0.f;

    for (int kt = 0; kt < NT; kt++) {
        const int cur = kt & 1;
        const bool more = (kt + 1 < NT);
        const uint32_t ks_u = ksb_u + (uint32_t)(cur * ABUF * 2);
        const uint32_t vs_u = vsb_u + (uint32_t)(cur * ABUF * 2);

        if (more) {
            const int j0 = (kt + 1) * KT;
            const uint32_t kdst = ksb_u + (uint32_t)((cur ^ 1) * ABUF * 2);
            const uint32_t vdst = vsb_u + (uint32_t)((cur ^ 1) * ABUF * 2);
#pragma unroll
            for (int u = 0; u < 2; u++) {
                const int row = crow + 32 * u;
                cp16(kdst + (uint32_t)((row * PS + cc8) * 2),
                     kb + (size_t)(j0 + row) * HEAD_DIM + cc8);
                cp16(vdst + (uint32_t)((row * PS + cc8) * 2),
                     vb + (size_t)(j0 + row) * HEAD_DIM + cc8);
            }
            CP_COMMIT();
        }

        // ---- S' = Q @ K^T (log2-domain scores; warp tile 16 x 64) ----
        float s[8][4];
#pragma unroll
        for (int nt = 0; nt < 8; nt++)
#pragma unroll
            for (int r = 0; r < 4; r++) s[nt][r] = 0.f;

#pragma unroll
        for (int ks = 0; ks < 4; ks++) {
            const int kc0 = ks * 16;
            uint32_t bf[8][2];
#pragma unroll
            for (int np = 0; np < 4; np++) {
                const int row = np * 16 + (g >> 1) * 8 + li;
                const uint32_t addr = ks_u + (uint32_t)((row * PS + kc0 + (g & 1) * 8) * 2);
                ldsm_x4(bf[2 * np][0], bf[2 * np][1],
                        bf[2 * np + 1][0], bf[2 * np + 1][1], addr);
            }
#pragma unroll
            for (int nt = 0; nt < 8; nt++)
                mma_f16(s[nt], qa[ks][0], qa[ks][1], qa[ks][2], qa[ks][3],
                        bf[nt][0], bf[nt][1]);
        }

        // ---- online softmax in base-2 domain; P via h2exp2 -> frags ----
        float rm0 = -1e30f, rm1 = -1e30f;
#pragma unroll
        for (int nt = 0; nt < 8; nt++) {
            rm0 = fmaxf(rm0, fmaxf(s[nt][0], s[nt][1]));
            rm1 = fmaxf(rm1, fmaxf(s[nt][2], s[nt][3]));
        }
        rm0 = fmaxf(rm0, __shfl_xor_sync(0xffffffffu, rm0, 1));
        rm0 = fmaxf(rm0, __shfl_xor_sync(0xffffffffu, rm0, 2));
        rm1 = fmaxf(rm1, __shfl_xor_sync(0xffffffffu, rm1, 1));
        rm1 = fmaxf(rm1, __shfl_xor_sync(0xffffffffu, rm1, 2));

        const float mn0 = fmaxf(m0, rm0);
        const float mn1 = fmaxf(m1, rm1);
        const float cr0 = exp2f(m0 - mn0);
        const float cr1 = exp2f(m1 - mn1);
        m0 = mn0; m1 = mn1;

        // P frags: pa[ks][0]=rows fr (nt=2ks), [1]=rows fr+8 (nt=2ks),
        //          [2]=rows fr (nt=2ks+1), [3]=rows fr+8 (nt=2ks+1)
        uint32_t pa[4][4];
        float rs0 = 0.f, rs1 = 0.f;
#pragma unroll
        for (int nt = 0; nt < 8; nt++) {
            __half2 a01 = __floats2half2_rn(s[nt][0] - mn0, s[nt][1] - mn0);
            __half2 a23 = __floats2half2_rn(s[nt][2] - mn1, s[nt][3] - mn1);
            __half2 p01 = h2exp2(a01);
            __half2 p23 = h2exp2(a23);
            pa[nt >> 1][(nt & 1) * 2 + 0] = *(uint32_t*)&p01;
            pa[nt >> 1][(nt & 1) * 2 + 1] = *(uint32_t*)&p23;
            float2 f01 = __half22float2(p01);
            float2 f23 = __half22float2(p23);
            rs0 += f01.x + f01.y;
            rs1 += f23.x + f23.y;
        }
        rs0 += __shfl_xor_sync(0xffffffffu, rs0, 1);
        rs0 += __shfl_xor_sync(0xffffffffu, rs0, 2);
        rs1 += __shfl_xor_sync(0xffffffffu, rs1, 1);
        rs1 += __shfl_xor_sync(0xffffffffu, rs1, 2);
        l0 = l0 * cr0 + rs0;
        l1 = l1 * cr1 + rs1;

#pragma unroll
        for (int nt = 0; nt < 8; nt++) {
            o[nt][0] *= cr0; o[nt][1] *= cr0;
            o[nt][2] *= cr1; o[nt][3] *= cr1;
        }

        // ---- O += P @ V (B-frags from row-major V via ldmatrix.trans) ----
#pragma unroll
        for (int ks = 0; ks < 4; ks++) {
            const int kc0 = ks * 16;   // j-rows within tile
            uint32_t bf[8][2];
#pragma unroll
            for (int np = 0; np < 4; np++) {
                const int row = kc0 + (g & 1) * 8 + li;       // j
                const int col = np * 16 + (g >> 1) * 8;       // dv
                const uint32_t addr = vs_u + (uint32_t)((row * PS + col) * 2);
                ldsm_x4_t(bf[2 * np][0], bf[2 * np][1],
                          bf[2 * np + 1][0], bf[2 * np + 1][1], addr);
            }
#pragma unroll
            for (int nt = 0; nt < 8; nt++)
                mma_f16(o[nt], pa[ks][0], pa[ks][1], pa[ks][2], pa[ks][3],
                        bf[nt][0], bf[nt][1]);
        }

        if (more) { CP_WAIT(0); }
        __syncthreads();
    }

    // ---- epilogue: O /= l, write g_ctx fp16 ----
    const int fr = lane >> 2;
    const int fc = lane & 3;
    const int b = bh >> 4;
    const int h = bh & 15;
    const float inv0 = 1.f / l0;
    const float inv1 = 1.f / l1;
    const int r0 = q0 + w * 16 + fr;
#pragma unroll
    for (int nt = 0; nt < 8; nt++) {
        const int dv = nt * 8 + fc * 2;
        __half* base0 = &g_ctx[((size_t)b * SEQ + r0) * D_MODEL + h * HEAD_DIM + dv];
        __half* base1 = &g_ctx[((size_t)b * SEQ + r0 + 8) * D_MODEL + h * HEAD_DIM + dv];
        *(__half2*)base0 = __floats2half2_rn(o[nt][0] * inv0, o[nt][1] * inv0);
        *(__half2*)base1 = __floats2half2_rn(o[nt][2] * inv1, o[nt][3] * inv1);
    }
}

// ---------------------------------------------------------------------------
// kernel_launch
// ---------------------------------------------------------------------------
extern "C" void kernel_launch(void* const* d_in, const int* in_sizes, int n_in,
                              void* d_out, int out_size)
{
    const float* query = (const float*)d_in[0];
    const float* key   = (const float*)d_in[1];
    const float* value = (const float*)d_in[2];
    const float* Wq    = (const float*)d_in[3];
    const float* Wk    = (const float*)d_in[4];
    const float* Wv    = (const float*)d_in[5];
    const float* Wo    = (const float*)d_in[6];
    const float* bo    = (const float*)d_in[7];
    float* out = (float*)d_out;

    __half *p_rq, *p_rk, *p_rv, *p_wq, *p_wk, *p_wv, *p_wo;
    cudaGetSymbolAddress((void**)&p_rq, r_q);
    cudaGetSymbolAddress((void**)&p_rk, r_k);
    cudaGetSymbolAddress((void**)&p_rv, r_v);
    cudaGetSymbolAddress((void**)&p_wq, r_wq);
    cudaGetSymbolAddress((void**)&p_wk, r_wk);
    cudaGetSymbolAddress((void**)&p_wv, r_wv);
    cudaGetSymbolAddress((void**)&p_wo, r_wo);

    const int n4_in = M_TOT * D_MODEL / 4;
    const int n4_w  = D_MODEL * D_MODEL / 4;

    PrepArgs pa;
    pa.src[0] = query; pa.dst[0] = p_rq; pa.n4[0] = n4_in; pa.scale[0] = 1.f;
    pa.src[1] = key;   pa.dst[1] = p_rk; pa.n4[1] = n4_in; pa.scale[1] = 1.f;
    pa.src[2] = value; pa.dst[2] = p_rv; pa.n4[2] = n4_in; pa.scale[2] = 1.f;
    pa.src[3] = Wq;    pa.dst[3] = p_wq; pa.n4[3] = n4_w;  pa.scale[3] = ATT_SCALE * LOG2E;
    pa.src[4] = Wk;    pa.dst[4] = p_wk; pa.n4[4] = n4_w;  pa.scale[4] = 1.f;
    pa.src[5] = Wv;    pa.dst[5] = p_wv; pa.n4[5] = n4_w;  pa.scale[5] = 1.f;
    pa.src[6] = Wo;    pa.dst[6] = p_wo; pa.n4[6] = n4_w;  pa.scale[6] = 1.f;

    prep_all_kernel<<<dim3(160, 7), 256>>>(pa);

    cudaFuncSetAttribute(proj_kernel, cudaFuncAttributeMaxDynamicSharedMemorySize, GEMM_SMEM);
    cudaFuncSetAttribute(out_kernel,  cudaFuncAttributeMaxDynamicSharedMemorySize, GEMM_SMEM);
    cudaFuncSetAttribute(attn_kernel, cudaFuncAttributeMaxDynamicSharedMemorySize, ATTN_SMEM);

    proj_kernel<<<dim3(D_MODEL / GBN, M_TOT / GBM, 3), 256, GEMM_SMEM>>>();

    attn_kernel<<<dim3(SEQ / QT, BATCH * NUM_HEADS), 256, ATTN_SMEM>>>();

    out_kernel<<<dim3(D_MODEL / GBN, M_TOT / GBM), 256, GEMM_SMEM>>>(bo, out);
}

// round 12
// speedup vs baseline: 6.7112x; 1.0338x over previous
#include <cuda_runtime.h>
#include <cuda_fp16.h>
#include <cstdint>
#include <math.h>

// Problem constants
#define D_MODEL   1024
#define NUM_HEADS 16
#define HEAD_DIM  64
#define BATCH     2
#define SEQ       2048
#define M_TOT     (BATCH * SEQ)
#define ATT_SCALE 0.125f
#define LOG2E     1.4426950408889634f

// ---------------------------------------------------------------------------
// Scratch (device globals: allocation-free per harness rules)
// ---------------------------------------------------------------------------
__device__ __half g_q[BATCH * NUM_HEADS * SEQ * HEAD_DIM];  // fp16, 0.125*log2e folded
__device__ __half g_k[BATCH * NUM_HEADS * SEQ * HEAD_DIM];
__device__ __half g_v[BATCH * NUM_HEADS * SEQ * HEAD_DIM];
__device__ __half g_ctx[BATCH * SEQ * D_MODEL];             // [B,N,H*Dh] fp16

__device__ __half r_q[M_TOT * D_MODEL];
__device__ __half r_k[M_TOT * D_MODEL];
__device__ __half r_v[M_TOT * D_MODEL];
__device__ __half r_wq[D_MODEL * D_MODEL];
__device__ __half r_wk[D_MODEL * D_MODEL];
__device__ __half r_wv[D_MODEL * D_MODEL];
__device__ __half r_wo[D_MODEL * D_MODEL];

// ---------------------------------------------------------------------------
// helpers
// ---------------------------------------------------------------------------
__device__ __forceinline__ uint32_t smem_to_u32(const void* p) {
    uint32_t a;
    asm("{ .reg .u64 t; cvta.to.shared.u64 t, %1; cvt.u32.u64 %0, t; }" : "=r"(a) : "l"(p));
    return a;
}

__device__ __forceinline__ void mma_f16(float* c,
                                        uint32_t a0, uint32_t a1, uint32_t a2, uint32_t a3,
                                        uint32_t b0, uint32_t b1)
{
    asm volatile(
        "mma.sync.aligned.m16n8k16.row.col.f32.f16.f16.f32 "
        "{%0,%1,%2,%3}, {%4,%5,%6,%7}, {%8,%9}, {%0,%1,%2,%3};\n"
        : "+f"(c[0]), "+f"(c[1]), "+f"(c[2]), "+f"(c[3])
        : "r"(a0), "r"(a1), "r"(a2), "r"(a3), "r"(b0), "r"(b1));
}

__device__ __forceinline__ void ldsm_x4(uint32_t& d0, uint32_t& d1,
                                        uint32_t& d2, uint32_t& d3, uint32_t addr)
{
    asm volatile("ldmatrix.sync.aligned.m8n8.x4.shared.b16 {%0,%1,%2,%3}, [%4];"
                 : "=r"(d0), "=r"(d1), "=r"(d2), "=r"(d3) : "r"(addr));
}

__device__ __forceinline__ void ldsm_x4_t(uint32_t& d0, uint32_t& d1,
                                          uint32_t& d2, uint32_t& d3, uint32_t addr)
{
    asm volatile("ldmatrix.sync.aligned.m8n8.x4.trans.shared.b16 {%0,%1,%2,%3}, [%4];"
                 : "=r"(d0), "=r"(d1), "=r"(d2), "=r"(d3) : "r"(addr));
}

__device__ __forceinline__ void cp16(uint32_t dst, const void* src) {
    asm volatile("cp.async.cg.shared.global [%0], [%1], 16;" :: "r"(dst), "l"(src));
}
#define CP_COMMIT() asm volatile("cp.async.commit_group;" ::: "memory")
#define CP_WAIT(n)  asm volatile("cp.async.wait_group %0;" :: "n"(n) : "memory")

__device__ __forceinline__ uint32_t pack_h2(float a, float b) {
    __half2 h = __floats2half2_rn(a, b);
    return *(uint32_t*)&h;
}

// ---------------------------------------------------------------------------
// prep (single launch)
// ---------------------------------------------------------------------------
struct PrepArgs {
    const float* src[7];
    __half*      dst[7];
    int          n4[7];
    float        scale[7];
};

__global__ __launch_bounds__(256)
void prep_all_kernel(PrepArgs a)
{
    const int seg = blockIdx.y;
    const float* __restrict__ s = a.src[seg];
    __half* __restrict__ d = a.dst[seg];
    const int n4 = a.n4[seg];
    const float sc = a.scale[seg];

    const int stride = gridDim.x * blockDim.x;
    for (int i = blockIdx.x * blockDim.x + threadIdx.x; i < n4; i += stride) {
        float4 v = ((const float4*)s)[i];
        uint2 o;
        o.x = pack_h2(v.x * sc, v.y * sc);
        o.y = pack_h2(v.z * sc, v.w * sc);
        ((uint2*)d)[i] = o;
    }
}

// ---------------------------------------------------------------------------
// fp16 MMA GEMM (unchanged from R10)
// ---------------------------------------------------------------------------
#define GBM 128
#define GBN 128
#define GBK 32
#define GPITCH 40
#define GSTG (GBM * GPITCH)
#define NKB (D_MODEL / GBK)
#define GEMM_SMEM (3 * GSTG * 2 * 2)

__device__ __forceinline__ void gemm_f16_body(const __half* __restrict__ A,
                                              const __half* __restrict__ W,
                                              void* __restrict__ Optr,
                                              const float* __restrict__ bo,
                                              int m0, int n0, int mode)
{
    extern __shared__ __align__(16) __half gsm[];
    __half* As = gsm;
    __half* Bs = gsm + 3 * GSTG;

    const int t    = threadIdx.x;
    const int lane = t & 31;
    const int wid  = t >> 5;
    const int wm   = wid & 1;
    const int wn   = wid >> 1;
    const int fr   = lane >> 2;
    const int fc   = lane & 3;
    const int g    = lane >> 3;
    const int li   = lane & 7;
    const int K    = D_MODEL;

    uint32_t as_u[3], bs_u[3];
#pragma unroll
    for (int s = 0; s < 3; s++) {
        as_u[s] = smem_to_u32(As + s * GSTG);
        bs_u[s] = smem_to_u32(Bs + s * GSTG);
    }

    float acc[4][4][4];
#pragma unroll
    for (int i = 0; i < 4; i++)
#pragma unroll
        for (int j = 0; j < 4; j++)
#pragma unroll
            for (int r = 0; r < 4; r++) acc[i][j][r] = 0.f;

    const int srow = t >> 2;
    const int sc8  = (t & 3) * 8;

#define GEMM_STAGE(s, kb) do {                                                   \
        const int _k0 = (kb) * GBK;                                              \
        _Pragma("unroll")                                                        \
        for (int _u = 0; _u < 2; _u++) {                                         \
            const int _row = srow + 64 * _u;                                     \
            const uint32_t _so = (uint32_t)((_row * GPITCH + sc8) * 2);          \
            cp16(as_u[s] + _so, A + (size_t)(m0 + _row) * K + _k0 + sc8);        \
            cp16(bs_u[s] + _so, W + (size_t)(n0 + _row) * K + _k0 + sc8);        \
        }                                                                        \
    } while (0)

    GEMM_STAGE(0, 0); CP_COMMIT();
    GEMM_STAGE(1, 1); CP_COMMIT();

    for (int kb = 0; kb < NKB; kb++) {
        const int cur = kb % 3;
        if (kb + 1 < NKB) { CP_WAIT(1); } else { CP_WAIT(0); }
        __syncthreads();

#pragma unroll
        for (int ks = 0; ks < 2; ks++) {
            const int kc0 = ks * 16;
            uint32_t af[4][4];
#pragma unroll
            for (int mt = 0; mt < 4; mt++) {
                const int row = wm * 64 + mt * 16 + (g & 1) * 8 + li;
                const uint32_t addr = as_u[cur] +
                    (uint32_t)((row * GPITCH + kc0 + (g >> 1) * 8) * 2);
                ldsm_x4(af[mt][0], af[mt][1], af[mt][2], af[mt][3], addr);
            }
            uint32_t bf[4][2];
#pragma unroll
            for (int np = 0; np < 2; np++) {
                const int row = wn * 32 + np * 16 + (g >> 1) * 8 + li;
                const uint32_t addr = bs_u[cur] +
                    (uint32_t)((row * GPITCH + kc0 + (g & 1) * 8) * 2);
                ldsm_x4(bf[2 * np][0], bf[2 * np][1],
                        bf[2 * np + 1][0], bf[2 * np + 1][1], addr);
            }
#pragma unroll
            for (int nt = 0; nt < 4; nt++)
#pragma unroll
                for (int mt = 0; mt < 4; mt++)
                    mma_f16(acc[mt][nt], af[mt][0], af[mt][1], af[mt][2], af[mt][3],
                            bf[nt][0], bf[nt][1]);
        }

        if (kb + 2 < NKB) { GEMM_STAGE((kb + 2) % 3, kb + 2); CP_COMMIT(); }
    }

#pragma unroll
    for (int mt = 0; mt < 4; mt++) {
        const int r0 = m0 + wm * 64 + mt * 16 + fr;
#pragma unroll
        for (int nt = 0; nt < 4; nt++) {
            const int col = n0 + wn * 32 + nt * 8 + fc * 2;
            if (mode == 0) {
                __half* O = (__half*)Optr;
                const int h = col >> 6, d = col & 63;
#pragma unroll
                for (int half_ = 0; half_ < 2; half_++) {
                    const int m  = r0 + half_ * 8;
                    const int b  = m >> 11;
                    const int nq = m & (SEQ - 1);
                    __half2 o = __floats2half2_rn(acc[mt][nt][half_ * 2],
                                                  acc[mt][nt][half_ * 2 + 1]);
                    *(__half2*)&O[(((size_t)b * NUM_HEADS + h) * SEQ + nq) * HEAD_DIM + d] = o;
                }
            } else {
                float* O = (float*)Optr;
                const float b0 = bo[col], b1 = bo[col + 1];
#pragma unroll
                for (int half_ = 0; half_ < 2; half_++) {
                    const int m = r0 + half_ * 8;
                    float2 o = make_float2(acc[mt][nt][half_ * 2] + b0,
                                           acc[mt][nt][half_ * 2 + 1] + b1);
                    *(float2*)&O[(size_t)m * D_MODEL + col] = o;
                }
            }
        }
    }
#undef GEMM_STAGE
}

__global__ __launch_bounds__(256)
void proj_kernel()
{
    const int z = blockIdx.z;
    const __half* A = (z == 0) ? r_q  : ((z == 1) ? r_k  : r_v);
    const __half* W = (z == 0) ? r_wq : ((z == 1) ? r_wk : r_wv);
    __half*       O = (z == 0) ? g_q  : ((z == 1) ? g_k  : g_v);
    gemm_f16_body(A, W, O, nullptr, blockIdx.y * GBM, blockIdx.x * GBN, 0);
}

__global__ __launch_bounds__(256)
void out_kernel(const float* __restrict__ bo, float* __restrict__ Cout)
{
    gemm_f16_body(g_ctx, r_wo, Cout, bo, blockIdx.y * GBM, blockIdx.x * GBN, 1);
}

// ---------------------------------------------------------------------------
// Flash attention, fp16 mma, fp32 accum. log2-domain softmax via h2exp2.
// 4 warps x 32 q-rows (MT=2): K/V B-fragments loaded ONCE per warp and
// reused across 2 m-tiles -> LDSM per CTA halved vs R10. Bit-identical math.
// ---------------------------------------------------------------------------
#define QT 128
#define KT 64
#define NT (SEQ / KT)
#define PS 72
#define ABUF (KT * PS)
#define ATTN_SMEM ((QT * PS + 4 * ABUF) * 2)   // 55296 B

__global__ __launch_bounds__(128)
void attn_kernel()
{
    extern __shared__ __align__(16) __half asm_[];

    const int t    = threadIdx.x;
    const int lane = t & 31;
    const int w    = t >> 5;          // 0..3, rows w*32 .. w*32+31
    const int g    = lane >> 3;
    const int li   = lane & 7;

    const uint32_t qs_u  = smem_to_u32(asm_);
    const uint32_t ksb_u = qs_u + QT * PS * 2;
    const uint32_t vsb_u = ksb_u + 2 * ABUF * 2;

    const int q0 = blockIdx.x * QT;
    const int bh = blockIdx.y;
    const __half* qb = g_q + (size_t)bh * SEQ * HEAD_DIM;
    const __half* kb = g_k + (size_t)bh * SEQ * HEAD_DIM;
    const __half* vb = g_v + (size_t)bh * SEQ * HEAD_DIM;

    // cp.async staging map (128 threads): chunk i: row = i>>3, c8 = (i&7)*8
    const int crow = t >> 3;          // 0..15 (+16u)
    const int cc8  = (t & 7) * 8;

    // ---- prologue: Q + K0 + V0 via cp.async ----
#pragma unroll
    for (int u = 0; u < 8; u++) {
        const int row = crow + 16 * u;
        cp16(qs_u + (uint32_t)((row * PS + cc8) * 2),
             qb + (size_t)(q0 + row) * HEAD_DIM + cc8);
    }
#pragma unroll
    for (int u = 0; u < 4; u++) {
        const int row = crow + 16 * u;
        cp16(ksb_u + (uint32_t)((row * PS + cc8) * 2),
             kb + (size_t)row * HEAD_DIM + cc8);
        cp16(vsb_u + (uint32_t)((row * PS + cc8) * 2),
             vb + (size_t)row * HEAD_DIM + cc8);
    }
    CP_COMMIT();
    CP_WAIT(0);
    __syncthreads();

    // Q frags: 2 m-tiles x 4 ksteps
    uint32_t qa[2][4][4];
#pragma unroll
    for (int mt = 0; mt < 2; mt++)
#pragma unroll
        for (int ks = 0; ks < 4; ks++) {
            const int row = w * 32 + mt * 16 + (g & 1) * 8 + li;
            const uint32_t addr = qs_u +
                (uint32_t)((row * PS + ks * 16 + (g >> 1) * 8) * 2);
            ldsm_x4(qa[mt][ks][0], qa[mt][ks][1], qa[mt][ks][2], qa[mt][ks][3], addr);
        }

    float o[2][8][4];
    float m_[2][2], l_[2][2];
#pragma unroll
    for (int mt = 0; mt < 2; mt++) {
        m_[mt][0] = -1e30f; m_[mt][1] = -1e30f;
        l_[mt][0] = 0.f;    l_[mt][1] = 0.f;
#pragma unroll
        for (int nt = 0; nt < 8; nt++)
#pragma unroll
            for (int r = 0; r < 4; r++) o[mt][nt][r] = 0.f;
    }

    for (int kt = 0; kt < NT; kt++) {
        const int cur = kt & 1;
        const bool more = (kt + 1 < NT);
        const uint32_t ks_u = ksb_u + (uint32_t)(cur * ABUF * 2);
        const uint32_t vs_u = vsb_u + (uint32_t)(cur * ABUF * 2);

        if (more) {
            const int j0 = (kt + 1) * KT;
            const uint32_t kdst = ksb_u + (uint32_t)((cur ^ 1) * ABUF * 2);
            const uint32_t vdst = vsb_u + (uint32_t)((cur ^ 1) * ABUF * 2);
#pragma unroll
            for (int u = 0; u < 4; u++) {
                const int row = crow + 16 * u;
                cp16(kdst + (uint32_t)((row * PS + cc8) * 2),
                     kb + (size_t)(j0 + row) * HEAD_DIM + cc8);
                cp16(vdst + (uint32_t)((row * PS + cc8) * 2),
                     vb + (size_t)(j0 + row) * HEAD_DIM + cc8);
            }
            CP_COMMIT();
        }

        // ---- S' = Q @ K^T (log2 domain). B-frags shared across both m-tiles.
        float s[2][8][4];
#pragma unroll
        for (int mt = 0; mt < 2; mt++)
#pragma unroll
            for (int nt = 0; nt < 8; nt++)
#pragma unroll
                for (int r = 0; r < 4; r++) s[mt][nt][r] = 0.f;

#pragma unroll
        for (int ks = 0; ks < 4; ks++) {
            const int kc0 = ks * 16;
            uint32_t bf[8][2];
#pragma unroll
            for (int np = 0; np < 4; np++) {
                const int row = np * 16 + (g >> 1) * 8 + li;
                const uint32_t addr = ks_u + (uint32_t)((row * PS + kc0 + (g & 1) * 8) * 2);
                ldsm_x4(bf[2 * np][0], bf[2 * np][1],
                        bf[2 * np + 1][0], bf[2 * np + 1][1], addr);
            }
#pragma unroll
            for (int nt = 0; nt < 8; nt++) {
                mma_f16(s[0][nt], qa[0][ks][0], qa[0][ks][1], qa[0][ks][2], qa[0][ks][3],
                        bf[nt][0], bf[nt][1]);
                mma_f16(s[1][nt], qa[1][ks][0], qa[1][ks][1], qa[1][ks][2], qa[1][ks][3],
                        bf[nt][0], bf[nt][1]);
            }
        }

        // ---- online softmax (base-2) + P frags, per m-tile ----
        uint32_t pa[2][4][4];
#pragma unroll
        for (int mt = 0; mt < 2; mt++) {
            float rm0 = -1e30f, rm1 = -1e30f;
#pragma unroll
            for (int nt = 0; nt < 8; nt++) {
                rm0 = fmaxf(rm0, fmaxf(s[mt][nt][0], s[mt][nt][1]));
                rm1 = fmaxf(rm1, fmaxf(s[mt][nt][2], s[mt][nt][3]));
            }
            rm0 = fmaxf(rm0, __shfl_xor_sync(0xffffffffu, rm0, 1));
            rm0 = fmaxf(rm0, __shfl_xor_sync(0xffffffffu, rm0, 2));
            rm1 = fmaxf(rm1, __shfl_xor_sync(0xffffffffu, rm1, 1));
            rm1 = fmaxf(rm1, __shfl_xor_sync(0xffffffffu, rm1, 2));

            const float mn0 = fmaxf(m_[mt][0], rm0);
            const float mn1 = fmaxf(m_[mt][1], rm1);
            const float cr0 = exp2f(m_[mt][0] - mn0);
            const float cr1 = exp2f(m_[mt][1] - mn1);
            m_[mt][0] = mn0; m_[mt][1] = mn1;

            float rs0 = 0.f, rs1 = 0.f;
#pragma unroll
            for (int nt = 0; nt < 8; nt++) {
                __half2 a01 = __floats2half2_rn(s[mt][nt][0] - mn0, s[mt][nt][1] - mn0);
                __half2 a23 = __floats2half2_rn(s[mt][nt][2] - mn1, s[mt][nt][3] - mn1);
                __half2 p01 = h2exp2(a01);
                __half2 p23 = h2exp2(a23);
                pa[mt][nt >> 1][(nt & 1) * 2 + 0] = *(uint32_t*)&p01;
                pa[mt][nt >> 1][(nt & 1) * 2 + 1] = *(uint32_t*)&p23;
                float2 f01 = __half22float2(p01);
                float2 f23 = __half22float2(p23);
                rs0 += f01.x + f01.y;
                rs1 += f23.x + f23.y;
            }
            rs0 += __shfl_xor_sync(0xffffffffu, rs0, 1);
            rs0 += __shfl_xor_sync(0xffffffffu, rs0, 2);
            rs1 += __shfl_xor_sync(0xffffffffu, rs1, 1);
            rs1 += __shfl_xor_sync(0xffffffffu, rs1, 2);
            l_[mt][0] = l_[mt][0] * cr0 + rs0;
            l_[mt][1] = l_[mt][1] * cr1 + rs1;

#pragma unroll
            for (int nt = 0; nt < 8; nt++) {
                o[mt][nt][0] *= cr0; o[mt][nt][1] *= cr0;
                o[mt][nt][2] *= cr1; o[mt][nt][3] *= cr1;
            }
        }

        // ---- O += P @ V (trans B-frags shared across both m-tiles) ----
#pragma unroll
        for (int ks = 0; ks < 4; ks++) {
            const int kc0 = ks * 16;
            uint32_t bf[8][2];
#pragma unroll
            for (int np = 0; np < 4; np++) {
                const int row = kc0 + (g & 1) * 8 + li;       // j
                const int col = np * 16 + (g >> 1) * 8;       // dv
                const uint32_t addr = vs_u + (uint32_t)((row * PS + col) * 2);
                ldsm_x4_t(bf[2 * np][0], bf[2 * np][1],
                          bf[2 * np + 1][0], bf[2 * np + 1][1], addr);
            }
#pragma unroll
            for (int nt = 0; nt < 8; nt++) {
                mma_f16(o[0][nt], pa[0][ks][0], pa[0][ks][1], pa[0][ks][2], pa[0][ks][3],
                        bf[nt][0], bf[nt][1]);
                mma_f16(o[1][nt], pa[1][ks][0], pa[1][ks][1], pa[1][ks][2], pa[1][ks][3],
                        bf[nt][0], bf[nt][1]);
            }
        }

        if (more) { CP_WAIT(0); }
        __syncthreads();
    }

    // ---- epilogue ----
    const int fr = lane >> 2;
    const int fc = lane & 3;
    const int b = bh >> 4;
    const int h = bh & 15;
#pragma unroll
    for (int mt = 0; mt < 2; mt++) {
        const float inv0 = 1.f / l_[mt][0];
        const float inv1 = 1.f / l_[mt][1];
        const int r0 = q0 + w * 32 + mt * 16 + fr;
#pragma unroll
        for (int nt = 0; nt < 8; nt++) {
            const int dv = nt * 8 + fc * 2;
            __half* base0 = &g_ctx[((size_t)b * SEQ + r0) * D_MODEL + h * HEAD_DIM + dv];
            __half* base1 = &g_ctx[((size_t)b * SEQ + r0 + 8) * D_MODEL + h * HEAD_DIM + dv];
            *(__half2*)base0 = __floats2half2_rn(o[mt][nt][0] * inv0, o[mt][nt][1] * inv0);
            *(__half2*)base1 = __floats2half2_rn(o[mt][nt][2] * inv1, o[mt][nt][3] * inv1);
        }
    }
}

// ---------------------------------------------------------------------------
// kernel_launch
// ---------------------------------------------------------------------------
extern "C" void kernel_launch(void* const* d_in, const int* in_sizes, int n_in,
                              void* d_out, int out_size)
{
    const float* query = (const float*)d_in[0];
    const float* key   = (const float*)d_in[1];
    const float* value = (const float*)d_in[2];
    const float* Wq    = (const float*)d_in[3];
    const float* Wk    = (const float*)d_in[4];
    const float* Wv    = (const float*)d_in[5];
    const float* Wo    = (const float*)d_in[6];
    const float* bo    = (const float*)d_in[7];
    float* out = (float*)d_out;

    __half *p_rq, *p_rk, *p_rv, *p_wq, *p_wk, *p_wv, *p_wo;
    cudaGetSymbolAddress((void**)&p_rq, r_q);
    cudaGetSymbolAddress((void**)&p_rk, r_k);
    cudaGetSymbolAddress((void**)&p_rv, r_v);
    cudaGetSymbolAddress((void**)&p_wq, r_wq);
    cudaGetSymbolAddress((void**)&p_wk, r_wk);
    cudaGetSymbolAddress((void**)&p_wv, r_wv);
    cudaGetSymbolAddress((void**)&p_wo, r_wo);

    const int n4_in = M_TOT * D_MODEL / 4;
    const int n4_w  = D_MODEL * D_MODEL / 4;

    PrepArgs pa;
    pa.src[0] = query; pa.dst[0] = p_rq; pa.n4[0] = n4_in; pa.scale[0] = 1.f;
    pa.src[1] = key;   pa.dst[1] = p_rk; pa.n4[1] = n4_in; pa.scale[1] = 1.f;
    pa.src[2] = value; pa.dst[2] = p_rv; pa.n4[2] = n4_in; pa.scale[2] = 1.f;
    pa.src[3] = Wq;    pa.dst[3] = p_wq; pa.n4[3] = n4_w;  pa.scale[3] = ATT_SCALE * LOG2E;
    pa.src[4] = Wk;    pa.dst[4] = p_wk; pa.n4[4] = n4_w;  pa.scale[4] = 1.f;
    pa.src[5] = Wv;    pa.dst[5] = p_wv; pa.n4[5] = n4_w;  pa.scale[5] = 1.f;
    pa.src[6] = Wo;    pa.dst[6] = p_wo; pa.n4[6] = n4_w;  pa.scale[6] = 1.f;

    prep_all_kernel<<<dim3(160, 7), 256>>>(pa);

    cudaFuncSetAttribute(proj_kernel, cudaFuncAttributeMaxDynamicSharedMemorySize, GEMM_SMEM);
    cudaFuncSetAttribute(out_kernel,  cudaFuncAttributeMaxDynamicSharedMemorySize, GEMM_SMEM);
    cudaFuncSetAttribute(attn_kernel, cudaFuncAttributeMaxDynamicSharedMemorySize, ATTN_SMEM);

    proj_kernel<<<dim3(D_MODEL / GBN, M_TOT / GBM, 3), 256, GEMM_SMEM>>>();

    attn_kernel<<<dim3(SEQ / QT, BATCH * NUM_HEADS), 128, ATTN_SMEM>>>();

    out_kernel<<<dim3(D_MODEL / GBN, M_TOT / GBM), 256, GEMM_SMEM>>>(bo, out);
}

// round 13
// speedup vs baseline: 6.9863x; 1.0410x over previous
#include <cuda_runtime.h>
#include <cuda_fp16.h>
#include <cstdint>
#include <math.h>

// Problem constants
#define D_MODEL   1024
#define NUM_HEADS 16
#define HEAD_DIM  64
#define BATCH     2
#define SEQ       2048
#define M_TOT     (BATCH * SEQ)
#define ATT_SCALE 0.125f
#define LOG2E     1.4426950408889634f

// ---------------------------------------------------------------------------
// Scratch (device globals: allocation-free per harness rules)
// ---------------------------------------------------------------------------
__device__ __half g_q[BATCH * NUM_HEADS * SEQ * HEAD_DIM];  // fp16, 0.125*log2e folded
__device__ __half g_k[BATCH * NUM_HEADS * SEQ * HEAD_DIM];
__device__ __half g_v[BATCH * NUM_HEADS * SEQ * HEAD_DIM];
__device__ __half g_ctx[BATCH * SEQ * D_MODEL];             // [B,N,H*Dh] fp16

__device__ __half r_q[M_TOT * D_MODEL];
__device__ __half r_k[M_TOT * D_MODEL];
__device__ __half r_v[M_TOT * D_MODEL];
__device__ __half r_wq[D_MODEL * D_MODEL];
__device__ __half r_wk[D_MODEL * D_MODEL];
__device__ __half r_wv[D_MODEL * D_MODEL];
__device__ __half r_wo[D_MODEL * D_MODEL];

// ---------------------------------------------------------------------------
// helpers
// ---------------------------------------------------------------------------
__device__ __forceinline__ uint32_t smem_to_u32(const void* p) {
    uint32_t a;
    asm("{ .reg .u64 t; cvta.to.shared.u64 t, %1; cvt.u32.u64 %0, t; }" : "=r"(a) : "l"(p));
    return a;
}

__device__ __forceinline__ void mma_f16(float* c,
                                        uint32_t a0, uint32_t a1, uint32_t a2, uint32_t a3,
                                        uint32_t b0, uint32_t b1)
{
    asm volatile(
        "mma.sync.aligned.m16n8k16.row.col.f32.f16.f16.f32 "
        "{%0,%1,%2,%3}, {%4,%5,%6,%7}, {%8,%9}, {%0,%1,%2,%3};\n"
        : "+f"(c[0]), "+f"(c[1]), "+f"(c[2]), "+f"(c[3])
        : "r"(a0), "r"(a1), "r"(a2), "r"(a3), "r"(b0), "r"(b1));
}

__device__ __forceinline__ void ldsm_x4(uint32_t& d0, uint32_t& d1,
                                        uint32_t& d2, uint32_t& d3, uint32_t addr)
{
    asm volatile("ldmatrix.sync.aligned.m8n8.x4.shared.b16 {%0,%1,%2,%3}, [%4];"
                 : "=r"(d0), "=r"(d1), "=r"(d2), "=r"(d3) : "r"(addr));
}

__device__ __forceinline__ void ldsm_x4_t(uint32_t& d0, uint32_t& d1,
                                          uint32_t& d2, uint32_t& d3, uint32_t addr)
{
    asm volatile("ldmatrix.sync.aligned.m8n8.x4.trans.shared.b16 {%0,%1,%2,%3}, [%4];"
                 : "=r"(d0), "=r"(d1), "=r"(d2), "=r"(d3) : "r"(addr));
}

__device__ __forceinline__ void cp16(uint32_t dst, const void* src) {
    asm volatile("cp.async.cg.shared.global [%0], [%1], 16;" :: "r"(dst), "l"(src));
}
#define CP_COMMIT() asm volatile("cp.async.commit_group;" ::: "memory")
#define CP_WAIT(n)  asm volatile("cp.async.wait_group %0;" :: "n"(n) : "memory")

__device__ __forceinline__ uint32_t pack_h2(float a, float b) {
    __half2 h = __floats2half2_rn(a, b);
    return *(uint32_t*)&h;
}

// ---------------------------------------------------------------------------
// prep (single launch)
// ---------------------------------------------------------------------------
struct PrepArgs {
    const float* src[7];
    __half*      dst[7];
    int          n4[7];
    float        scale[7];
};

__global__ __launch_bounds__(256)
void prep_all_kernel(PrepArgs a)
{
    const int seg = blockIdx.y;
    const float* __restrict__ s = a.src[seg];
    __half* __restrict__ d = a.dst[seg];
    const int n4 = a.n4[seg];
    const float sc = a.scale[seg];

    const int stride = gridDim.x * blockDim.x;
    for (int i = blockIdx.x * blockDim.x + threadIdx.x; i < n4; i += stride) {
        float4 v = ((const float4*)s)[i];
        uint2 o;
        o.x = pack_h2(v.x * sc, v.y * sc);
        o.y = pack_h2(v.z * sc, v.w * sc);
        ((uint2*)d)[i] = o;
    }
}

// ---------------------------------------------------------------------------
// fp16 MMA GEMM: C = A @ W^T. CTA 128x128x32(halves), 128 thr = 4 warps
// (2m x 2n), warp tile 64x64. 3-stage cp.async, LDSM frags.
// LDSM:MMA ratio 0.25 (was 0.375 at warp 64x32).
// ---------------------------------------------------------------------------
#define GBM 128
#define GBN 128
#define GBK 32
#define GPITCH 40
#define GSTG (GBM * GPITCH)
#define NKB (D_MODEL / GBK)
#define GEMM_SMEM (3 * GSTG * 2 * 2)

__device__ __forceinline__ void gemm_f16_body(const __half* __restrict__ A,
                                              const __half* __restrict__ W,
                                              void* __restrict__ Optr,
                                              const float* __restrict__ bo,
                                              int m0, int n0, int mode)
{
    extern __shared__ __align__(16) __half gsm[];
    __half* As = gsm;
    __half* Bs = gsm + 3 * GSTG;

    const int t    = threadIdx.x;     // 0..127
    const int lane = t & 31;
    const int wid  = t >> 5;          // 0..3
    const int wm   = wid & 1;         // 0..1
    const int wn   = wid >> 1;        // 0..1
    const int fr   = lane >> 2;
    const int fc   = lane & 3;
    const int g    = lane >> 3;
    const int li   = lane & 7;
    const int K    = D_MODEL;

    uint32_t as_u[3], bs_u[3];
#pragma unroll
    for (int s = 0; s < 3; s++) {
        as_u[s] = smem_to_u32(As + s * GSTG);
        bs_u[s] = smem_to_u32(Bs + s * GSTG);
    }

    float acc[4][8][4];
#pragma unroll
    for (int i = 0; i < 4; i++)
#pragma unroll
        for (int j = 0; j < 8; j++)
#pragma unroll
            for (int r = 0; r < 4; r++) acc[i][j][r] = 0.f;

    // staging (128 threads): tile = 512 chunks of 16B per matrix -> 4/thread
    const int srow = t >> 2;          // 0..31 (+32u, u<4)
    const int sc8  = (t & 3) * 8;

#define GEMM_STAGE(s, kb) do {                                                   \
        const int _k0 = (kb) * GBK;                                              \
        _Pragma("unroll")                                                        \
        for (int _u = 0; _u < 4; _u++) {                                         \
            const int _row = srow + 32 * _u;                                     \
            const uint32_t _so = (uint32_t)((_row * GPITCH + sc8) * 2);          \
            cp16(as_u[s] + _so, A + (size_t)(m0 + _row) * K + _k0 + sc8);        \
            cp16(bs_u[s] + _so, W + (size_t)(n0 + _row) * K + _k0 + sc8);        \
        }                                                                        \
    } while (0)

    GEMM_STAGE(0, 0); CP_COMMIT();
    GEMM_STAGE(1, 1); CP_COMMIT();

    for (int kb = 0; kb < NKB; kb++) {
        const int cur = kb % 3;
        if (kb + 1 < NKB) { CP_WAIT(1); } else { CP_WAIT(0); }
        __syncthreads();

#pragma unroll
        for (int ks = 0; ks < 2; ks++) {
            const int kc0 = ks * 16;
            uint32_t af[4][4];
#pragma unroll
            for (int mt = 0; mt < 4; mt++) {
                const int row = wm * 64 + mt * 16 + (g & 1) * 8 + li;
                const uint32_t addr = as_u[cur] +
                    (uint32_t)((row * GPITCH + kc0 + (g >> 1) * 8) * 2);
                ldsm_x4(af[mt][0], af[mt][1], af[mt][2], af[mt][3], addr);
            }
            uint32_t bf[8][2];
#pragma unroll
            for (int np = 0; np < 4; np++) {
                const int row = wn * 64 + np * 16 + (g >> 1) * 8 + li;
                const uint32_t addr = bs_u[cur] +
                    (uint32_t)((row * GPITCH + kc0 + (g & 1) * 8) * 2);
                ldsm_x4(bf[2 * np][0], bf[2 * np][1],
                        bf[2 * np + 1][0], bf[2 * np + 1][1], addr);
            }
#pragma unroll
            for (int nt = 0; nt < 8; nt++)
#pragma unroll
                for (int mt = 0; mt < 4; mt++)
                    mma_f16(acc[mt][nt], af[mt][0], af[mt][1], af[mt][2], af[mt][3],
                            bf[nt][0], bf[nt][1]);
        }

        if (kb + 2 < NKB) { GEMM_STAGE((kb + 2) % 3, kb + 2); CP_COMMIT(); }
    }

    // epilogue
#pragma unroll
    for (int mt = 0; mt < 4; mt++) {
        const int r0 = m0 + wm * 64 + mt * 16 + fr;
#pragma unroll
        for (int nt = 0; nt < 8; nt++) {
            const int col = n0 + wn * 64 + nt * 8 + fc * 2;
            if (mode == 0) {
                __half* O = (__half*)Optr;
                const int h = col >> 6, d = col & 63;
#pragma unroll
                for (int half_ = 0; half_ < 2; half_++) {
                    const int m  = r0 + half_ * 8;
                    const int b  = m >> 11;
                    const int nq = m & (SEQ - 1);
                    __half2 o = __floats2half2_rn(acc[mt][nt][half_ * 2],
                                                  acc[mt][nt][half_ * 2 + 1]);
                    *(__half2*)&O[(((size_t)b * NUM_HEADS + h) * SEQ + nq) * HEAD_DIM + d] = o;
                }
            } else {
                float* O = (float*)Optr;
                const float b0 = bo[col], b1 = bo[col + 1];
#pragma unroll
                for (int half_ = 0; half_ < 2; half_++) {
                    const int m = r0 + half_ * 8;
                    float2 o = make_float2(acc[mt][nt][half_ * 2] + b0,
                                           acc[mt][nt][half_ * 2 + 1] + b1);
                    *(float2*)&O[(size_t)m * D_MODEL + col] = o;
                }
            }
        }
    }
#undef GEMM_STAGE
}

__global__ __launch_bounds__(128)
void proj_kernel()
{
    const int z = blockIdx.z;
    const __half* A = (z == 0) ? r_q  : ((z == 1) ? r_k  : r_v);
    const __half* W = (z == 0) ? r_wq : ((z == 1) ? r_wk : r_wv);
    __half*       O = (z == 0) ? g_q  : ((z == 1) ? g_k  : g_v);
    gemm_f16_body(A, W, O, nullptr, blockIdx.y * GBM, blockIdx.x * GBN, 0);
}

__global__ __launch_bounds__(128)
void out_kernel(const float* __restrict__ bo, float* __restrict__ Cout)
{
    gemm_f16_body(g_ctx, r_wo, Cout, bo, blockIdx.y * GBM, blockIdx.x * GBN, 1);
}

// ---------------------------------------------------------------------------
// Flash attention (unchanged from R11): fp16 mma, fp32 accum, log2-domain
// softmax via h2exp2, 4 warps x 32 q-rows, P in registers, V via ldsm.trans.
// ---------------------------------------------------------------------------
#define QT 128
#define KT 64
#define NT (SEQ / KT)
#define PS 72
#define ABUF (KT * PS)
#define ATTN_SMEM ((QT * PS + 4 * ABUF) * 2)   // 55296 B

__global__ __launch_bounds__(128)
void attn_kernel()
{
    extern __shared__ __align__(16) __half asm_[];

    const int t    = threadIdx.x;
    const int lane = t & 31;
    const int w    = t >> 5;
    const int g    = lane >> 3;
    const int li   = lane & 7;

    const uint32_t qs_u  = smem_to_u32(asm_);
    const uint32_t ksb_u = qs_u + QT * PS * 2;
    const uint32_t vsb_u = ksb_u + 2 * ABUF * 2;

    const int q0 = blockIdx.x * QT;
    const int bh = blockIdx.y;
    const __half* qb = g_q + (size_t)bh * SEQ * HEAD_DIM;
    const __half* kb = g_k + (size_t)bh * SEQ * HEAD_DIM;
    const __half* vb = g_v + (size_t)bh * SEQ * HEAD_DIM;

    const int crow = t >> 3;
    const int cc8  = (t & 7) * 8;

#pragma unroll
    for (int u = 0; u < 8; u++) {
        const int row = crow + 16 * u;
        cp16(qs_u + (uint32_t)((row * PS + cc8) * 2),
             qb + (size_t)(q0 + row) * HEAD_DIM + cc8);
    }
#pragma unroll
    for (int u = 0; u < 4; u++) {
        const int row = crow + 16 * u;
        cp16(ksb_u + (uint32_t)((row * PS + cc8) * 2),
             kb + (size_t)row * HEAD_DIM + cc8);
        cp16(vsb_u + (uint32_t)((row * PS + cc8) * 2),
             vb + (size_t)row * HEAD_DIM + cc8);
    }
    CP_COMMIT();
    CP_WAIT(0);
    __syncthreads();

    uint32_t qa[2][4][4];
#pragma unroll
    for (int mt = 0; mt < 2; mt++)
#pragma unroll
        for (int ks = 0; ks < 4; ks++) {
            const int row = w * 32 + mt * 16 + (g & 1) * 8 + li;
            const uint32_t addr = qs_u +
                (uint32_t)((row * PS + ks * 16 + (g >> 1) * 8) * 2);
            ldsm_x4(qa[mt][ks][0], qa[mt][ks][1], qa[mt][ks][2], qa[mt][ks][3], addr);
        }

    float o[2][8][4];
    float m_[2][2], l_[2][2];
#pragma unroll
    for (int mt = 0; mt < 2; mt++) {
        m_[mt][0] = -1e30f; m_[mt][1] = -1e30f;
        l_[mt][0] = 0.f;    l_[mt][1] = 0.f;
#pragma unroll
        for (int nt = 0; nt < 8; nt++)
#pragma unroll
            for (int r = 0; r < 4; r++) o[mt][nt][r] = 0.f;
    }

    for (int kt = 0; kt < NT; kt++) {
        const int cur = kt & 1;
        const bool more = (kt + 1 < NT);
        const uint32_t ks_u = ksb_u + (uint32_t)(cur * ABUF * 2);
        const uint32_t vs_u = vsb_u + (uint32_t)(cur * ABUF * 2);

        if (more) {
            const int j0 = (kt + 1) * KT;
            const uint32_t kdst = ksb_u + (uint32_t)((cur ^ 1) * ABUF * 2);
            const uint32_t vdst = vsb_u + (uint32_t)((cur ^ 1) * ABUF * 2);
#pragma unroll
            for (int u = 0; u < 4; u++) {
                const int row = crow + 16 * u;
                cp16(kdst + (uint32_t)((row * PS + cc8) * 2),
                     kb + (size_t)(j0 + row) * HEAD_DIM + cc8);
                cp16(vdst + (uint32_t)((row * PS + cc8) * 2),
                     vb + (size_t)(j0 + row) * HEAD_DIM + cc8);
            }
            CP_COMMIT();
        }

        float s[2][8][4];
#pragma unroll
        for (int mt = 0; mt < 2; mt++)
#pragma unroll
            for (int nt = 0; nt < 8; nt++)
#pragma unroll
                for (int r = 0; r < 4; r++) s[mt][nt][r] = 0.f;

#pragma unroll
        for (int ks = 0; ks < 4; ks++) {
            const int kc0 = ks * 16;
            uint32_t bf[8][2];
#pragma unroll
            for (int np = 0; np < 4; np++) {
                const int row = np * 16 + (g >> 1) * 8 + li;
                const uint32_t addr = ks_u + (uint32_t)((row * PS + kc0 + (g & 1) * 8) * 2);
                ldsm_x4(bf[2 * np][0], bf[2 * np][1],
                        bf[2 * np + 1][0], bf[2 * np + 1][1], addr);
            }
#pragma unroll
            for (int nt = 0; nt < 8; nt++) {
                mma_f16(s[0][nt], qa[0][ks][0], qa[0][ks][1], qa[0][ks][2], qa[0][ks][3],
                        bf[nt][0], bf[nt][1]);
                mma_f16(s[1][nt], qa[1][ks][0], qa[1][ks][1], qa[1][ks][2], qa[1][ks][3],
                        bf[nt][0], bf[nt][1]);
            }
        }

        uint32_t pa[2][4][4];
#pragma unroll
        for (int mt = 0; mt < 2; mt++) {
            float rm0 = -1e30f, rm1 = -1e30f;
#pragma unroll
            for (int nt = 0; nt < 8; nt++) {
                rm0 = fmaxf(rm0, fmaxf(s[mt][nt][0], s[mt][nt][1]));
                rm1 = fmaxf(rm1, fmaxf(s[mt][nt][2], s[mt][nt][3]));
            }
            rm0 = fmaxf(rm0, __shfl_xor_sync(0xffffffffu, rm0, 1));
            rm0 = fmaxf(rm0, __shfl_xor_sync(0xffffffffu, rm0, 2));
            rm1 = fmaxf(rm1, __shfl_xor_sync(0xffffffffu, rm1, 1));
            rm1 = fmaxf(rm1, __shfl_xor_sync(0xffffffffu, rm1, 2));

            const float mn0 = fmaxf(m_[mt][0], rm0);
            const float mn1 = fmaxf(m_[mt][1], rm1);
            const float cr0 = exp2f(m_[mt][0] - mn0);
            const float cr1 = exp2f(m_[mt][1] - mn1);
            m_[mt][0] = mn0; m_[mt][1] = mn1;

            float rs0 = 0.f, rs1 = 0.f;
#pragma unroll
            for (int nt = 0; nt < 8; nt++) {
                __half2 a01 = __floats2half2_rn(s[mt][nt][0] - mn0, s[mt][nt][1] - mn0);
                __half2 a23 = __floats2half2_rn(s[mt][nt][2] - mn1, s[mt][nt][3] - mn1);
                __half2 p01 = h2exp2(a01);
                __half2 p23 = h2exp2(a23);
                pa[mt][nt >> 1][(nt & 1) * 2 + 0] = *(uint32_t*)&p01;
                pa[mt][nt >> 1][(nt & 1) * 2 + 1] = *(uint32_t*)&p23;
                float2 f01 = __half22float2(p01);
                float2 f23 = __half22float2(p23);
                rs0 += f01.x + f01.y;
                rs1 += f23.x + f23.y;
            }
            rs0 += __shfl_xor_sync(0xffffffffu, rs0, 1);
            rs0 += __shfl_xor_sync(0xffffffffu, rs0, 2);
            rs1 += __shfl_xor_sync(0xffffffffu, rs1, 1);
            rs1 += __shfl_xor_sync(0xffffffffu, rs1, 2);
            l_[mt][0] = l_[mt][0] * cr0 + rs0;
            l_[mt][1] = l_[mt][1] * cr1 + rs1;

#pragma unroll
            for (int nt = 0; nt < 8; nt++) {
                o[mt][nt][0] *= cr0; o[mt][nt][1] *= cr0;
                o[mt][nt][2] *= cr1; o[mt][nt][3] *= cr1;
            }
        }

#pragma unroll
        for (int ks = 0; ks < 4; ks++) {
            const int kc0 = ks * 16;
            uint32_t bf[8][2];
#pragma unroll
            for (int np = 0; np < 4; np++) {
                const int row = kc0 + (g & 1) * 8 + li;
                const int col = np * 16 + (g >> 1) * 8;
                const uint32_t addr = vs_u + (uint32_t)((row * PS + col) * 2);
                ldsm_x4_t(bf[2 * np][0], bf[2 * np][1],
                          bf[2 * np + 1][0], bf[2 * np + 1][1], addr);
            }
#pragma unroll
            for (int nt = 0; nt < 8; nt++) {
                mma_f16(o[0][nt], pa[0][ks][0], pa[0][ks][1], pa[0][ks][2], pa[0][ks][3],
                        bf[nt][0], bf[nt][1]);
                mma_f16(o[1][nt], pa[1][ks][0], pa[1][ks][1], pa[1][ks][2], pa[1][ks][3],
                        bf[nt][0], bf[nt][1]);
            }
        }

        if (more) { CP_WAIT(0); }
        __syncthreads();
    }

    const int fr = lane >> 2;
    const int fc = lane & 3;
    const int b = bh >> 4;
    const int h = bh & 15;
#pragma unroll
    for (int mt = 0; mt < 2; mt++) {
        const float inv0 = 1.f / l_[mt][0];
        const float inv1 = 1.f / l_[mt][1];
        const int r0 = q0 + w * 32 + mt * 16 + fr;
#pragma unroll
        for (int nt = 0; nt < 8; nt++) {
            const int dv = nt * 8 + fc * 2;
            __half* base0 = &g_ctx[((size_t)b * SEQ + r0) * D_MODEL + h * HEAD_DIM + dv];
            __half* base1 = &g_ctx[((size_t)b * SEQ + r0 + 8) * D_MODEL + h * HEAD_DIM + dv];
            *(__half2*)base0 = __floats2half2_rn(o[mt][nt][0] * inv0, o[mt][nt][1] * inv0);
            *(__half2*)base1 = __floats2half2_rn(o[mt][nt][2] * inv1, o[mt][nt][3] * inv1);
        }
    }
}

// ---------------------------------------------------------------------------
// kernel_launch
// ---------------------------------------------------------------------------
extern "C" void kernel_launch(void* const* d_in, const int* in_sizes, int n_in,
                              void* d_out, int out_size)
{
    const float* query = (const float*)d_in[0];
    const float* key   = (const float*)d_in[1];
    const float* value = (const float*)d_in[2];
    const float* Wq    = (const float*)d_in[3];
    const float* Wk    = (const float*)d_in[4];
    const float* Wv    = (const float*)d_in[5];
    const float* Wo    = (const float*)d_in[6];
    const float* bo    = (const float*)d_in[7];
    float* out = (float*)d_out;

    __half *p_rq, *p_rk, *p_rv, *p_wq, *p_wk, *p_wv, *p_wo;
    cudaGetSymbolAddress((void**)&p_rq, r_q);
    cudaGetSymbolAddress((void**)&p_rk, r_k);
    cudaGetSymbolAddress((void**)&p_rv, r_v);
    cudaGetSymbolAddress((void**)&p_wq, r_wq);
    cudaGetSymbolAddress((void**)&p_wk, r_wk);
    cudaGetSymbolAddress((void**)&p_wv, r_wv);
    cudaGetSymbolAddress((void**)&p_wo, r_wo);

    const int n4_in = M_TOT * D_MODEL / 4;
    const int n4_w  = D_MODEL * D_MODEL / 4;

    PrepArgs pa;
    pa.src[0] = query; pa.dst[0] = p_rq; pa.n4[0] = n4_in; pa.scale[0] = 1.f;
    pa.src[1] = key;   pa.dst[1] = p_rk; pa.n4[1] = n4_in; pa.scale[1] = 1.f;
    pa.src[2] = value; pa.dst[2] = p_rv; pa.n4[2] = n4_in; pa.scale[2] = 1.f;
    pa.src[3] = Wq;    pa.dst[3] = p_wq; pa.n4[3] = n4_w;  pa.scale[3] = ATT_SCALE * LOG2E;
    pa.src[4] = Wk;    pa.dst[4] = p_wk; pa.n4[4] = n4_w;  pa.scale[4] = 1.f;
    pa.src[5] = Wv;    pa.dst[5] = p_wv; pa.n4[5] = n4_w;  pa.scale[5] = 1.f;
    pa.src[6] = Wo;    pa.dst[6] = p_wo; pa.n4[6] = n4_w;  pa.scale[6] = 1.f;

    prep_all_kernel<<<dim3(160, 7), 256>>>(pa);

    cudaFuncSetAttribute(proj_kernel, cudaFuncAttributeMaxDynamicSharedMemorySize, GEMM_SMEM);
    cudaFuncSetAttribute(out_kernel,  cudaFuncAttributeMaxDynamicSharedMemorySize, GEMM_SMEM);
    cudaFuncSetAttribute(attn_kernel, cudaFuncAttributeMaxDynamicSharedMemorySize, ATTN_SMEM);

    proj_kernel<<<dim3(D_MODEL / GBN, M_TOT / GBM, 3), 128, GEMM_SMEM>>>();

    attn_kernel<<<dim3(SEQ / QT, BATCH * NUM_HEADS), 128, ATTN_SMEM>>>();

    out_kernel<<<dim3(D_MODEL / GBN, M_TOT / GBM), 128, GEMM_SMEM>>>(bo, out);
}

// round 14
// speedup vs baseline: 7.0814x; 1.0136x over previous
#include <cuda_runtime.h>
#include <cuda_fp16.h>
#include <cstdint>
#include <math.h>

// Problem constants
#define D_MODEL   1024
#define NUM_HEADS 16
#define HEAD_DIM  64
#define BATCH     2
#define SEQ       2048
#define M_TOT     (BATCH * SEQ)
#define ATT_SCALE 0.125f
#define LOG2E     1.4426950408889634f

// ---------------------------------------------------------------------------
// Scratch (device globals: allocation-free per harness rules)
// ---------------------------------------------------------------------------
__device__ __half g_q[BATCH * NUM_HEADS * SEQ * HEAD_DIM];  // fp16, 0.125*log2e folded
__device__ __half g_k[BATCH * NUM_HEADS * SEQ * HEAD_DIM];
__device__ __half g_v[BATCH * NUM_HEADS * SEQ * HEAD_DIM];
__device__ __half g_ctx[BATCH * SEQ * D_MODEL];             // [B,N,H*Dh] fp16

__device__ __half r_q[M_TOT * D_MODEL];
__device__ __half r_k[M_TOT * D_MODEL];
__device__ __half r_v[M_TOT * D_MODEL];
__device__ __half r_wq[D_MODEL * D_MODEL];
__device__ __half r_wk[D_MODEL * D_MODEL];
__device__ __half r_wv[D_MODEL * D_MODEL];
__device__ __half r_wo[D_MODEL * D_MODEL];

// ---------------------------------------------------------------------------
// helpers
// ---------------------------------------------------------------------------
__device__ __forceinline__ uint32_t smem_to_u32(const void* p) {
    uint32_t a;
    asm("{ .reg .u64 t; cvta.to.shared.u64 t, %1; cvt.u32.u64 %0, t; }" : "=r"(a) : "l"(p));
    return a;
}

__device__ __forceinline__ void mma_f16(float* c,
                                        uint32_t a0, uint32_t a1, uint32_t a2, uint32_t a3,
                                        uint32_t b0, uint32_t b1)
{
    asm volatile(
        "mma.sync.aligned.m16n8k16.row.col.f32.f16.f16.f32 "
        "{%0,%1,%2,%3}, {%4,%5,%6,%7}, {%8,%9}, {%0,%1,%2,%3};\n"
        : "+f"(c[0]), "+f"(c[1]), "+f"(c[2]), "+f"(c[3])
        : "r"(a0), "r"(a1), "r"(a2), "r"(a3), "r"(b0), "r"(b1));
}

__device__ __forceinline__ void ldsm_x4(uint32_t& d0, uint32_t& d1,
                                        uint32_t& d2, uint32_t& d3, uint32_t addr)
{
    asm volatile("ldmatrix.sync.aligned.m8n8.x4.shared.b16 {%0,%1,%2,%3}, [%4];"
                 : "=r"(d0), "=r"(d1), "=r"(d2), "=r"(d3) : "r"(addr));
}

__device__ __forceinline__ void ldsm_x4_t(uint32_t& d0, uint32_t& d1,
                                          uint32_t& d2, uint32_t& d3, uint32_t addr)
{
    asm volatile("ldmatrix.sync.aligned.m8n8.x4.trans.shared.b16 {%0,%1,%2,%3}, [%4];"
                 : "=r"(d0), "=r"(d1), "=r"(d2), "=r"(d3) : "r"(addr));
}

__device__ __forceinline__ void cp16(uint32_t dst, const void* src) {
    asm volatile("cp.async.cg.shared.global [%0], [%1], 16;" :: "r"(dst), "l"(src));
}
#define CP_COMMIT() asm volatile("cp.async.commit_group;" ::: "memory")
#define CP_WAIT(n)  asm volatile("cp.async.wait_group %0;" :: "n"(n) : "memory")

__device__ __forceinline__ uint32_t pack_h2(float a, float b) {
    __half2 h = __floats2half2_rn(a, b);
    return *(uint32_t*)&h;
}

// ---------------------------------------------------------------------------
// prep (single launch)
// ---------------------------------------------------------------------------
struct PrepArgs {
    const float* src[7];
    __half*      dst[7];
    int          n4[7];
    float        scale[7];
};

__global__ __launch_bounds__(256)
void prep_all_kernel(PrepArgs a)
{
    const int seg = blockIdx.y;
    const float* __restrict__ s = a.src[seg];
    __half* __restrict__ d = a.dst[seg];
    const int n4 = a.n4[seg];
    const float sc = a.scale[seg];

    const int stride = gridDim.x * blockDim.x;
    for (int i = blockIdx.x * blockDim.x + threadIdx.x; i < n4; i += stride) {
        float4 v = ((const float4*)s)[i];
        uint2 o;
        o.x = pack_h2(v.x * sc, v.y * sc);
        o.y = pack_h2(v.z * sc, v.w * sc);
        ((uint2*)d)[i] = o;
    }
}

// ---------------------------------------------------------------------------
// fp16 MMA GEMM: C = A @ W^T. CTA 128x128x64(halves), 128 thr = 4 warps
// (2m x 2n), warp tile 64x64. 2-stage cp.async pipeline, ONE barrier per
// k-iter, 128 uninterrupted HMMAs per barrier interval per warp.
// ---------------------------------------------------------------------------
#define GBM 128
#define GBN 128
#define GBK 64                          // halves per k-chunk
#define GPITCH 72                       // 64 + 8 pad (144B rows, conflict-free)
#define GSTG (GBM * GPITCH)             // halves per stage per matrix
#define NKB (D_MODEL / GBK)             // 16
#define GEMM_SMEM (2 * GSTG * 2 * 2)    // 73728 B

__device__ __forceinline__ void gemm_f16_body(const __half* __restrict__ A,
                                              const __half* __restrict__ W,
                                              void* __restrict__ Optr,
                                              const float* __restrict__ bo,
                                              int m0, int n0, int mode)
{
    extern __shared__ __align__(16) __half gsm[];
    __half* As = gsm;                   // [2][GSTG]
    __half* Bs = gsm + 2 * GSTG;        // [2][GSTG]

    const int t    = threadIdx.x;       // 0..127
    const int lane = t & 31;
    const int wid  = t >> 5;            // 0..3
    const int wm   = wid & 1;           // 0..1
    const int wn   = wid >> 1;          // 0..1
    const int fr   = lane >> 2;
    const int fc   = lane & 3;
    const int g    = lane >> 3;
    const int li   = lane & 7;
    const int K    = D_MODEL;

    uint32_t as_u[2], bs_u[2];
#pragma unroll
    for (int s = 0; s < 2; s++) {
        as_u[s] = smem_to_u32(As + s * GSTG);
        bs_u[s] = smem_to_u32(Bs + s * GSTG);
    }

    float acc[4][8][4];
#pragma unroll
    for (int i = 0; i < 4; i++)
#pragma unroll
        for (int j = 0; j < 8; j++)
#pragma unroll
            for (int r = 0; r < 4; r++) acc[i][j][r] = 0.f;

    // staging: tile = 128 rows x 64 halves = 1024 x 16B chunks per matrix.
    // chunk i = t + 128u (u<8): row = i>>3, c8 = (i&7)*8
    const int srow = t >> 3;            // 0..15 (+16u)
    const int sc8  = (t & 7) * 8;

#define GEMM_STAGE(s, kb) do {                                                   \
        const int _k0 = (kb) * GBK;                                              \
        _Pragma("unroll")                                                        \
        for (int _u = 0; _u < 8; _u++) {                                         \
            const int _row = srow + 16 * _u;                                     \
            const uint32_t _so = (uint32_t)((_row * GPITCH + sc8) * 2);          \
            cp16(as_u[s] + _so, A + (size_t)(m0 + _row) * K + _k0 + sc8);        \
            cp16(bs_u[s] + _so, W + (size_t)(n0 + _row) * K + _k0 + sc8);        \
        }                                                                        \
    } while (0)

    // prologue: stage tile 0 into buffer 0
    GEMM_STAGE(0, 0); CP_COMMIT();

    for (int kb = 0; kb < NKB; kb++) {
        const int cur = kb & 1;
        // tile kb complete + all threads done computing from buffer cur^1
        CP_WAIT(0);
        __syncthreads();
        // stage tile kb+1 into the other buffer (its readers passed the barrier)
        if (kb + 1 < NKB) { GEMM_STAGE(cur ^ 1, kb + 1); CP_COMMIT(); }

#pragma unroll
        for (int ks = 0; ks < 4; ks++) {
            const int kc0 = ks * 16;
            uint32_t af[4][4];
#pragma unroll
            for (int mt = 0; mt < 4; mt++) {
                const int row = wm * 64 + mt * 16 + (g & 1) * 8 + li;
                const uint32_t addr = as_u[cur] +
                    (uint32_t)((row * GPITCH + kc0 + (g >> 1) * 8) * 2);
                ldsm_x4(af[mt][0], af[mt][1], af[mt][2], af[mt][3], addr);
            }
            uint32_t bf[8][2];
#pragma unroll
            for (int np = 0; np < 4; np++) {
                const int row = wn * 64 + np * 16 + (g >> 1) * 8 + li;
                const uint32_t addr = bs_u[cur] +
                    (uint32_t)((row * GPITCH + kc0 + (g & 1) * 8) * 2);
                ldsm_x4(bf[2 * np][0], bf[2 * np][1],
                        bf[2 * np + 1][0], bf[2 * np + 1][1], addr);
            }
#pragma unroll
            for (int nt = 0; nt < 8; nt++)
#pragma unroll
                for (int mt = 0; mt < 4; mt++)
                    mma_f16(acc[mt][nt], af[mt][0], af[mt][1], af[mt][2], af[mt][3],
                            bf[nt][0], bf[nt][1]);
        }
    }

    // epilogue
#pragma unroll
    for (int mt = 0; mt < 4; mt++) {
        const int r0 = m0 + wm * 64 + mt * 16 + fr;
#pragma unroll
        for (int nt = 0; nt < 8; nt++) {
            const int col = n0 + wn * 64 + nt * 8 + fc * 2;
            if (mode == 0) {
                __half* O = (__half*)Optr;
                const int h = col >> 6, d = col & 63;
#pragma unroll
                for (int half_ = 0; half_ < 2; half_++) {
                    const int m  = r0 + half_ * 8;
                    const int b  = m >> 11;
                    const int nq = m & (SEQ - 1);
                    __half2 o = __floats2half2_rn(acc[mt][nt][half_ * 2],
                                                  acc[mt][nt][half_ * 2 + 1]);
                    *(__half2*)&O[(((size_t)b * NUM_HEADS + h) * SEQ + nq) * HEAD_DIM + d] = o;
                }
            } else {
                float* O = (float*)Optr;
                const float b0 = bo[col], b1 = bo[col + 1];
#pragma unroll
                for (int half_ = 0; half_ < 2; half_++) {
                    const int m = r0 + half_ * 8;
                    float2 o = make_float2(acc[mt][nt][half_ * 2] + b0,
                                           acc[mt][nt][half_ * 2 + 1] + b1);
                    *(float2*)&O[(size_t)m * D_MODEL + col] = o;
                }
            }
        }
    }
#undef GEMM_STAGE
}

__global__ __launch_bounds__(128)
void proj_kernel()
{
    const int z = blockIdx.z;
    const __half* A = (z == 0) ? r_q  : ((z == 1) ? r_k  : r_v);
    const __half* W = (z == 0) ? r_wq : ((z == 1) ? r_wk : r_wv);
    __half*       O = (z == 0) ? g_q  : ((z == 1) ? g_k  : g_v);
    gemm_f16_body(A, W, O, nullptr, blockIdx.y * GBM, blockIdx.x * GBN, 0);
}

__global__ __launch_bounds__(128)
void out_kernel(const float* __restrict__ bo, float* __restrict__ Cout)
{
    gemm_f16_body(g_ctx, r_wo, Cout, bo, blockIdx.y * GBM, blockIdx.x * GBN, 1);
}

// ---------------------------------------------------------------------------
// Flash attention (unchanged from R12): fp16 mma, fp32 accum, log2-domain
// softmax via h2exp2, 4 warps x 32 q-rows, P in registers, V via ldsm.trans.
// ---------------------------------------------------------------------------
#define QT 128
#define KT 64
#define NT (SEQ / KT)
#define PS 72
#define ABUF (KT * PS)
#define ATTN_SMEM ((QT * PS + 4 * ABUF) * 2)   // 55296 B

__global__ __launch_bounds__(128)
void attn_kernel()
{
    extern __shared__ __align__(16) __half asm_[];

    const int t    = threadIdx.x;
    const int lane = t & 31;
    const int w    = t >> 5;
    const int g    = lane >> 3;
    const int li   = lane & 7;

    const uint32_t qs_u  = smem_to_u32(asm_);
    const uint32_t ksb_u = qs_u + QT * PS * 2;
    const uint32_t vsb_u = ksb_u + 2 * ABUF * 2;

    const int q0 = blockIdx.x * QT;
    const int bh = blockIdx.y;
    const __half* qb = g_q + (size_t)bh * SEQ * HEAD_DIM;
    const __half* kb = g_k + (size_t)bh * SEQ * HEAD_DIM;
    const __half* vb = g_v + (size_t)bh * SEQ * HEAD_DIM;

    const int crow = t >> 3;
    const int cc8  = (t & 7) * 8;

#pragma unroll
    for (int u = 0; u < 8; u++) {
        const int row = crow + 16 * u;
        cp16(qs_u + (uint32_t)((row * PS + cc8) * 2),
             qb + (size_t)(q0 + row) * HEAD_DIM + cc8);
    }
#pragma unroll
    for (int u = 0; u < 4; u++) {
        const int row = crow + 16 * u;
        cp16(ksb_u + (uint32_t)((row * PS + cc8) * 2),
             kb + (size_t)row * HEAD_DIM + cc8);
        cp16(vsb_u + (uint32_t)((row * PS + cc8) * 2),
             vb + (size_t)row * HEAD_DIM + cc8);
    }
    CP_COMMIT();
    CP_WAIT(0);
    __syncthreads();

    uint32_t qa[2][4][4];
#pragma unroll
    for (int mt = 0; mt < 2; mt++)
#pragma unroll
        for (int ks = 0; ks < 4; ks++) {
            const int row = w * 32 + mt * 16 + (g & 1) * 8 + li;
            const uint32_t addr = qs_u +
                (uint32_t)((row * PS + ks * 16 + (g >> 1) * 8) * 2);
            ldsm_x4(qa[mt][ks][0], qa[mt][ks][1], qa[mt][ks][2], qa[mt][ks][3], addr);
        }

    float o[2][8][4];
    float m_[2][2], l_[2][2];
#pragma unroll
    for (int mt = 0; mt < 2; mt++) {
        m_[mt][0] = -1e30f; m_[mt][1] = -1e30f;
        l_[mt][0] = 0.f;    l_[mt][1] = 0.f;
#pragma unroll
        for (int nt = 0; nt < 8; nt++)
#pragma unroll
            for (int r = 0; r < 4; r++) o[mt][nt][r] = 0.f;
    }

    for (int kt = 0; kt < NT; kt++) {
        const int cur = kt & 1;
        const bool more = (kt + 1 < NT);
        const uint32_t ks_u = ksb_u + (uint32_t)(cur * ABUF * 2);
        const uint32_t vs_u = vsb_u + (uint32_t)(cur * ABUF * 2);

        if (more) {
            const int j0 = (kt + 1) * KT;
            const uint32_t kdst = ksb_u + (uint32_t)((cur ^ 1) * ABUF * 2);
            const uint32_t vdst = vsb_u + (uint32_t)((cur ^ 1) * ABUF * 2);
#pragma unroll
            for (int u = 0; u < 4; u++) {
                const int row = crow + 16 * u;
                cp16(kdst + (uint32_t)((row * PS + cc8) * 2),
                     kb + (size_t)(j0 + row) * HEAD_DIM + cc8);
                cp16(vdst + (uint32_t)((row * PS + cc8) * 2),
                     vb + (size_t)(j0 + row) * HEAD_DIM + cc8);
            }
            CP_COMMIT();
        }

        float s[2][8][4];
#pragma unroll
        for (int mt = 0; mt < 2; mt++)
#pragma unroll
            for (int nt = 0; nt < 8; nt++)
#pragma unroll
                for (int r = 0; r < 4; r++) s[mt][nt][r] = 0.f;

#pragma unroll
        for (int ks = 0; ks < 4; ks++) {
            const int kc0 = ks * 16;
            uint32_t bf[8][2];
#pragma unroll
            for (int np = 0; np < 4; np++) {
                const int row = np * 16 + (g >> 1) * 8 + li;
                const uint32_t addr = ks_u + (uint32_t)((row * PS + kc0 + (g & 1) * 8) * 2);
                ldsm_x4(bf[2 * np][0], bf[2 * np][1],
                        bf[2 * np + 1][0], bf[2 * np + 1][1], addr);
            }
#pragma unroll
            for (int nt = 0; nt < 8; nt++) {
                mma_f16(s[0][nt], qa[0][ks][0], qa[0][ks][1], qa[0][ks][2], qa[0][ks][3],
                        bf[nt][0], bf[nt][1]);
                mma_f16(s[1][nt], qa[1][ks][0], qa[1][ks][1], qa[1][ks][2], qa[1][ks][3],
                        bf[nt][0], bf[nt][1]);
            }
        }

        uint32_t pa[2][4][4];
#pragma unroll
        for (int mt = 0; mt < 2; mt++) {
            float rm0 = -1e30f, rm1 = -1e30f;
#pragma unroll
            for (int nt = 0; nt < 8; nt++) {
                rm0 = fmaxf(rm0, fmaxf(s[mt][nt][0], s[mt][nt][1]));
                rm1 = fmaxf(rm1, fmaxf(s[mt][nt][2], s[mt][nt][3]));
            }
            rm0 = fmaxf(rm0, __shfl_xor_sync(0xffffffffu, rm0, 1));
            rm0 = fmaxf(rm0, __shfl_xor_sync(0xffffffffu, rm0, 2));
            rm1 = fmaxf(rm1, __shfl_xor_sync(0xffffffffu, rm1, 1));
            rm1 = fmaxf(rm1, __shfl_xor_sync(0xffffffffu, rm1, 2));

            const float mn0 = fmaxf(m_[mt][0], rm0);
            const float mn1 = fmaxf(m_[mt][1], rm1);
            const float cr0 = exp2f(m_[mt][0] - mn0);
            const float cr1 = exp2f(m_[mt][1] - mn1);
            m_[mt][0] = mn0; m_[mt][1] = mn1;

            float rs0 = 0.f, rs1 = 0.f;
#pragma unroll
            for (int nt = 0; nt < 8; nt++) {
                __half2 a01 = __floats2half2_rn(s[mt][nt][0] - mn0, s[mt][nt][1] - mn0);
                __half2 a23 = __floats2half2_rn(s[mt][nt][2] - mn1, s[mt][nt][3] - mn1);
                __half2 p01 = h2exp2(a01);
                __half2 p23 = h2exp2(a23);
                pa[mt][nt >> 1][(nt & 1) * 2 + 0] = *(uint32_t*)&p01;
                pa[mt][nt >> 1][(nt & 1) * 2 + 1] = *(uint32_t*)&p23;
                float2 f01 = __half22float2(p01);
                float2 f23 = __half22float2(p23);
                rs0 += f01.x + f01.y;
                rs1 += f23.x + f23.y;
            }
            rs0 += __shfl_xor_sync(0xffffffffu, rs0, 1);
            rs0 += __shfl_xor_sync(0xffffffffu, rs0, 2);
            rs1 += __shfl_xor_sync(0xffffffffu, rs1, 1);
            rs1 += __shfl_xor_sync(0xffffffffu, rs1, 2);
            l_[mt][0] = l_[mt][0] * cr0 + rs0;
            l_[mt][1] = l_[mt][1] * cr1 + rs1;

#pragma unroll
            for (int nt = 0; nt < 8; nt++) {
                o[mt][nt][0] *= cr0; o[mt][nt][1] *= cr0;
                o[mt][nt][2] *= cr1; o[mt][nt][3] *= cr1;
            }
        }

#pragma unroll
        for (int ks = 0; ks < 4; ks++) {
            const int kc0 = ks * 16;
            uint32_t bf[8][2];
#pragma unroll
            for (int np = 0; np < 4; np++) {
                const int row = kc0 + (g & 1) * 8 + li;
                const int col = np * 16 + (g >> 1) * 8;
                const uint32_t addr = vs_u + (uint32_t)((row * PS + col) * 2);
                ldsm_x4_t(bf[2 * np][0], bf[2 * np][1],
                          bf[2 * np + 1][0], bf[2 * np + 1][1], addr);
            }
#pragma unroll
            for (int nt = 0; nt < 8; nt++) {
                mma_f16(o[0][nt], pa[0][ks][0], pa[0][ks][1], pa[0][ks][2], pa[0][ks][3],
                        bf[nt][0], bf[nt][1]);
                mma_f16(o[1][nt], pa[1][ks][0], pa[1][ks][1], pa[1][ks][2], pa[1][ks][3],
                        bf[nt][0], bf[nt][1]);
            }
        }

        if (more) { CP_WAIT(0); }
        __syncthreads();
    }

    const int fr = lane >> 2;
    const int fc = lane & 3;
    const int b = bh >> 4;
    const int h = bh & 15;
#pragma unroll
    for (int mt = 0; mt < 2; mt++) {
        const float inv0 = 1.f / l_[mt][0];
        const float inv1 = 1.f / l_[mt][1];
        const int r0 = q0 + w * 32 + mt * 16 + fr;
#pragma unroll
        for (int nt = 0; nt < 8; nt++) {
            const int dv = nt * 8 + fc * 2;
            __half* base0 = &g_ctx[((size_t)b * SEQ + r0) * D_MODEL + h * HEAD_DIM + dv];
            __half* base1 = &g_ctx[((size_t)b * SEQ + r0 + 8) * D_MODEL + h * HEAD_DIM + dv];
            *(__half2*)base0 = __floats2half2_rn(o[mt][nt][0] * inv0, o[mt][nt][1] * inv0);
            *(__half2*)base1 = __floats2half2_rn(o[mt][nt][2] * inv1, o[mt][nt][3] * inv1);
        }
    }
}

// ---------------------------------------------------------------------------
// kernel_launch
// ---------------------------------------------------------------------------
extern "C" void kernel_launch(void* const* d_in, const int* in_sizes, int n_in,
                              void* d_out, int out_size)
{
    const float* query = (const float*)d_in[0];
    const float* key   = (const float*)d_in[1];
    const float* value = (const float*)d_in[2];
    const float* Wq    = (const float*)d_in[3];
    const float* Wk    = (const float*)d_in[4];
    const float* Wv    = (const float*)d_in[5];
    const float* Wo    = (const float*)d_in[6];
    const float* bo    = (const float*)d_in[7];
    float* out = (float*)d_out;

    __half *p_rq, *p_rk, *p_rv, *p_wq, *p_wk, *p_wv, *p_wo;
    cudaGetSymbolAddress((void**)&p_rq, r_q);
    cudaGetSymbolAddress((void**)&p_rk, r_k);
    cudaGetSymbolAddress((void**)&p_rv, r_v);
    cudaGetSymbolAddress((void**)&p_wq, r_wq);
    cudaGetSymbolAddress((void**)&p_wk, r_wk);
    cudaGetSymbolAddress((void**)&p_wv, r_wv);
    cudaGetSymbolAddress((void**)&p_wo, r_wo);

    const int n4_in = M_TOT * D_MODEL / 4;
    const int n4_w  = D_MODEL * D_MODEL / 4;

    PrepArgs pa;
    pa.src[0] = query; pa.dst[0] = p_rq; pa.n4[0] = n4_in; pa.scale[0] = 1.f;
    pa.src[1] = key;   pa.dst[1] = p_rk; pa.n4[1] = n4_in; pa.scale[1] = 1.f;
    pa.src[2] = value; pa.dst[2] = p_rv; pa.n4[2] = n4_in; pa.scale[2] = 1.f;
    pa.src[3] = Wq;    pa.dst[3] = p_wq; pa.n4[3] = n4_w;  pa.scale[3] = ATT_SCALE * LOG2E;
    pa.src[4] = Wk;    pa.dst[4] = p_wk; pa.n4[4] = n4_w;  pa.scale[4] = 1.f;
    pa.src[5] = Wv;    pa.dst[5] = p_wv; pa.n4[5] = n4_w;  pa.scale[5] = 1.f;
    pa.src[6] = Wo;    pa.dst[6] = p_wo; pa.n4[6] = n4_w;  pa.scale[6] = 1.f;

    prep_all_kernel<<<dim3(160, 7), 256>>>(pa);

    cudaFuncSetAttribute(proj_kernel, cudaFuncAttributeMaxDynamicSharedMemorySize, GEMM_SMEM);
    cudaFuncSetAttribute(out_kernel,  cudaFuncAttributeMaxDynamicSharedMemorySize, GEMM_SMEM);
    cudaFuncSetAttribute(attn_kernel, cudaFuncAttributeMaxDynamicSharedMemorySize, ATTN_SMEM);

    proj_kernel<<<dim3(D_MODEL / GBN, M_TOT / GBM, 3), 128, GEMM_SMEM>>>();

    attn_kernel<<<dim3(SEQ / QT, BATCH * NUM_HEADS), 128, ATTN_SMEM>>>();

    out_kernel<<<dim3(D_MODEL / GBN, M_TOT / GBM), 128, GEMM_SMEM>>>(bo, out);
}

// round 15
// speedup vs baseline: 7.2464x; 1.0233x over previous
#include <cuda_runtime.h>
#include <cuda_fp16.h>
#include <cstdint>
#include <math.h>

// Problem constants
#define D_MODEL   1024
#define NUM_HEADS 16
#define HEAD_DIM  64
#define BATCH     2
#define SEQ       2048
#define M_TOT     (BATCH * SEQ)
#define ATT_SCALE 0.125f
#define LOG2E     1.4426950408889634f

// ---------------------------------------------------------------------------
// Scratch (device globals: allocation-free per harness rules)
// ---------------------------------------------------------------------------
__device__ __half g_q[BATCH * NUM_HEADS * SEQ * HEAD_DIM];  // fp16, 0.125*log2e folded
__device__ __half g_k[BATCH * NUM_HEADS * SEQ * HEAD_DIM];
__device__ __half g_v[BATCH * NUM_HEADS * SEQ * HEAD_DIM];
__device__ __half g_ctx[BATCH * SEQ * D_MODEL];             // [B,N,H*Dh] fp16

__device__ __half r_q[M_TOT * D_MODEL];
__device__ __half r_k[M_TOT * D_MODEL];
__device__ __half r_v[M_TOT * D_MODEL];
__device__ __half r_wq[D_MODEL * D_MODEL];
__device__ __half r_wk[D_MODEL * D_MODEL];
__device__ __half r_wv[D_MODEL * D_MODEL];
__device__ __half r_wo[D_MODEL * D_MODEL];

// ---------------------------------------------------------------------------
// helpers
// ---------------------------------------------------------------------------
__device__ __forceinline__ uint32_t smem_to_u32(const void* p) {
    uint32_t a;
    asm("{ .reg .u64 t; cvta.to.shared.u64 t, %1; cvt.u32.u64 %0, t; }" : "=r"(a) : "l"(p));
    return a;
}

__device__ __forceinline__ void mma_f16(float* c,
                                        uint32_t a0, uint32_t a1, uint32_t a2, uint32_t a3,
                                        uint32_t b0, uint32_t b1)
{
    asm volatile(
        "mma.sync.aligned.m16n8k16.row.col.f32.f16.f16.f32 "
        "{%0,%1,%2,%3}, {%4,%5,%6,%7}, {%8,%9}, {%0,%1,%2,%3};\n"
        : "+f"(c[0]), "+f"(c[1]), "+f"(c[2]), "+f"(c[3])
        : "r"(a0), "r"(a1), "r"(a2), "r"(a3), "r"(b0), "r"(b1));
}

__device__ __forceinline__ void ldsm_x4(uint32_t& d0, uint32_t& d1,
                                        uint32_t& d2, uint32_t& d3, uint32_t addr)
{
    asm volatile("ldmatrix.sync.aligned.m8n8.x4.shared.b16 {%0,%1,%2,%3}, [%4];"
                 : "=r"(d0), "=r"(d1), "=r"(d2), "=r"(d3) : "r"(addr));
}

__device__ __forceinline__ void ldsm_x4_t(uint32_t& d0, uint32_t& d1,
                                          uint32_t& d2, uint32_t& d3, uint32_t addr)
{
    asm volatile("ldmatrix.sync.aligned.m8n8.x4.trans.shared.b16 {%0,%1,%2,%3}, [%4];"
                 : "=r"(d0), "=r"(d1), "=r"(d2), "=r"(d3) : "r"(addr));
}

__device__ __forceinline__ void cp16(uint32_t dst, const void* src) {
    asm volatile("cp.async.cg.shared.global [%0], [%1], 16;" :: "r"(dst), "l"(src));
}
#define CP_COMMIT() asm volatile("cp.async.commit_group;" ::: "memory")
#define CP_WAIT(n)  asm volatile("cp.async.wait_group %0;" :: "n"(n) : "memory")

__device__ __forceinline__ uint32_t pack_h2(float a, float b) {
    __half2 h = __floats2half2_rn(a, b);
    return *(uint32_t*)&h;
}

// ---------------------------------------------------------------------------
// prep (single launch)
// ---------------------------------------------------------------------------
struct PrepArgs {
    const float* src[7];
    __half*      dst[7];
    int          n4[7];
    float        scale[7];
};

__global__ __launch_bounds__(256)
void prep_all_kernel(PrepArgs a)
{
    const int seg = blockIdx.y;
    const float* __restrict__ s = a.src[seg];
    __half* __restrict__ d = a.dst[seg];
    const int n4 = a.n4[seg];
    const float sc = a.scale[seg];

    const int stride = gridDim.x * blockDim.x;
    for (int i = blockIdx.x * blockDim.x + threadIdx.x; i < n4; i += stride) {
        float4 v = ((const float4*)s)[i];
        uint2 o;
        o.x = pack_h2(v.x * sc, v.y * sc);
        o.y = pack_h2(v.z * sc, v.w * sc);
        ((uint2*)d)[i] = o;
    }
}

// ---------------------------------------------------------------------------
// fp16 MMA GEMM: C = A @ W^T. CTA 128x128x64(halves), 128 thr = 4 warps
// (2m x 2n), warp tile 64x64. 2-stage cp.async pipeline, ONE barrier per
// k-iter. __launch_bounds__(128,3): 3 CTAs/SM (regs<=170, smem 3x72KB fits).
// ---------------------------------------------------------------------------
#define GBM 128
#define GBN 128
#define GBK 64                          // halves per k-chunk
#define GPITCH 72                       // 64 + 8 pad (144B rows, conflict-free)
#define GSTG (GBM * GPITCH)             // halves per stage per matrix
#define NKB (D_MODEL / GBK)             // 16
#define GEMM_SMEM (2 * GSTG * 2 * 2)    // 73728 B

__device__ __forceinline__ void gemm_f16_body(const __half* __restrict__ A,
                                              const __half* __restrict__ W,
                                              void* __restrict__ Optr,
                                              const float* __restrict__ bo,
                                              int m0, int n0, int mode)
{
    extern __shared__ __align__(16) __half gsm[];
    __half* As = gsm;                   // [2][GSTG]
    __half* Bs = gsm + 2 * GSTG;        // [2][GSTG]

    const int t    = threadIdx.x;       // 0..127
    const int lane = t & 31;
    const int wid  = t >> 5;            // 0..3
    const int wm   = wid & 1;           // 0..1
    const int wn   = wid >> 1;          // 0..1
    const int fr   = lane >> 2;
    const int fc   = lane & 3;
    const int g    = lane >> 3;
    const int li   = lane & 7;
    const int K    = D_MODEL;

    uint32_t as_u[2], bs_u[2];
#pragma unroll
    for (int s = 0; s < 2; s++) {
        as_u[s] = smem_to_u32(As + s * GSTG);
        bs_u[s] = smem_to_u32(Bs + s * GSTG);
    }

    float acc[4][8][4];
#pragma unroll
    for (int i = 0; i < 4; i++)
#pragma unroll
        for (int j = 0; j < 8; j++)
#pragma unroll
            for (int r = 0; r < 4; r++) acc[i][j][r] = 0.f;

    // staging: tile = 128 rows x 64 halves = 1024 x 16B chunks per matrix.
    const int srow = t >> 3;            // 0..15 (+16u)
    const int sc8  = (t & 7) * 8;

#define GEMM_STAGE(s, kb) do {                                                   \
        const int _k0 = (kb) * GBK;                                              \
        _Pragma("unroll")                                                        \
        for (int _u = 0; _u < 8; _u++) {                                         \
            const int _row = srow + 16 * _u;                                     \
            const uint32_t _so = (uint32_t)((_row * GPITCH + sc8) * 2);          \
            cp16(as_u[s] + _so, A + (size_t)(m0 + _row) * K + _k0 + sc8);        \
            cp16(bs_u[s] + _so, W + (size_t)(n0 + _row) * K + _k0 + sc8);        \
        }                                                                        \
    } while (0)

    GEMM_STAGE(0, 0); CP_COMMIT();

    for (int kb = 0; kb < NKB; kb++) {
        const int cur = kb & 1;
        CP_WAIT(0);
        __syncthreads();
        if (kb + 1 < NKB) { GEMM_STAGE(cur ^ 1, kb + 1); CP_COMMIT(); }

#pragma unroll
        for (int ks = 0; ks < 4; ks++) {
            const int kc0 = ks * 16;
            uint32_t af[4][4];
#pragma unroll
            for (int mt = 0; mt < 4; mt++) {
                const int row = wm * 64 + mt * 16 + (g & 1) * 8 + li;
                const uint32_t addr = as_u[cur] +
                    (uint32_t)((row * GPITCH + kc0 + (g >> 1) * 8) * 2);
                ldsm_x4(af[mt][0], af[mt][1], af[mt][2], af[mt][3], addr);
            }
            uint32_t bf[8][2];
#pragma unroll
            for (int np = 0; np < 4; np++) {
                const int row = wn * 64 + np * 16 + (g >> 1) * 8 + li;
                const uint32_t addr = bs_u[cur] +
                    (uint32_t)((row * GPITCH + kc0 + (g & 1) * 8) * 2);
                ldsm_x4(bf[2 * np][0], bf[2 * np][1],
                        bf[2 * np + 1][0], bf[2 * np + 1][1], addr);
            }
#pragma unroll
            for (int nt = 0; nt < 8; nt++)
#pragma unroll
                for (int mt = 0; mt < 4; mt++)
                    mma_f16(acc[mt][nt], af[mt][0], af[mt][1], af[mt][2], af[mt][3],
                            bf[nt][0], bf[nt][1]);
        }
    }

    // epilogue
#pragma unroll
    for (int mt = 0; mt < 4; mt++) {
        const int r0 = m0 + wm * 64 + mt * 16 + fr;
#pragma unroll
        for (int nt = 0; nt < 8; nt++) {
            const int col = n0 + wn * 64 + nt * 8 + fc * 2;
            if (mode == 0) {
                __half* O = (__half*)Optr;
                const int h = col >> 6, d = col & 63;
#pragma unroll
                for (int half_ = 0; half_ < 2; half_++) {
                    const int m  = r0 + half_ * 8;
                    const int b  = m >> 11;
                    const int nq = m & (SEQ - 1);
                    __half2 o = __floats2half2_rn(acc[mt][nt][half_ * 2],
                                                  acc[mt][nt][half_ * 2 + 1]);
                    *(__half2*)&O[(((size_t)b * NUM_HEADS + h) * SEQ + nq) * HEAD_DIM + d] = o;
                }
            } else {
                float* O = (float*)Optr;
                const float b0 = bo[col], b1 = bo[col + 1];
#pragma unroll
                for (int half_ = 0; half_ < 2; half_++) {
                    const int m = r0 + half_ * 8;
                    float2 o = make_float2(acc[mt][nt][half_ * 2] + b0,
                                           acc[mt][nt][half_ * 2 + 1] + b1);
                    *(float2*)&O[(size_t)m * D_MODEL + col] = o;
                }
            }
        }
    }
#undef GEMM_STAGE
}

__global__ __launch_bounds__(128, 3)
void proj_kernel()
{
    const int z = blockIdx.z;
    const __half* A = (z == 0) ? r_q  : ((z == 1) ? r_k  : r_v);
    const __half* W = (z == 0) ? r_wq : ((z == 1) ? r_wk : r_wv);
    __half*       O = (z == 0) ? g_q  : ((z == 1) ? g_k  : g_v);
    gemm_f16_body(A, W, O, nullptr, blockIdx.y * GBM, blockIdx.x * GBN, 0);
}

__global__ __launch_bounds__(128, 3)
void out_kernel(const float* __restrict__ bo, float* __restrict__ Cout)
{
    gemm_f16_body(g_ctx, r_wo, Cout, bo, blockIdx.y * GBM, blockIdx.x * GBN, 1);
}

// ---------------------------------------------------------------------------
// Flash attention (unchanged from R13): fp16 mma, fp32 accum, log2-domain
// softmax via h2exp2, 4 warps x 32 q-rows, P in registers, V via ldsm.trans.
// ---------------------------------------------------------------------------
#define QT 128
#define KT 64
#define NT (SEQ / KT)
#define PS 72
#define ABUF (KT * PS)
#define ATTN_SMEM ((QT * PS + 4 * ABUF) * 2)   // 55296 B

__global__ __launch_bounds__(128)
void attn_kernel()
{
    extern __shared__ __align__(16) __half asm_[];

    const int t    = threadIdx.x;
    const int lane = t & 31;
    const int w    = t >> 5;
    const int g    = lane >> 3;
    const int li   = lane & 7;

    const uint32_t qs_u  = smem_to_u32(asm_);
    const uint32_t ksb_u = qs_u + QT * PS * 2;
    const uint32_t vsb_u = ksb_u + 2 * ABUF * 2;

    const int q0 = blockIdx.x * QT;
    const int bh = blockIdx.y;
    const __half* qb = g_q + (size_t)bh * SEQ * HEAD_DIM;
    const __half* kb = g_k + (size_t)bh * SEQ * HEAD_DIM;
    const __half* vb = g_v + (size_t)bh * SEQ * HEAD_DIM;

    const int crow = t >> 3;
    const int cc8  = (t & 7) * 8;

#pragma unroll
    for (int u = 0; u < 8; u++) {
        const int row = crow + 16 * u;
        cp16(qs_u + (uint32_t)((row * PS + cc8) * 2),
             qb + (size_t)(q0 + row) * HEAD_DIM + cc8);
    }
#pragma unroll
    for (int u = 0; u < 4; u++) {
        const int row = crow + 16 * u;
        cp16(ksb_u + (uint32_t)((row * PS + cc8) * 2),
             kb + (size_t)row * HEAD_DIM + cc8);
        cp16(vsb_u + (uint32_t)((row * PS + cc8) * 2),
             vb + (size_t)row * HEAD_DIM + cc8);
    }
    CP_COMMIT();
    CP_WAIT(0);
    __syncthreads();

    uint32_t qa[2][4][4];
#pragma unroll
    for (int mt = 0; mt < 2; mt++)
#pragma unroll
        for (int ks = 0; ks < 4; ks++) {
            const int row = w * 32 + mt * 16 + (g & 1) * 8 + li;
            const uint32_t addr = qs_u +
                (uint32_t)((row * PS + ks * 16 + (g >> 1) * 8) * 2);
            ldsm_x4(qa[mt][ks][0], qa[mt][ks][1], qa[mt][ks][2], qa[mt][ks][3], addr);
        }

    float o[2][8][4];
    float m_[2][2], l_[2][2];
#pragma unroll
    for (int mt = 0; mt < 2; mt++) {
        m_[mt][0] = -1e30f; m_[mt][1] = -1e30f;
        l_[mt][0] = 0.f;    l_[mt][1] = 0.f;
#pragma unroll
        for (int nt = 0; nt < 8; nt++)
#pragma unroll
            for (int r = 0; r < 4; r++) o[mt][nt][r] = 0.f;
    }

    for (int kt = 0; kt < NT; kt++) {
        const int cur = kt & 1;
        const bool more = (kt + 1 < NT);
        const uint32_t ks_u = ksb_u + (uint32_t)(cur * ABUF * 2);
        const uint32_t vs_u = vsb_u + (uint32_t)(cur * ABUF * 2);

        if (more) {
            const int j0 = (kt + 1) * KT;
            const uint32_t kdst = ksb_u + (uint32_t)((cur ^ 1) * ABUF * 2);
            const uint32_t vdst = vsb_u + (uint32_t)((cur ^ 1) * ABUF * 2);
#pragma unroll
            for (int u = 0; u < 4; u++) {
                const int row = crow + 16 * u;
                cp16(kdst + (uint32_t)((row * PS + cc8) * 2),
                     kb + (size_t)(j0 + row) * HEAD_DIM + cc8);
                cp16(vdst + (uint32_t)((row * PS + cc8) * 2),
                     vb + (size_t)(j0 + row) * HEAD_DIM + cc8);
            }
            CP_COMMIT();
        }

        float s[2][8][4];
#pragma unroll
        for (int mt = 0; mt < 2; mt++)
#pragma unroll
            for (int nt = 0; nt < 8; nt++)
#pragma unroll
                for (int r = 0; r < 4; r++) s[mt][nt][r] = 0.f;

#pragma unroll
        for (int ks = 0; ks < 4; ks++) {
            const int kc0 = ks * 16;
            uint32_t bf[8][2];
#pragma unroll
            for (int np = 0; np < 4; np++) {
                const int row = np * 16 + (g >> 1) * 8 + li;
                const uint32_t addr = ks_u + (uint32_t)((row * PS + kc0 + (g & 1) * 8) * 2);
                ldsm_x4(bf[2 * np][0], bf[2 * np][1],
                        bf[2 * np + 1][0], bf[2 * np + 1][1], addr);
            }
#pragma unroll
            for (int nt = 0; nt < 8; nt++) {
                mma_f16(s[0][nt], qa[0][ks][0], qa[0][ks][1], qa[0][ks][2], qa[0][ks][3],
                        bf[nt][0], bf[nt][1]);
                mma_f16(s[1][nt], qa[1][ks][0], qa[1][ks][1], qa[1][ks][2], qa[1][ks][3],
                        bf[nt][0], bf[nt][1]);
            }
        }

        uint32_t pa[2][4][4];
#pragma unroll
        for (int mt = 0; mt < 2; mt++) {
            float rm0 = -1e30f, rm1 = -1e30f;
#pragma unroll
            for (int nt = 0; nt < 8; nt++) {
                rm0 = fmaxf(rm0, fmaxf(s[mt][nt][0], s[mt][nt][1]));
                rm1 = fmaxf(rm1, fmaxf(s[mt][nt][2], s[mt][nt][3]));
            }
            rm0 = fmaxf(rm0, __shfl_xor_sync(0xffffffffu, rm0, 1));
            rm0 = fmaxf(rm0, __shfl_xor_sync(0xffffffffu, rm0, 2));
            rm1 = fmaxf(rm1, __shfl_xor_sync(0xffffffffu, rm1, 1));
            rm1 = fmaxf(rm1, __shfl_xor_sync(0xffffffffu, rm1, 2));

            const float mn0 = fmaxf(m_[mt][0], rm0);
            const float mn1 = fmaxf(m_[mt][1], rm1);
            const float cr0 = exp2f(m_[mt][0] - mn0);
            const float cr1 = exp2f(m_[mt][1] - mn1);
            m_[mt][0] = mn0; m_[mt][1] = mn1;

            float rs0 = 0.f, rs1 = 0.f;
#pragma unroll
            for (int nt = 0; nt < 8; nt++) {
                __half2 a01 = __floats2half2_rn(s[mt][nt][0] - mn0, s[mt][nt][1] - mn0);
                __half2 a23 = __floats2half2_rn(s[mt][nt][2] - mn1, s[mt][nt][3] - mn1);
                __half2 p01 = h2exp2(a01);
                __half2 p23 = h2exp2(a23);
                pa[mt][nt >> 1][(nt & 1) * 2 + 0] = *(uint32_t*)&p01;
                pa[mt][nt >> 1][(nt & 1) * 2 + 1] = *(uint32_t*)&p23;
                float2 f01 = __half22float2(p01);
                float2 f23 = __half22float2(p23);
                rs0 += f01.x + f01.y;
                rs1 += f23.x + f23.y;
            }
            rs0 += __shfl_xor_sync(0xffffffffu, rs0, 1);
            rs0 += __shfl_xor_sync(0xffffffffu, rs0, 2);
            rs1 += __shfl_xor_sync(0xffffffffu, rs1, 1);
            rs1 += __shfl_xor_sync(0xffffffffu, rs1, 2);
            l_[mt][0] = l_[mt][0] * cr0 + rs0;
            l_[mt][1] = l_[mt][1] * cr1 + rs1;

#pragma unroll
            for (int nt = 0; nt < 8; nt++) {
                o[mt][nt][0] *= cr0; o[mt][nt][1] *= cr0;
                o[mt][nt][2] *= cr1; o[mt][nt][3] *= cr1;
            }
        }

#pragma unroll
        for (int ks = 0; ks < 4; ks++) {
            const int kc0 = ks * 16;
            uint32_t bf[8][2];
#pragma unroll
            for (int np = 0; np < 4; np++) {
                const int row = kc0 + (g & 1) * 8 + li;
                const int col = np * 16 + (g >> 1) * 8;
                const uint32_t addr = vs_u + (uint32_t)((row * PS + col) * 2);
                ldsm_x4_t(bf[2 * np][0], bf[2 * np][1],
                          bf[2 * np + 1][0], bf[2 * np + 1][1], addr);
            }
#pragma unroll
            for (int nt = 0; nt < 8; nt++) {
                mma_f16(o[0][nt], pa[0][ks][0], pa[0][ks][1], pa[0][ks][2], pa[0][ks][3],
                        bf[nt][0], bf[nt][1]);
                mma_f16(o[1][nt], pa[1][ks][0], pa[1][ks][1], pa[1][ks][2], pa[1][ks][3],
                        bf[nt][0], bf[nt][1]);
            }
        }

        if (more) { CP_WAIT(0); }
        __syncthreads();
    }

    const int fr = lane >> 2;
    const int fc = lane & 3;
    const int b = bh >> 4;
    const int h = bh & 15;
#pragma unroll
    for (int mt = 0; mt < 2; mt++) {
        const float inv0 = 1.f / l_[mt][0];
        const float inv1 = 1.f / l_[mt][1];
        const int r0 = q0 + w * 32 + mt * 16 + fr;
#pragma unroll
        for (int nt = 0; nt < 8; nt++) {
            const int dv = nt * 8 + fc * 2;
            __half* base0 = &g_ctx[((size_t)b * SEQ + r0) * D_MODEL + h * HEAD_DIM + dv];
            __half* base1 = &g_ctx[((size_t)b * SEQ + r0 + 8) * D_MODEL + h * HEAD_DIM + dv];
            *(__half2*)base0 = __floats2half2_rn(o[mt][nt][0] * inv0, o[mt][nt][1] * inv0);
            *(__half2*)base1 = __floats2half2_rn(o[mt][nt][2] * inv1, o[mt][nt][3] * inv1);
        }
    }
}

// ---------------------------------------------------------------------------
// kernel_launch
// ---------------------------------------------------------------------------
extern "C" void kernel_launch(void* const* d_in, const int* in_sizes, int n_in,
                              void* d_out, int out_size)
{
    const float* query = (const float*)d_in[0];
    const float* key   = (const float*)d_in[1];
    const float* value = (const float*)d_in[2];
    const float* Wq    = (const float*)d_in[3];
    const float* Wk    = (const float*)d_in[4];
    const float* Wv    = (const float*)d_in[5];
    const float* Wo    = (const float*)d_in[6];
    const float* bo    = (const float*)d_in[7];
    float* out = (float*)d_out;

    __half *p_rq, *p_rk, *p_rv, *p_wq, *p_wk, *p_wv, *p_wo;
    cudaGetSymbolAddress((void**)&p_rq, r_q);
    cudaGetSymbolAddress((void**)&p_rk, r_k);
    cudaGetSymbolAddress((void**)&p_rv, r_v);
    cudaGetSymbolAddress((void**)&p_wq, r_wq);
    cudaGetSymbolAddress((void**)&p_wk, r_wk);
    cudaGetSymbolAddress((void**)&p_wv, r_wv);
    cudaGetSymbolAddress((void**)&p_wo, r_wo);

    const int n4_in = M_TOT * D_MODEL / 4;
    const int n4_w  = D_MODEL * D_MODEL / 4;

    PrepArgs pa;
    pa.src[0] = query; pa.dst[0] = p_rq; pa.n4[0] = n4_in; pa.scale[0] = 1.f;
    pa.src[1] = key;   pa.dst[1] = p_rk; pa.n4[1] = n4_in; pa.scale[1] = 1.f;
    pa.src[2] = value; pa.dst[2] = p_rv; pa.n4[2] = n4_in; pa.scale[2] = 1.f;
    pa.src[3] = Wq;    pa.dst[3] = p_wq; pa.n4[3] = n4_w;  pa.scale[3] = ATT_SCALE * LOG2E;
    pa.src[4] = Wk;    pa.dst[4] = p_wk; pa.n4[4] = n4_w;  pa.scale[4] = 1.f;
    pa.src[5] = Wv;    pa.dst[5] = p_wv; pa.n4[5] = n4_w;  pa.scale[5] = 1.f;
    pa.src[6] = Wo;    pa.dst[6] = p_wo; pa.n4[6] = n4_w;  pa.scale[6] = 1.f;

    prep_all_kernel<<<dim3(256, 7), 256>>>(pa);

    cudaFuncSetAttribute(proj_kernel, cudaFuncAttributeMaxDynamicSharedMemorySize, GEMM_SMEM);
    cudaFuncSetAttribute(out_kernel,  cudaFuncAttributeMaxDynamicSharedMemorySize, GEMM_SMEM);
    cudaFuncSetAttribute(attn_kernel, cudaFuncAttributeMaxDynamicSharedMemorySize, ATTN_SMEM);

    proj_kernel<<<dim3(D_MODEL / GBN, M_TOT / GBM, 3), 128, GEMM_SMEM>>>();

    attn_kernel<<<dim3(SEQ / QT, BATCH * NUM_HEADS), 128, ATTN_SMEM>>>();

    out_kernel<<<dim3(D_MODEL / GBN, M_TOT / GBM), 128, GEMM_SMEM>>>(bo, out);
}

// round 16
// speedup vs baseline: 7.2823x; 1.0050x over previous
#include <cuda_runtime.h>
#include <cuda_fp16.h>
#include <cstdint>
#include <math.h>

// Problem constants
#define D_MODEL   1024
#define NUM_HEADS 16
#define HEAD_DIM  64
#define BATCH     2
#define SEQ       2048
#define M_TOT     (BATCH * SEQ)
#define ATT_SCALE 0.125f
#define LOG2E     1.4426950408889634f

// ---------------------------------------------------------------------------
// Scratch (device globals: allocation-free per harness rules)
// ---------------------------------------------------------------------------
__device__ __half g_q[BATCH * NUM_HEADS * SEQ * HEAD_DIM];  // fp16, 0.125*log2e folded
__device__ __half g_k[BATCH * NUM_HEADS * SEQ * HEAD_DIM];
__device__ __half g_v[BATCH * NUM_HEADS * SEQ * HEAD_DIM];
__device__ __half g_ctx[BATCH * SEQ * D_MODEL];             // [B,N,H*Dh] fp16

__device__ __half r_q[M_TOT * D_MODEL];
__device__ __half r_k[M_TOT * D_MODEL];
__device__ __half r_v[M_TOT * D_MODEL];
__device__ __half r_wq[D_MODEL * D_MODEL];
__device__ __half r_wk[D_MODEL * D_MODEL];
__device__ __half r_wv[D_MODEL * D_MODEL];
__device__ __half r_wo[D_MODEL * D_MODEL];

// ---------------------------------------------------------------------------
// helpers
// ---------------------------------------------------------------------------
__device__ __forceinline__ uint32_t smem_to_u32(const void* p) {
    uint32_t a;
    asm("{ .reg .u64 t; cvta.to.shared.u64 t, %1; cvt.u32.u64 %0, t; }" : "=r"(a) : "l"(p));
    return a;
}

__device__ __forceinline__ void mma_f16(float* c,
                                        uint32_t a0, uint32_t a1, uint32_t a2, uint32_t a3,
                                        uint32_t b0, uint32_t b1)
{
    asm volatile(
        "mma.sync.aligned.m16n8k16.row.col.f32.f16.f16.f32 "
        "{%0,%1,%2,%3}, {%4,%5,%6,%7}, {%8,%9}, {%0,%1,%2,%3};\n"
        : "+f"(c[0]), "+f"(c[1]), "+f"(c[2]), "+f"(c[3])
        : "r"(a0), "r"(a1), "r"(a2), "r"(a3), "r"(b0), "r"(b1));
}

__device__ __forceinline__ void ldsm_x4(uint32_t& d0, uint32_t& d1,
                                        uint32_t& d2, uint32_t& d3, uint32_t addr)
{
    asm volatile("ldmatrix.sync.aligned.m8n8.x4.shared.b16 {%0,%1,%2,%3}, [%4];"
                 : "=r"(d0), "=r"(d1), "=r"(d2), "=r"(d3) : "r"(addr));
}

__device__ __forceinline__ void ldsm_x4_t(uint32_t& d0, uint32_t& d1,
                                          uint32_t& d2, uint32_t& d3, uint32_t addr)
{
    asm volatile("ldmatrix.sync.aligned.m8n8.x4.trans.shared.b16 {%0,%1,%2,%3}, [%4];"
                 : "=r"(d0), "=r"(d1), "=r"(d2), "=r"(d3) : "r"(addr));
}

__device__ __forceinline__ void cp16(uint32_t dst, const void* src) {
    asm volatile("cp.async.cg.shared.global [%0], [%1], 16;" :: "r"(dst), "l"(src));
}
#define CP_COMMIT() asm volatile("cp.async.commit_group;" ::: "memory")
#define CP_WAIT(n)  asm volatile("cp.async.wait_group %0;" :: "n"(n) : "memory")

__device__ __forceinline__ uint32_t pack_h2(float a, float b) {
    __half2 h = __floats2half2_rn(a, b);
    return *(uint32_t*)&h;
}

// ---------------------------------------------------------------------------
// prep (single launch)
// ---------------------------------------------------------------------------
struct PrepArgs {
    const float* src[7];
    __half*      dst[7];
    int          n4[7];
    float        scale[7];
};

__global__ __launch_bounds__(256)
void prep_all_kernel(PrepArgs a)
{
    const int seg = blockIdx.y;
    const float* __restrict__ s = a.src[seg];
    __half* __restrict__ d = a.dst[seg];
    const int n4 = a.n4[seg];
    const float sc = a.scale[seg];

    const int stride = gridDim.x * blockDim.x;
    for (int i = blockIdx.x * blockDim.x + threadIdx.x; i < n4; i += stride) {
        float4 v = ((const float4*)s)[i];
        uint2 o;
        o.x = pack_h2(v.x * sc, v.y * sc);
        o.y = pack_h2(v.z * sc, v.w * sc);
        ((uint2*)d)[i] = o;
    }
}

// ---------------------------------------------------------------------------
// fp16 MMA GEMM: C = A @ W^T. CTA 128x64x64(halves), 128 thr = 4 warps
// (2m x 2n), warp tile 64x32. 2-stage cp.async pipeline, one barrier/k-iter.
// Small tiles -> 4 CTAs/SM (regs<=128, smem 55296x4 fits) for latency hiding
// and finer wave granularity.
// ---------------------------------------------------------------------------
#define GBM 128
#define GBN 64
#define GBK 64                          // halves per k-chunk
#define GPITCH 72                       // 64 + 8 pad (144B rows, conflict-free)
#define GSTG_A (GBM * GPITCH)           // 9216 halves
#define GSTG_B (GBN * GPITCH)           // 4608 halves
#define NKB (D_MODEL / GBK)             // 16
#define GEMM_SMEM ((2 * GSTG_A + 2 * GSTG_B) * 2)  // 55296 B

__device__ __forceinline__ void gemm_f16_body(const __half* __restrict__ A,
                                              const __half* __restrict__ W,
                                              void* __restrict__ Optr,
                                              const float* __restrict__ bo,
                                              int m0, int n0, int mode)
{
    extern __shared__ __align__(16) __half gsm[];

    const int t    = threadIdx.x;       // 0..127
    const int lane = t & 31;
    const int wid  = t >> 5;            // 0..3
    const int wm   = wid & 1;           // 0..1 : m-offset 64
    const int wn   = wid >> 1;          // 0..1 : n-offset 32
    const int fr   = lane >> 2;
    const int fc   = lane & 3;
    const int g    = lane >> 3;
    const int li   = lane & 7;
    const int K    = D_MODEL;

    uint32_t as_u[2], bs_u[2];
    {
        const uint32_t base = smem_to_u32(gsm);
#pragma unroll
        for (int s = 0; s < 2; s++) {
            as_u[s] = base + (uint32_t)(s * GSTG_A * 2);
            bs_u[s] = base + (uint32_t)((2 * GSTG_A + s * GSTG_B) * 2);
        }
    }

    float acc[4][4][4];
#pragma unroll
    for (int i = 0; i < 4; i++)
#pragma unroll
        for (int j = 0; j < 4; j++)
#pragma unroll
            for (int r = 0; r < 4; r++) acc[i][j][r] = 0.f;

    // staging: A = 128 rows x 64 halves = 1024 chunks (8/thr);
    //          B = 64 rows x 64 halves = 512 chunks (4/thr)
    const int srow = t >> 3;            // 0..15 (+16u)
    const int sc8  = (t & 7) * 8;

#define GEMM_STAGE(s, kb) do {                                                   \
        const int _k0 = (kb) * GBK;                                              \
        _Pragma("unroll")                                                        \
        for (int _u = 0; _u < 8; _u++) {                                         \
            const int _row = srow + 16 * _u;                                     \
            const uint32_t _so = (uint32_t)((_row * GPITCH + sc8) * 2);          \
            cp16(as_u[s] + _so, A + (size_t)(m0 + _row) * K + _k0 + sc8);        \
        }                                                                        \
        _Pragma("unroll")                                                        \
        for (int _u = 0; _u < 4; _u++) {                                         \
            const int _row = srow + 16 * _u;                                     \
            const uint32_t _so = (uint32_t)((_row * GPITCH + sc8) * 2);          \
            cp16(bs_u[s] + _so, W + (size_t)(n0 + _row) * K + _k0 + sc8);        \
        }                                                                        \
    } while (0)

    GEMM_STAGE(0, 0); CP_COMMIT();

    for (int kb = 0; kb < NKB; kb++) {
        const int cur = kb & 1;
        CP_WAIT(0);
        __syncthreads();
        if (kb + 1 < NKB) { GEMM_STAGE(cur ^ 1, kb + 1); CP_COMMIT(); }

#pragma unroll
        for (int ks = 0; ks < 4; ks++) {
            const int kc0 = ks * 16;
            uint32_t af[4][4];
#pragma unroll
            for (int mt = 0; mt < 4; mt++) {
                const int row = wm * 64 + mt * 16 + (g & 1) * 8 + li;
                const uint32_t addr = as_u[cur] +
                    (uint32_t)((row * GPITCH + kc0 + (g >> 1) * 8) * 2);
                ldsm_x4(af[mt][0], af[mt][1], af[mt][2], af[mt][3], addr);
            }
            uint32_t bf[4][2];
#pragma unroll
            for (int np = 0; np < 2; np++) {
                const int row = wn * 32 + np * 16 + (g >> 1) * 8 + li;
                const uint32_t addr = bs_u[cur] +
                    (uint32_t)((row * GPITCH + kc0 + (g & 1) * 8) * 2);
                ldsm_x4(bf[2 * np][0], bf[2 * np][1],
                        bf[2 * np + 1][0], bf[2 * np + 1][1], addr);
            }
#pragma unroll
            for (int nt = 0; nt < 4; nt++)
#pragma unroll
                for (int mt = 0; mt < 4; mt++)
                    mma_f16(acc[mt][nt], af[mt][0], af[mt][1], af[mt][2], af[mt][3],
                            bf[nt][0], bf[nt][1]);
        }
    }

    // epilogue
#pragma unroll
    for (int mt = 0; mt < 4; mt++) {
        const int r0 = m0 + wm * 64 + mt * 16 + fr;
#pragma unroll
        for (int nt = 0; nt < 4; nt++) {
            const int col = n0 + wn * 32 + nt * 8 + fc * 2;
            if (mode == 0) {
                __half* O = (__half*)Optr;
                const int h = col >> 6, d = col & 63;
#pragma unroll
                for (int half_ = 0; half_ < 2; half_++) {
                    const int m  = r0 + half_ * 8;
                    const int b  = m >> 11;
                    const int nq = m & (SEQ - 1);
                    __half2 o = __floats2half2_rn(acc[mt][nt][half_ * 2],
                                                  acc[mt][nt][half_ * 2 + 1]);
                    *(__half2*)&O[(((size_t)b * NUM_HEADS + h) * SEQ + nq) * HEAD_DIM + d] = o;
                }
            } else {
                float* O = (float*)Optr;
                const float b0 = bo[col], b1 = bo[col + 1];
#pragma unroll
                for (int half_ = 0; half_ < 2; half_++) {
                    const int m = r0 + half_ * 8;
                    float2 o = make_float2(acc[mt][nt][half_ * 2] + b0,
                                           acc[mt][nt][half_ * 2 + 1] + b1);
                    *(float2*)&O[(size_t)m * D_MODEL + col] = o;
                }
            }
        }
    }
#undef GEMM_STAGE
}

__global__ __launch_bounds__(128, 4)
void proj_kernel()
{
    const int z = blockIdx.z;
    const __half* A = (z == 0) ? r_q  : ((z == 1) ? r_k  : r_v);
    const __half* W = (z == 0) ? r_wq : ((z == 1) ? r_wk : r_wv);
    __half*       O = (z == 0) ? g_q  : ((z == 1) ? g_k  : g_v);
    gemm_f16_body(A, W, O, nullptr, blockIdx.y * GBM, blockIdx.x * GBN, 0);
}

__global__ __launch_bounds__(128, 4)
void out_kernel(const float* __restrict__ bo, float* __restrict__ Cout)
{
    gemm_f16_body(g_ctx, r_wo, Cout, bo, blockIdx.y * GBM, blockIdx.x * GBN, 1);
}

// ---------------------------------------------------------------------------
// Flash attention (unchanged from R14): fp16 mma, fp32 accum, log2-domain
// softmax via h2exp2, 4 warps x 32 q-rows, P in registers, V via ldsm.trans.
// ---------------------------------------------------------------------------
#define QT 128
#define KT 64
#define NT (SEQ / KT)
#define PS 72
#define ABUF (KT * PS)
#define ATTN_SMEM ((QT * PS + 4 * ABUF) * 2)   // 55296 B

__global__ __launch_bounds__(128)
void attn_kernel()
{
    extern __shared__ __align__(16) __half asm_[];

    const int t    = threadIdx.x;
    const int lane = t & 31;
    const int w    = t >> 5;
    const int g    = lane >> 3;
    const int li   = lane & 7;

    const uint32_t qs_u  = smem_to_u32(asm_);
    const uint32_t ksb_u = qs_u + QT * PS * 2;
    const uint32_t vsb_u = ksb_u + 2 * ABUF * 2;

    const int q0 = blockIdx.x * QT;
    const int bh = blockIdx.y;
    const __half* qb = g_q + (size_t)bh * SEQ * HEAD_DIM;
    const __half* kb = g_k + (size_t)bh * SEQ * HEAD_DIM;
    const __half* vb = g_v + (size_t)bh * SEQ * HEAD_DIM;

    const int crow = t >> 3;
    const int cc8  = (t & 7) * 8;

#pragma unroll
    for (int u = 0; u < 8; u++) {
        const int row = crow + 16 * u;
        cp16(qs_u + (uint32_t)((row * PS + cc8) * 2),
             qb + (size_t)(q0 + row) * HEAD_DIM + cc8);
    }
#pragma unroll
    for (int u = 0; u < 4; u++) {
        const int row = crow + 16 * u;
        cp16(ksb_u + (uint32_t)((row * PS + cc8) * 2),
             kb + (size_t)row * HEAD_DIM + cc8);
        cp16(vsb_u + (uint32_t)((row * PS + cc8) * 2),
             vb + (size_t)row * HEAD_DIM + cc8);
    }
    CP_COMMIT();
    CP_WAIT(0);
    __syncthreads();

    uint32_t qa[2][4][4];
#pragma unroll
    for (int mt = 0; mt < 2; mt++)
#pragma unroll
        for (int ks = 0; ks < 4; ks++) {
            const int row = w * 32 + mt * 16 + (g & 1) * 8 + li;
            const uint32_t addr = qs_u +
                (uint32_t)((row * PS + ks * 16 + (g >> 1) * 8) * 2);
            ldsm_x4(qa[mt][ks][0], qa[mt][ks][1], qa[mt][ks][2], qa[mt][ks][3], addr);
        }

    float o[2][8][4];
    float m_[2][2], l_[2][2];
#pragma unroll
    for (int mt = 0; mt < 2; mt++) {
        m_[mt][0] = -1e30f; m_[mt][1] = -1e30f;
        l_[mt][0] = 0.f;    l_[mt][1] = 0.f;
#pragma unroll
        for (int nt = 0; nt < 8; nt++)
#pragma unroll
            for (int r = 0; r < 4; r++) o[mt][nt][r] = 0.f;
    }

    for (int kt = 0; kt < NT; kt++) {
        const int cur = kt & 1;
        const bool more = (kt + 1 < NT);
        const uint32_t ks_u = ksb_u + (uint32_t)(cur * ABUF * 2);
        const uint32_t vs_u = vsb_u + (uint32_t)(cur * ABUF * 2);

        if (more) {
            const int j0 = (kt + 1) * KT;
            const uint32_t kdst = ksb_u + (uint32_t)((cur ^ 1) * ABUF * 2);
            const uint32_t vdst = vsb_u + (uint32_t)((cur ^ 1) * ABUF * 2);
#pragma unroll
            for (int u = 0; u < 4; u++) {
                const int row = crow + 16 * u;
                cp16(kdst + (uint32_t)((row * PS + cc8) * 2),
                     kb + (size_t)(j0 + row) * HEAD_DIM + cc8);
                cp16(vdst + (uint32_t)((row * PS + cc8) * 2),
                     vb + (size_t)(j0 + row) * HEAD_DIM + cc8);
            }
            CP_COMMIT();
        }

        float s[2][8][4];
#pragma unroll
        for (int mt = 0; mt < 2; mt++)
#pragma unroll
            for (int nt = 0; nt < 8; nt++)
#pragma unroll
                for (int r = 0; r < 4; r++) s[mt][nt][r] = 0.f;

#pragma unroll
        for (int ks = 0; ks < 4; ks++) {
            const int kc0 = ks * 16;
            uint32_t bf[8][2];
#pragma unroll
            for (int np = 0; np < 4; np++) {
                const int row = np * 16 + (g >> 1) * 8 + li;
                const uint32_t addr = ks_u + (uint32_t)((row * PS + kc0 + (g & 1) * 8) * 2);
                ldsm_x4(bf[2 * np][0], bf[2 * np][1],
                        bf[2 * np + 1][0], bf[2 * np + 1][1], addr);
            }
#pragma unroll
            for (int nt = 0; nt < 8; nt++) {
                mma_f16(s[0][nt], qa[0][ks][0], qa[0][ks][1], qa[0][ks][2], qa[0][ks][3],
                        bf[nt][0], bf[nt][1]);
                mma_f16(s[1][nt], qa[1][ks][0], qa[1][ks][1], qa[1][ks][2], qa[1][ks][3],
                        bf[nt][0], bf[nt][1]);
            }
        }

        uint32_t pa[2][4][4];
#pragma unroll
        for (int mt = 0; mt < 2; mt++) {
            float rm0 = -1e30f, rm1 = -1e30f;
#pragma unroll
            for (int nt = 0; nt < 8; nt++) {
                rm0 = fmaxf(rm0, fmaxf(s[mt][nt][0], s[mt][nt][1]));
                rm1 = fmaxf(rm1, fmaxf(s[mt][nt][2], s[mt][nt][3]));
            }
            rm0 = fmaxf(rm0, __shfl_xor_sync(0xffffffffu, rm0, 1));
            rm0 = fmaxf(rm0, __shfl_xor_sync(0xffffffffu, rm0, 2));
            rm1 = fmaxf(rm1, __shfl_xor_sync(0xffffffffu, rm1, 1));
            rm1 = fmaxf(rm1, __shfl_xor_sync(0xffffffffu, rm1, 2));

            const float mn0 = fmaxf(m_[mt][0], rm0);
            const float mn1 = fmaxf(m_[mt][1], rm1);
            const float cr0 = exp2f(m_[mt][0] - mn0);
            const float cr1 = exp2f(m_[mt][1] - mn1);
            m_[mt][0] = mn0; m_[mt][1] = mn1;

            float rs0 = 0.f, rs1 = 0.f;
#pragma unroll
            for (int nt = 0; nt < 8; nt++) {
                __half2 a01 = __floats2half2_rn(s[mt][nt][0] - mn0, s[mt][nt][1] - mn0);
                __half2 a23 = __floats2half2_rn(s[mt][nt][2] - mn1, s[mt][nt][3] - mn1);
                __half2 p01 = h2exp2(a01);
                __half2 p23 = h2exp2(a23);
                pa[mt][nt >> 1][(nt & 1) * 2 + 0] = *(uint32_t*)&p01;
                pa[mt][nt >> 1][(nt & 1) * 2 + 1] = *(uint32_t*)&p23;
                float2 f01 = __half22float2(p01);
                float2 f23 = __half22float2(p23);
                rs0 += f01.x + f01.y;
                rs1 += f23.x + f23.y;
            }
            rs0 += __shfl_xor_sync(0xffffffffu, rs0, 1);
            rs0 += __shfl_xor_sync(0xffffffffu, rs0, 2);
            rs1 += __shfl_xor_sync(0xffffffffu, rs1, 1);
            rs1 += __shfl_xor_sync(0xffffffffu, rs1, 2);
            l_[mt][0] = l_[mt][0] * cr0 + rs0;
            l_[mt][1] = l_[mt][1] * cr1 + rs1;

#pragma unroll
            for (int nt = 0; nt < 8; nt++) {
                o[mt][nt][0] *= cr0; o[mt][nt][1] *= cr0;
                o[mt][nt][2] *= cr1; o[mt][nt][3] *= cr1;
            }
        }

#pragma unroll
        for (int ks = 0; ks < 4; ks++) {
            const int kc0 = ks * 16;
            uint32_t bf[8][2];
#pragma unroll
            for (int np = 0; np < 4; np++) {
                const int row = kc0 + (g & 1) * 8 + li;
                const int col = np * 16 + (g >> 1) * 8;
                const uint32_t addr = vs_u + (uint32_t)((row * PS + col) * 2);
                ldsm_x4_t(bf[2 * np][0], bf[2 * np][1],
                          bf[2 * np + 1][0], bf[2 * np + 1][1], addr);
            }
#pragma unroll
            for (int nt = 0; nt < 8; nt++) {
                mma_f16(o[0][nt], pa[0][ks][0], pa[0][ks][1], pa[0][ks][2], pa[0][ks][3],
                        bf[nt][0], bf[nt][1]);
                mma_f16(o[1][nt], pa[1][ks][0], pa[1][ks][1], pa[1][ks][2], pa[1][ks][3],
                        bf[nt][0], bf[nt][1]);
            }
        }

        if (more) { CP_WAIT(0); }
        __syncthreads();
    }

    const int fr = lane >> 2;
    const int fc = lane & 3;
    const int b = bh >> 4;
    const int h = bh & 15;
#pragma unroll
    for (int mt = 0; mt < 2; mt++) {
        const float inv0 = 1.f / l_[mt][0];
        const float inv1 = 1.f / l_[mt][1];
        const int r0 = q0 + w * 32 + mt * 16 + fr;
#pragma unroll
        for (int nt = 0; nt < 8; nt++) {
            const int dv = nt * 8 + fc * 2;
            __half* base0 = &g_ctx[((size_t)b * SEQ + r0) * D_MODEL + h * HEAD_DIM + dv];
            __half* base1 = &g_ctx[((size_t)b * SEQ + r0 + 8) * D_MODEL + h * HEAD_DIM + dv];
            *(__half2*)base0 = __floats2half2_rn(o[mt][nt][0] * inv0, o[mt][nt][1] * inv0);
            *(__half2*)base1 = __floats2half2_rn(o[mt][nt][2] * inv1, o[mt][nt][3] * inv1);
        }
    }
}

// ---------------------------------------------------------------------------
// kernel_launch
// ---------------------------------------------------------------------------
extern "C" void kernel_launch(void* const* d_in, const int* in_sizes, int n_in,
                              void* d_out, int out_size)
{
    const float* query = (const float*)d_in[0];
    const float* key   = (const float*)d_in[1];
    const float* value = (const float*)d_in[2];
    const float* Wq    = (const float*)d_in[3];
    const float* Wk    = (const float*)d_in[4];
    const float* Wv    = (const float*)d_in[5];
    const float* Wo    = (const float*)d_in[6];
    const float* bo    = (const float*)d_in[7];
    float* out = (float*)d_out;

    __half *p_rq, *p_rk, *p_rv, *p_wq, *p_wk, *p_wv, *p_wo;
    cudaGetSymbolAddress((void**)&p_rq, r_q);
    cudaGetSymbolAddress((void**)&p_rk, r_k);
    cudaGetSymbolAddress((void**)&p_rv, r_v);
    cudaGetSymbolAddress((void**)&p_wq, r_wq);
    cudaGetSymbolAddress((void**)&p_wk, r_wk);
    cudaGetSymbolAddress((void**)&p_wv, r_wv);
    cudaGetSymbolAddress((void**)&p_wo, r_wo);

    const int n4_in = M_TOT * D_MODEL / 4;
    const int n4_w  = D_MODEL * D_MODEL / 4;

    PrepArgs pa;
    pa.src[0] = query; pa.dst[0] = p_rq; pa.n4[0] = n4_in; pa.scale[0] = 1.f;
    pa.src[1] = key;   pa.dst[1] = p_rk; pa.n4[1] = n4_in; pa.scale[1] = 1.f;
    pa.src[2] = value; pa.dst[2] = p_rv; pa.n4[2] = n4_in; pa.scale[2] = 1.f;
    pa.src[3] = Wq;    pa.dst[3] = p_wq; pa.n4[3] = n4_w;  pa.scale[3] = ATT_SCALE * LOG2E;
    pa.src[4] = Wk;    pa.dst[4] = p_wk; pa.n4[4] = n4_w;  pa.scale[4] = 1.f;
    pa.src[5] = Wv;    pa.dst[5] = p_wv; pa.n4[5] = n4_w;  pa.scale[5] = 1.f;
    pa.src[6] = Wo;    pa.dst[6] = p_wo; pa.n4[6] = n4_w;  pa.scale[6] = 1.f;

    prep_all_kernel<<<dim3(256, 7), 256>>>(pa);

    cudaFuncSetAttribute(proj_kernel, cudaFuncAttributeMaxDynamicSharedMemorySize, GEMM_SMEM);
    cudaFuncSetAttribute(out_kernel,  cudaFuncAttributeMaxDynamicSharedMemorySize, GEMM_SMEM);
    cudaFuncSetAttribute(attn_kernel, cudaFuncAttributeMaxDynamicSharedMemorySize, ATTN_SMEM);

    proj_kernel<<<dim3(D_MODEL / GBN, M_TOT / GBM, 3), 128, GEMM_SMEM>>>();

    attn_kernel<<<dim3(SEQ / QT, BATCH * NUM_HEADS), 128, ATTN_SMEM>>>();

    out_kernel<<<dim3(D_MODEL / GBN, M_TOT / GBM), 128, GEMM_SMEM>>>(bo, out);
}

// round 17
// speedup vs baseline: 7.3460x; 1.0087x over previous
#include <cuda_runtime.h>
#include <cuda_fp16.h>
#include <cstdint>
#include <math.h>

// Problem constants
#define D_MODEL   1024
#define NUM_HEADS 16
#define HEAD_DIM  64
#define BATCH     2
#define SEQ       2048
#define M_TOT     (BATCH * SEQ)
#define ATT_SCALE 0.125f
#define LOG2E     1.4426950408889634f

// ---------------------------------------------------------------------------
// Scratch (device globals: allocation-free per harness rules)
// ---------------------------------------------------------------------------
__device__ __half g_q[BATCH * NUM_HEADS * SEQ * HEAD_DIM];  // fp16, 0.125*log2e folded
__device__ __half g_k[BATCH * NUM_HEADS * SEQ * HEAD_DIM];
__device__ __half g_v[BATCH * NUM_HEADS * SEQ * HEAD_DIM];
__device__ __half g_ctx[BATCH * SEQ * D_MODEL];             // [B,N,H*Dh] fp16

__device__ __half r_q[M_TOT * D_MODEL];
__device__ __half r_k[M_TOT * D_MODEL];
__device__ __half r_v[M_TOT * D_MODEL];
__device__ __half r_wq[D_MODEL * D_MODEL];
__device__ __half r_wk[D_MODEL * D_MODEL];
__device__ __half r_wv[D_MODEL * D_MODEL];
__device__ __half r_wo[D_MODEL * D_MODEL];

// ---------------------------------------------------------------------------
// helpers
// ---------------------------------------------------------------------------
__device__ __forceinline__ uint32_t smem_to_u32(const void* p) {
    uint32_t a;
    asm("{ .reg .u64 t; cvta.to.shared.u64 t, %1; cvt.u32.u64 %0, t; }" : "=r"(a) : "l"(p));
    return a;
}

__device__ __forceinline__ void mma_f16(float* c,
                                        uint32_t a0, uint32_t a1, uint32_t a2, uint32_t a3,
                                        uint32_t b0, uint32_t b1)
{
    asm volatile(
        "mma.sync.aligned.m16n8k16.row.col.f32.f16.f16.f32 "
        "{%0,%1,%2,%3}, {%4,%5,%6,%7}, {%8,%9}, {%0,%1,%2,%3};\n"
        : "+f"(c[0]), "+f"(c[1]), "+f"(c[2]), "+f"(c[3])
        : "r"(a0), "r"(a1), "r"(a2), "r"(a3), "r"(b0), "r"(b1));
}

__device__ __forceinline__ void ldsm_x4(uint32_t& d0, uint32_t& d1,
                                        uint32_t& d2, uint32_t& d3, uint32_t addr)
{
    asm volatile("ldmatrix.sync.aligned.m8n8.x4.shared.b16 {%0,%1,%2,%3}, [%4];"
                 : "=r"(d0), "=r"(d1), "=r"(d2), "=r"(d3) : "r"(addr));
}

__device__ __forceinline__ void ldsm_x4_t(uint32_t& d0, uint32_t& d1,
                                          uint32_t& d2, uint32_t& d3, uint32_t addr)
{
    asm volatile("ldmatrix.sync.aligned.m8n8.x4.trans.shared.b16 {%0,%1,%2,%3}, [%4];"
                 : "=r"(d0), "=r"(d1), "=r"(d2), "=r"(d3) : "r"(addr));
}

__device__ __forceinline__ void cp16(uint32_t dst, const void* src) {
    asm volatile("cp.async.cg.shared.global [%0], [%1], 16;" :: "r"(dst), "l"(src));
}
#define CP_COMMIT() asm volatile("cp.async.commit_group;" ::: "memory")
#define CP_WAIT(n)  asm volatile("cp.async.wait_group %0;" :: "n"(n) : "memory")

__device__ __forceinline__ uint32_t pack_h2(float a, float b) {
    __half2 h = __floats2half2_rn(a, b);
    return *(uint32_t*)&h;
}

// ---------------------------------------------------------------------------
// prep (single launch)
// ---------------------------------------------------------------------------
struct PrepArgs {
    const float* src[7];
    __half*      dst[7];
    int          n4[7];
    float        scale[7];
};

__global__ __launch_bounds__(256)
void prep_all_kernel(PrepArgs a)
{
    const int seg = blockIdx.y;
    const float* __restrict__ s = a.src[seg];
    __half* __restrict__ d = a.dst[seg];
    const int n4 = a.n4[seg];
    const float sc = a.scale[seg];

    const int stride = gridDim.x * blockDim.x;
    for (int i = blockIdx.x * blockDim.x + threadIdx.x; i < n4; i += stride) {
        float4 v = ((const float4*)s)[i];
        uint2 o;
        o.x = pack_h2(v.x * sc, v.y * sc);
        o.y = pack_h2(v.z * sc, v.w * sc);
        ((uint2*)d)[i] = o;
    }
}

// ---------------------------------------------------------------------------
// fp16 MMA GEMM (unchanged from R15): CTA 128x64x64(halves), 128 thr = 4 warps
// (2m x 2n), warp tile 64x32. 2-stage cp.async pipeline, one barrier/k-iter.
// ---------------------------------------------------------------------------
#define GBM 128
#define GBN 64
#define GBK 64
#define GPITCH 72
#define GSTG_A (GBM * GPITCH)
#define GSTG_B (GBN * GPITCH)
#define NKB (D_MODEL / GBK)
#define GEMM_SMEM ((2 * GSTG_A + 2 * GSTG_B) * 2)  // 55296 B

__device__ __forceinline__ void gemm_f16_body(const __half* __restrict__ A,
                                              const __half* __restrict__ W,
                                              void* __restrict__ Optr,
                                              const float* __restrict__ bo,
                                              int m0, int n0, int mode)
{
    extern __shared__ __align__(16) __half gsm[];

    const int t    = threadIdx.x;
    const int lane = t & 31;
    const int wid  = t >> 5;
    const int wm   = wid & 1;
    const int wn   = wid >> 1;
    const int fr   = lane >> 2;
    const int fc   = lane & 3;
    const int g    = lane >> 3;
    const int li   = lane & 7;
    const int K    = D_MODEL;

    uint32_t as_u[2], bs_u[2];
    {
        const uint32_t base = smem_to_u32(gsm);
#pragma unroll
        for (int s = 0; s < 2; s++) {
            as_u[s] = base + (uint32_t)(s * GSTG_A * 2);
            bs_u[s] = base + (uint32_t)((2 * GSTG_A + s * GSTG_B) * 2);
        }
    }

    float acc[4][4][4];
#pragma unroll
    for (int i = 0; i < 4; i++)
#pragma unroll
        for (int j = 0; j < 4; j++)
#pragma unroll
            for (int r = 0; r < 4; r++) acc[i][j][r] = 0.f;

    const int srow = t >> 3;
    const int sc8  = (t & 7) * 8;

#define GEMM_STAGE(s, kb) do {                                                   \
        const int _k0 = (kb) * GBK;                                              \
        _Pragma("unroll")                                                        \
        for (int _u = 0; _u < 8; _u++) {                                         \
            const int _row = srow + 16 * _u;                                     \
            const uint32_t _so = (uint32_t)((_row * GPITCH + sc8) * 2);          \
            cp16(as_u[s] + _so, A + (size_t)(m0 + _row) * K + _k0 + sc8);        \
        }                                                                        \
        _Pragma("unroll")                                                        \
        for (int _u = 0; _u < 4; _u++) {                                         \
            const int _row = srow + 16 * _u;                                     \
            const uint32_t _so = (uint32_t)((_row * GPITCH + sc8) * 2);          \
            cp16(bs_u[s] + _so, W + (size_t)(n0 + _row) * K + _k0 + sc8);        \
        }                                                                        \
    } while (0)

    GEMM_STAGE(0, 0); CP_COMMIT();

    for (int kb = 0; kb < NKB; kb++) {
        const int cur = kb & 1;
        CP_WAIT(0);
        __syncthreads();
        if (kb + 1 < NKB) { GEMM_STAGE(cur ^ 1, kb + 1); CP_COMMIT(); }

#pragma unroll
        for (int ks = 0; ks < 4; ks++) {
            const int kc0 = ks * 16;
            uint32_t af[4][4];
#pragma unroll
            for (int mt = 0; mt < 4; mt++) {
                const int row = wm * 64 + mt * 16 + (g & 1) * 8 + li;
                const uint32_t addr = as_u[cur] +
                    (uint32_t)((row * GPITCH + kc0 + (g >> 1) * 8) * 2);
                ldsm_x4(af[mt][0], af[mt][1], af[mt][2], af[mt][3], addr);
            }
            uint32_t bf[4][2];
#pragma unroll
            for (int np = 0; np < 2; np++) {
                const int row = wn * 32 + np * 16 + (g >> 1) * 8 + li;
                const uint32_t addr = bs_u[cur] +
                    (uint32_t)((row * GPITCH + kc0 + (g & 1) * 8) * 2);
                ldsm_x4(bf[2 * np][0], bf[2 * np][1],
                        bf[2 * np + 1][0], bf[2 * np + 1][1], addr);
            }
#pragma unroll
            for (int nt = 0; nt < 4; nt++)
#pragma unroll
                for (int mt = 0; mt < 4; mt++)
                    mma_f16(acc[mt][nt], af[mt][0], af[mt][1], af[mt][2], af[mt][3],
                            bf[nt][0], bf[nt][1]);
        }
    }

    // epilogue
#pragma unroll
    for (int mt = 0; mt < 4; mt++) {
        const int r0 = m0 + wm * 64 + mt * 16 + fr;
#pragma unroll
        for (int nt = 0; nt < 4; nt++) {
            const int col = n0 + wn * 32 + nt * 8 + fc * 2;
            if (mode == 0) {
                __half* O = (__half*)Optr;
                const int h = col >> 6, d = col & 63;
#pragma unroll
                for (int half_ = 0; half_ < 2; half_++) {
                    const int m  = r0 + half_ * 8;
                    const int b  = m >> 11;
                    const int nq = m & (SEQ - 1);
                    __half2 o = __floats2half2_rn(acc[mt][nt][half_ * 2],
                                                  acc[mt][nt][half_ * 2 + 1]);
                    *(__half2*)&O[(((size_t)b * NUM_HEADS + h) * SEQ + nq) * HEAD_DIM + d] = o;
                }
            } else {
                float* O = (float*)Optr;
                const float b0 = bo[col], b1 = bo[col + 1];
#pragma unroll
                for (int half_ = 0; half_ < 2; half_++) {
                    const int m = r0 + half_ * 8;
                    float2 o = make_float2(acc[mt][nt][half_ * 2] + b0,
                                           acc[mt][nt][half_ * 2 + 1] + b1);
                    *(float2*)&O[(size_t)m * D_MODEL + col] = o;
                }
            }
        }
    }
#undef GEMM_STAGE
}

__global__ __launch_bounds__(128, 4)
void proj_kernel()
{
    const int z = blockIdx.z;
    const __half* A = (z == 0) ? r_q  : ((z == 1) ? r_k  : r_v);
    const __half* W = (z == 0) ? r_wq : ((z == 1) ? r_wk : r_wv);
    __half*       O = (z == 0) ? g_q  : ((z == 1) ? g_k  : g_v);
    gemm_f16_body(A, W, O, nullptr, blockIdx.y * GBM, blockIdx.x * GBN, 0);
}

__global__ __launch_bounds__(128, 4)
void out_kernel(const float* __restrict__ bo, float* __restrict__ Cout)
{
    gemm_f16_body(g_ctx, r_wo, Cout, bo, blockIdx.y * GBM, blockIdx.x * GBN, 1);
}

// ---------------------------------------------------------------------------
// Flash attention: QT=64 (finer CTA granularity -> near-perfect per-SM work
// balance: 1024 CTAs / 148 SMs = 6.92, tail 7/6.92 vs old 4/3.46).
// 128 thr = 4 warps x 16 q-rows. fp16 mma, fp32 accum, log2-domain softmax
// via h2exp2, P in registers, V via ldsm.trans. Per-row math order identical
// to previous rounds (bit-identical result).
// ---------------------------------------------------------------------------
#define QT 64
#define KT 64
#define NT (SEQ / KT)
#define PS 72
#define ABUF (KT * PS)
#define ATTN_SMEM ((QT * PS + 4 * ABUF) * 2)   // 46080 B

__global__ __launch_bounds__(128, 3)
void attn_kernel()
{
    extern __shared__ __align__(16) __half asm_[];

    const int t    = threadIdx.x;
    const int lane = t & 31;
    const int w    = t >> 5;          // 0..3 : q-rows w*16 .. w*16+15
    const int g    = lane >> 3;
    const int li   = lane & 7;

    const uint32_t qs_u  = smem_to_u32(asm_);
    const uint32_t ksb_u = qs_u + QT * PS * 2;
    const uint32_t vsb_u = ksb_u + 2 * ABUF * 2;

    const int q0 = blockIdx.x * QT;
    const int bh = blockIdx.y;
    const __half* qb = g_q + (size_t)bh * SEQ * HEAD_DIM;
    const __half* kb = g_k + (size_t)bh * SEQ * HEAD_DIM;
    const __half* vb = g_v + (size_t)bh * SEQ * HEAD_DIM;

    const int crow = t >> 3;          // 0..15 (+16u)
    const int cc8  = (t & 7) * 8;

    // ---- prologue: Q (4 chunks/thr) + K0 + V0 via cp.async ----
#pragma unroll
    for (int u = 0; u < 4; u++) {
        const int row = crow + 16 * u;
        cp16(qs_u + (uint32_t)((row * PS + cc8) * 2),
             qb + (size_t)(q0 + row) * HEAD_DIM + cc8);
    }
#pragma unroll
    for (int u = 0; u < 4; u++) {
        const int row = crow + 16 * u;
        cp16(ksb_u + (uint32_t)((row * PS + cc8) * 2),
             kb + (size_t)row * HEAD_DIM + cc8);
        cp16(vsb_u + (uint32_t)((row * PS + cc8) * 2),
             vb + (size_t)row * HEAD_DIM + cc8);
    }
    CP_COMMIT();
    CP_WAIT(0);
    __syncthreads();

    // Q frags: 4 ksteps
    uint32_t qa[4][4];
#pragma unroll
    for (int ks = 0; ks < 4; ks++) {
        const int row = w * 16 + (g & 1) * 8 + li;
        const uint32_t addr = qs_u +
            (uint32_t)((row * PS + ks * 16 + (g >> 1) * 8) * 2);
        ldsm_x4(qa[ks][0], qa[ks][1], qa[ks][2], qa[ks][3], addr);
    }

    float o[8][4];
    float m0 = -1e30f, m1 = -1e30f, l0 = 0.f, l1 = 0.f;
#pragma unroll
    for (int nt = 0; nt < 8; nt++)
#pragma unroll
        for (int r = 0; r < 4; r++) o[nt][r] = 0.f;

    for (int kt = 0; kt < NT; kt++) {
        const int cur = kt & 1;
        const bool more = (kt + 1 < NT);
        const uint32_t ks_u = ksb_u + (uint32_t)(cur * ABUF * 2);
        const uint32_t vs_u = vsb_u + (uint32_t)(cur * ABUF * 2);

        if (more) {
            const int j0 = (kt + 1) * KT;
            const uint32_t kdst = ksb_u + (uint32_t)((cur ^ 1) * ABUF * 2);
            const uint32_t vdst = vsb_u + (uint32_t)((cur ^ 1) * ABUF * 2);
#pragma unroll
            for (int u = 0; u < 4; u++) {
                const int row = crow + 16 * u;
                cp16(kdst + (uint32_t)((row * PS + cc8) * 2),
                     kb + (size_t)(j0 + row) * HEAD_DIM + cc8);
                cp16(vdst + (uint32_t)((row * PS + cc8) * 2),
                     vb + (size_t)(j0 + row) * HEAD_DIM + cc8);
            }
            CP_COMMIT();
        }

        // ---- S' = Q @ K^T (log2 domain; warp tile 16 x 64) ----
        float s[8][4];
#pragma unroll
        for (int nt = 0; nt < 8; nt++)
#pragma unroll
            for (int r = 0; r < 4; r++) s[nt][r] = 0.f;

#pragma unroll
        for (int ks = 0; ks < 4; ks++) {
            const int kc0 = ks * 16;
            uint32_t bf[8][2];
#pragma unroll
            for (int np = 0; np < 4; np++) {
                const int row = np * 16 + (g >> 1) * 8 + li;
                const uint32_t addr = ks_u + (uint32_t)((row * PS + kc0 + (g & 1) * 8) * 2);
                ldsm_x4(bf[2 * np][0], bf[2 * np][1],
                        bf[2 * np + 1][0], bf[2 * np + 1][1], addr);
            }
#pragma unroll
            for (int nt = 0; nt < 8; nt++)
                mma_f16(s[nt], qa[ks][0], qa[ks][1], qa[ks][2], qa[ks][3],
                        bf[nt][0], bf[nt][1]);
        }

        // ---- online softmax (base-2) + P frags via h2exp2 ----
        float rm0 = -1e30f, rm1 = -1e30f;
#pragma unroll
        for (int nt = 0; nt < 8; nt++) {
            rm0 = fmaxf(rm0, fmaxf(s[nt][0], s[nt][1]));
            rm1 = fmaxf(rm1, fmaxf(s[nt][2], s[nt][3]));
        }
        rm0 = fmaxf(rm0, __shfl_xor_sync(0xffffffffu, rm0, 1));
        rm0 = fmaxf(rm0, __shfl_xor_sync(0xffffffffu, rm0, 2));
        rm1 = fmaxf(rm1, __shfl_xor_sync(0xffffffffu, rm1, 1));
        rm1 = fmaxf(rm1, __shfl_xor_sync(0xffffffffu, rm1, 2));

        const float mn0 = fmaxf(m0, rm0);
        const float mn1 = fmaxf(m1, rm1);
        const float cr0 = exp2f(m0 - mn0);
        const float cr1 = exp2f(m1 - mn1);
        m0 = mn0; m1 = mn1;

        uint32_t pa[4][4];
        float rs0 = 0.f, rs1 = 0.f;
#pragma unroll
        for (int nt = 0; nt < 8; nt++) {
            __half2 a01 = __floats2half2_rn(s[nt][0] - mn0, s[nt][1] - mn0);
            __half2 a23 = __floats2half2_rn(s[nt][2] - mn1, s[nt][3] - mn1);
            __half2 p01 = h2exp2(a01);
            __half2 p23 = h2exp2(a23);
            pa[nt >> 1][(nt & 1) * 2 + 0] = *(uint32_t*)&p01;
            pa[nt >> 1][(nt & 1) * 2 + 1] = *(uint32_t*)&p23;
            float2 f01 = __half22float2(p01);
            float2 f23 = __half22float2(p23);
            rs0 += f01.x + f01.y;
            rs1 += f23.x + f23.y;
        }
        rs0 += __shfl_xor_sync(0xffffffffu, rs0, 1);
        rs0 += __shfl_xor_sync(0xffffffffu, rs0, 2);
        rs1 += __shfl_xor_sync(0xffffffffu, rs1, 1);
        rs1 += __shfl_xor_sync(0xffffffffu, rs1, 2);
        l0 = l0 * cr0 + rs0;
        l1 = l1 * cr1 + rs1;

#pragma unroll
        for (int nt = 0; nt < 8; nt++) {
            o[nt][0] *= cr0; o[nt][1] *= cr0;
            o[nt][2] *= cr1; o[nt][3] *= cr1;
        }

        // ---- O += P @ V (trans B-frags from row-major V) ----
#pragma unroll
        for (int ks = 0; ks < 4; ks++) {
            const int kc0 = ks * 16;
            uint32_t bf[8][2];
#pragma unroll
            for (int np = 0; np < 4; np++) {
                const int row = kc0 + (g & 1) * 8 + li;       // j
                const int col = np * 16 + (g >> 1) * 8;       // dv
                const uint32_t addr = vs_u + (uint32_t)((row * PS + col) * 2);
                ldsm_x4_t(bf[2 * np][0], bf[2 * np][1],
                          bf[2 * np + 1][0], bf[2 * np + 1][1], addr);
            }
#pragma unroll
            for (int nt = 0; nt < 8; nt++)
                mma_f16(o[nt], pa[ks][0], pa[ks][1], pa[ks][2], pa[ks][3],
                        bf[nt][0], bf[nt][1]);
        }

        if (more) { CP_WAIT(0); }
        __syncthreads();
    }

    // ---- epilogue ----
    const int fr = lane >> 2;
    const int fc = lane & 3;
    const int b = bh >> 4;
    const int h = bh & 15;
    const float inv0 = 1.f / l0;
    const float inv1 = 1.f / l1;
    const int r0 = q0 + w * 16 + fr;
#pragma unroll
    for (int nt = 0; nt < 8; nt++) {
        const int dv = nt * 8 + fc * 2;
        __half* base0 = &g_ctx[((size_t)b * SEQ + r0) * D_MODEL + h * HEAD_DIM + dv];
        __half* base1 = &g_ctx[((size_t)b * SEQ + r0 + 8) * D_MODEL + h * HEAD_DIM + dv];
        *(__half2*)base0 = __floats2half2_rn(o[nt][0] * inv0, o[nt][1] * inv0);
        *(__half2*)base1 = __floats2half2_rn(o[nt][2] * inv1, o[nt][3] * inv1);
    }
}

// ---------------------------------------------------------------------------
// kernel_launch
// ---------------------------------------------------------------------------
extern "C" void kernel_launch(void* const* d_in, const int* in_sizes, int n_in,
                              void* d_out, int out_size)
{
    const float* query = (const float*)d_in[0];
    const float* key   = (const float*)d_in[1];
    const float* value = (const float*)d_in[2];
    const float* Wq    = (const float*)d_in[3];
    const float* Wk    = (const float*)d_in[4];
    const float* Wv    = (const float*)d_in[5];
    const float* Wo    = (const float*)d_in[6];
    const float* bo    = (const float*)d_in[7];
    float* out = (float*)d_out;

    __half *p_rq, *p_rk, *p_rv, *p_wq, *p_wk, *p_wv, *p_wo;
    cudaGetSymbolAddress((void**)&p_rq, r_q);
    cudaGetSymbolAddress((void**)&p_rk, r_k);
    cudaGetSymbolAddress((void**)&p_rv, r_v);
    cudaGetSymbolAddress((void**)&p_wq, r_wq);
    cudaGetSymbolAddress((void**)&p_wk, r_wk);
    cudaGetSymbolAddress((void**)&p_wv, r_wv);
    cudaGetSymbolAddress((void**)&p_wo, r_wo);

    const int n4_in = M_TOT * D_MODEL / 4;
    const int n4_w  = D_MODEL * D_MODEL / 4;

    PrepArgs pa;
    pa.src[0] = query; pa.dst[0] = p_rq; pa.n4[0] = n4_in; pa.scale[0] = 1.f;
    pa.src[1] = key;   pa.dst[1] = p_rk; pa.n4[1] = n4_in; pa.scale[1] = 1.f;
    pa.src[2] = value; pa.dst[2] = p_rv; pa.n4[2] = n4_in; pa.scale[2] = 1.f;
    pa.src[3] = Wq;    pa.dst[3] = p_wq; pa.n4[3] = n4_w;  pa.scale[3] = ATT_SCALE * LOG2E;
    pa.src[4] = Wk;    pa.dst[4] = p_wk; pa.n4[4] = n4_w;  pa.scale[4] = 1.f;
    pa.src[5] = Wv;    pa.dst[5] = p_wv; pa.n4[5] = n4_w;  pa.scale[5] = 1.f;
    pa.src[6] = Wo;    pa.dst[6] = p_wo; pa.n4[6] = n4_w;  pa.scale[6] = 1.f;

    prep_all_kernel<<<dim3(512, 7), 256>>>(pa);

    cudaFuncSetAttribute(proj_kernel, cudaFuncAttributeMaxDynamicSharedMemorySize, GEMM_SMEM);
    cudaFuncSetAttribute(out_kernel,  cudaFuncAttributeMaxDynamicSharedMemorySize, GEMM_SMEM);
    cudaFuncSetAttribute(attn_kernel, cudaFuncAttributeMaxDynamicSharedMemorySize, ATTN_SMEM);

    proj_kernel<<<dim3(D_MODEL / GBN, M_TOT / GBM, 3), 128, GEMM_SMEM>>>();

    attn_kernel<<<dim3(SEQ / QT, BATCH * NUM_HEADS), 128, ATTN_SMEM>>>();

    out_kernel<<<dim3(D_MODEL / GBN, M_TOT / GBM), 128, GEMM_SMEM>>>(bo, out);
}